// round 6
// baseline (speedup 1.0000x reference)
#include <cuda_runtime.h>
#include <cuda_bf16.h>
#include <math.h>
#include <stdint.h>

#define Bc    4
#define Tt    2048
#define TRAIN 1536
#define Dd    512
#define Ll    12
#define FFd   2048
#define BT    (Bc*Tt)
#define NBH   32
#define MTEST 2048

typedef __nv_bfloat16 bf16;

// ---------------- static buffers ----------------
__device__ float g_rep [BT*Dd];
__device__ float g_qkv [BT*3*Dd];
__device__ bf16  g_hh[BT*Dd], g_hl[BT*Dd];
__device__ bf16  g_ah[BT*Dd], g_al[BT*Dd];
__device__ bf16  g_fh[BT*FFd], g_fl[BT*FFd];
__device__ bf16  g_qh[NBH*Tt*64], g_ql[NBH*Tt*64];
__device__ bf16  g_kh[NBH*Tt*64], g_kl[NBH*Tt*64];
__device__ bf16  g_Vth[(size_t)NBH*128*Tt], g_Vtl[(size_t)NBH*128*Tt];
__device__ bf16  g_th[MTEST*Dd], g_tl[MTEST*Dd];
__device__ bf16  g_gh[MTEST*2*Dd], g_gl[MTEST*2*Dd];
__device__ bf16  g_Wqkvh[Ll*3*Dd*Dd], g_Wqkvl[Ll*3*Dd*Dd];
__device__ bf16  g_Woh[Ll*Dd*Dd],  g_Wol[Ll*Dd*Dd];
__device__ bf16  g_W1h[Ll*FFd*Dd], g_W1l[Ll*FFd*Dd];
__device__ bf16  g_W2h[Ll*Dd*FFd], g_W2l[Ll*Dd*FFd];
__device__ bf16  g_pW1h[2*Dd*Dd],  g_pW1l[2*Dd*Dd];
__device__ bf16  g_pW2h[128*2*Dd], g_pW2l[128*2*Dd];
__device__ float g_cos[Tt*32], g_sin[Tt*32];

// ---------------- helpers ----------------
__device__ __forceinline__ float gelu_f(float x){
    float y = 0.7978845608028654f*(x + 0.044715f*x*x*x);
    float yc = fminf(fmaxf(y, -15.f), 15.f);
    float t = __expf(2.f*yc);
    float th = (t - 1.f)/(t + 1.f);
    return 0.5f*x*(1.f + th);
}
__device__ __forceinline__ void split2(float x, bf16& h, bf16& l){
    h = __float2bfloat16(x);
    l = __float2bfloat16(x - __bfloat162float(h));
}
__device__ __forceinline__ uint32_t smem_u32(const void* p){
    uint32_t a;
    asm("{ .reg .u64 t; cvta.to.shared.u64 t, %1; cvt.u32.u64 %0, t; }" : "=r"(a) : "l"(p));
    return a;
}
__device__ __forceinline__ void cpasync16(uint32_t dst, const void* src){
    asm volatile("cp.async.cg.shared.global [%0], [%1], 16;" :: "r"(dst), "l"(src) : "memory");
}
__device__ __forceinline__ void ldsm4(uint32_t* r, uint32_t a){
    asm volatile("ldmatrix.sync.aligned.m8n8.x4.shared.b16 {%0,%1,%2,%3}, [%4];"
        : "=r"(r[0]),"=r"(r[1]),"=r"(r[2]),"=r"(r[3]) : "r"(a));
}
__device__ __forceinline__ void mma16816(float* c, const uint32_t* a, const uint32_t* b){
    asm volatile("mma.sync.aligned.m16n8k16.row.col.f32.bf16.bf16.f32 "
        "{%0,%1,%2,%3}, {%4,%5,%6,%7}, {%8,%9}, {%0,%1,%2,%3};"
        : "+f"(c[0]),"+f"(c[1]),"+f"(c[2]),"+f"(c[3])
        : "r"(a[0]),"r"(a[1]),"r"(a[2]),"r"(a[3]), "r"(b[0]),"r"(b[1]));
}
__device__ __forceinline__ uint32_t packbf(float lo, float hi){
    uint32_t r;
    asm("cvt.rn.bf16x2.f32 %0, %1, %2;" : "=r"(r) : "f"(hi), "f"(lo));
    return r;
}

// ================= fused flash attention =================
#define FLDS 72
#define FTILE (64*FLDS*2)
#define FQT   (128*FLDS*2)
#define FSTG  (4*FTILE)
#define FSM   (2*FQT + 2*FSTG)

__global__ __launch_bounds__(256) void flash_kernel(){
    extern __shared__ __align__(128) char smem[];
    const uint32_t sb = smem_u32(smem);
    const int tid = threadIdx.x, lane = tid & 31, warp = tid >> 5;
    const int bh = blockIdx.y, b = bh >> 3, h = bh & 7;
    const int t0 = blockIdx.x * 128;
    const int r0 = lane >> 2, cq = lane & 3;
    const int aRow = lane & 15, aCol = (lane >> 4)*8;
    // ldsm4 B addressing: quad selects (n-subtile, k-half)
    const int bQuad = lane >> 3, bRowQ = lane & 7;
    const int ntOff = bQuad >> 1, colQ = (bQuad & 1)*8;
    const uint32_t QH = sb, ST0 = sb + 2*FQT;

    {
        #pragma unroll
        for (int i = 0; i < 8; i++){
            int idx = tid + i*256;
            int tile = idx >> 10, rem = idx & 1023;
            int row = rem >> 3, ch = rem & 7;
            const bf16* src = (tile ? g_ql : g_qh) + ((size_t)bh*Tt + t0 + row)*64 + ch*8;
            cpasync16(sb + tile*FQT + (uint32_t)(row*FLDS + ch*8)*2, src);
        }
        #pragma unroll
        for (int i = 0; i < 8; i++){
            int idx = tid + i*256;
            int tile = idx >> 9, rem = idx & 511;
            int row = rem >> 3, ch = rem & 7;
            const bf16* src;
            if (tile == 0)      src = g_kh  + ((size_t)bh*Tt + row)*64 + ch*8;
            else if (tile == 1) src = g_kl  + ((size_t)bh*Tt + row)*64 + ch*8;
            else if (tile == 2) src = g_Vth + ((size_t)bh*128 + row)*Tt + ch*8;
            else                src = g_Vtl + ((size_t)bh*128 + row)*Tt + ch*8;
            cpasync16(ST0 + tile*FTILE + (uint32_t)(row*FLDS + ch*8)*2, src);
        }
        asm volatile("cp.async.commit_group;" ::: "memory");
    }

    float o[8][4] = {};
    float m0 = -INFINITY, m1 = -INFINITY, l0 = 0.f, l1 = 0.f;
    uint32_t qfh[4][4], qfl[4][4];

    for (int kt = 0; kt < 24; kt++){
        int s = kt & 1;
        if (kt + 1 < 24){
            int s2 = s ^ 1, s0n = (kt+1)*64;
            uint32_t base = ST0 + s2*FSTG;
            #pragma unroll
            for (int i = 0; i < 8; i++){
                int idx = tid + i*256;
                int tile = idx >> 9, rem = idx & 511;
                int row = rem >> 3, ch = rem & 7;
                const bf16* src;
                if (tile == 0)      src = g_kh  + ((size_t)bh*Tt + s0n + row)*64 + ch*8;
                else if (tile == 1) src = g_kl  + ((size_t)bh*Tt + s0n + row)*64 + ch*8;
                else if (tile == 2) src = g_Vth + ((size_t)bh*128 + row)*Tt + s0n + ch*8;
                else                src = g_Vtl + ((size_t)bh*128 + row)*Tt + s0n + ch*8;
                cpasync16(base + tile*FTILE + (uint32_t)(row*FLDS + ch*8)*2, src);
            }
            asm volatile("cp.async.commit_group;" ::: "memory");
            asm volatile("cp.async.wait_group 1;" ::: "memory");
        } else {
            asm volatile("cp.async.wait_group 0;" ::: "memory");
        }
        __syncthreads();

        if (kt == 0){
            #pragma unroll
            for (int ks = 0; ks < 4; ks++){
                uint32_t ad = QH + (uint32_t)((warp*16 + aRow)*FLDS + ks*16 + aCol)*2;
                ldsm4(qfh[ks], ad);
                ldsm4(qfl[ks], ad + FQT);
            }
        }

        uint32_t KB = ST0 + s*FSTG;
        // ---- S = Q K^T (3-term split) ----
        float acc[8][4] = {};
        #pragma unroll
        for (int ks = 0; ks < 4; ks++){
            #pragma unroll
            for (int g = 0; g < 2; g++){
                uint32_t bfh[4][2], bfl[4][2];
                #pragma unroll
                for (int p = 0; p < 2; p++){
                    int ntb = g*4 + p*2;
                    uint32_t bd = KB + (uint32_t)(((ntb + ntOff)*8 + bRowQ)*FLDS + ks*16 + colQ)*2;
                    uint32_t r4[4];
                    ldsm4(r4, bd);
                    bfh[p*2][0]=r4[0]; bfh[p*2][1]=r4[1]; bfh[p*2+1][0]=r4[2]; bfh[p*2+1][1]=r4[3];
                    ldsm4(r4, bd + FTILE);
                    bfl[p*2][0]=r4[0]; bfl[p*2][1]=r4[1]; bfl[p*2+1][0]=r4[2]; bfl[p*2+1][1]=r4[3];
                }
                #pragma unroll
                for (int j = 0; j < 4; j++) mma16816(acc[g*4+j], qfh[ks], bfh[j]);
                #pragma unroll
                for (int j = 0; j < 4; j++) mma16816(acc[g*4+j], qfh[ks], bfl[j]);
                #pragma unroll
                for (int j = 0; j < 4; j++) mma16816(acc[g*4+j], qfl[ks], bfh[j]);
            }
        }

        // ---- online softmax ----
        float tm0 = -INFINITY, tm1 = -INFINITY;
        #pragma unroll
        for (int nt = 0; nt < 8; nt++){
            tm0 = fmaxf(tm0, fmaxf(acc[nt][0], acc[nt][1]));
            tm1 = fmaxf(tm1, fmaxf(acc[nt][2], acc[nt][3]));
        }
        tm0 = fmaxf(tm0, __shfl_xor_sync(~0u, tm0, 1));
        tm0 = fmaxf(tm0, __shfl_xor_sync(~0u, tm0, 2));
        tm1 = fmaxf(tm1, __shfl_xor_sync(~0u, tm1, 1));
        tm1 = fmaxf(tm1, __shfl_xor_sync(~0u, tm1, 2));
        float mn0 = fmaxf(m0, tm0), mn1 = fmaxf(m1, tm1);
        float al0 = __expf(m0 - mn0), al1 = __expf(m1 - mn1);
        float ps0 = 0.f, ps1 = 0.f;
        #pragma unroll
        for (int nt = 0; nt < 8; nt++){
            acc[nt][0] = __expf(acc[nt][0] - mn0);
            acc[nt][1] = __expf(acc[nt][1] - mn0);
            acc[nt][2] = __expf(acc[nt][2] - mn1);
            acc[nt][3] = __expf(acc[nt][3] - mn1);
            ps0 += acc[nt][0] + acc[nt][1];
            ps1 += acc[nt][2] + acc[nt][3];
        }
        ps0 += __shfl_xor_sync(~0u, ps0, 1); ps0 += __shfl_xor_sync(~0u, ps0, 2);
        ps1 += __shfl_xor_sync(~0u, ps1, 1); ps1 += __shfl_xor_sync(~0u, ps1, 2);
        l0 = l0*al0 + ps0; l1 = l1*al1 + ps1;
        m0 = mn0; m1 = mn1;
        #pragma unroll
        for (int nt = 0; nt < 8; nt++){
            o[nt][0] *= al0; o[nt][1] *= al0; o[nt][2] *= al1; o[nt][3] *= al1;
        }

        // ---- O += P V (3-term split) ----
        uint32_t VB = KB + 2*FTILE;
        #pragma unroll
        for (int kc = 0; kc < 4; kc++){
            uint32_t aph[4], apl[4];
            {
                float e[8] = {acc[2*kc][0], acc[2*kc][1], acc[2*kc][2], acc[2*kc][3],
                              acc[2*kc+1][0], acc[2*kc+1][1], acc[2*kc+1][2], acc[2*kc+1][3]};
                float hi[8], lo[8];
                #pragma unroll
                for (int e2 = 0; e2 < 8; e2++){
                    hi[e2] = __bfloat162float(__float2bfloat16(e[e2]));
                    lo[e2] = e[e2] - hi[e2];
                }
                aph[0] = packbf(hi[0], hi[1]); aph[1] = packbf(hi[2], hi[3]);
                aph[2] = packbf(hi[4], hi[5]); aph[3] = packbf(hi[6], hi[7]);
                apl[0] = packbf(lo[0], lo[1]); apl[1] = packbf(lo[2], lo[3]);
                apl[2] = packbf(lo[4], lo[5]); apl[3] = packbf(lo[6], lo[7]);
            }
            #pragma unroll
            for (int g = 0; g < 2; g++){
                uint32_t bfh[4][2], bfl[4][2];
                #pragma unroll
                for (int p = 0; p < 2; p++){
                    int ntb = g*4 + p*2;
                    uint32_t bd = VB + (uint32_t)(((ntb + ntOff)*8 + bRowQ)*FLDS + kc*16 + colQ)*2;
                    uint32_t r4[4];
                    ldsm4(r4, bd);
                    bfh[p*2][0]=r4[0]; bfh[p*2][1]=r4[1]; bfh[p*2+1][0]=r4[2]; bfh[p*2+1][1]=r4[3];
                    ldsm4(r4, bd + FTILE);
                    bfl[p*2][0]=r4[0]; bfl[p*2][1]=r4[1]; bfl[p*2+1][0]=r4[2]; bfl[p*2+1][1]=r4[3];
                }
                #pragma unroll
                for (int j = 0; j < 4; j++) mma16816(o[g*4+j], aph, bfh[j]);
                #pragma unroll
                for (int j = 0; j < 4; j++) mma16816(o[g*4+j], aph, bfl[j]);
                #pragma unroll
                for (int j = 0; j < 4; j++) mma16816(o[g*4+j], apl, bfh[j]);
            }
        }
        __syncthreads();
    }

    // ---- self-key fixup ----
    if (t0 >= TRAIN){
        float mm[2] = {m0, m1}, ll[2] = {l0, l1};
        #pragma unroll
        for (int r = 0; r < 2; r++){
            int trow = t0 + warp*16 + r0 + 8*r;
            size_t qb = ((size_t)(b*Tt + trow))*1536 + h*64;
            float part = 0.f;
            #pragma unroll
            for (int d = 0; d < 16; d++)
                part += g_qkv[qb + cq*16 + d] * g_qkv[qb + 512 + cq*16 + d];
            part += __shfl_xor_sync(~0u, part, 1);
            part += __shfl_xor_sync(~0u, part, 2);
            float mn = fmaxf(mm[r], part);
            float al = __expf(mm[r] - mn);
            float p  = __expf(part - mn);
            ll[r] = ll[r]*al + p;
            const float* vs = g_qkv + qb + 1024;
            #pragma unroll
            for (int nt = 0; nt < 8; nt++){
                o[nt][2*r+0] = o[nt][2*r+0]*al + p*vs[nt*8 + 2*cq + 0];
                o[nt][2*r+1] = o[nt][2*r+1]*al + p*vs[nt*8 + 2*cq + 1];
            }
        }
        l0 = ll[0]; l1 = ll[1];
    }

    // ---- normalize + split write ----
    float inv[2] = {1.f/l0, 1.f/l1};
    #pragma unroll
    for (int r = 0; r < 2; r++){
        int trow = t0 + warp*16 + r0 + 8*r;
        size_t ob = ((size_t)(b*Tt + trow))*Dd + h*64;
        #pragma unroll
        for (int nt = 0; nt < 8; nt++){
            #pragma unroll
            for (int j = 0; j < 2; j++){
                float v = o[nt][2*r+j]*inv[r];
                size_t off = ob + nt*8 + 2*cq + j;
                split2(v, g_ah[off], g_al[off]);
            }
        }
    }
}

// ---------------- split-bf16 HMMA GEMM (3-stage, 1 sync/chunk) ----------------
#define BK 32
#define LDS 40
#define TILE_B (128*LDS*2)
#define STAGE_B (4*TILE_B)
#define GSM (3*STAGE_B)

__global__ __launch_bounds__(256) void mma_gemm(
    const bf16* __restrict__ Ah, const bf16* __restrict__ Al,
    const bf16* __restrict__ Bh, const bf16* __restrict__ Bl,
    const float* __restrict__ bias, const float* __restrict__ res,
    float* C, bf16* Chi, bf16* Clo,
    int K, int ldb, int Nreal, int ldC, size_t sA, size_t sB, size_t sC, int EPI)
{
    extern __shared__ __align__(128) char smem[];
    const uint32_t sb = smem_u32(smem);
    const int tid = threadIdx.x, lane = tid & 31, wid = tid >> 5;
    const int m0 = blockIdx.y*128, n0 = blockIdx.x*128;
    const size_t zb = blockIdx.z;
    const bf16* pAh = Ah + zb*sA + (size_t)m0*K;
    const bf16* pAl = Al + zb*sA + (size_t)m0*K;
    const bf16* pBh = Bh + zb*sB + (size_t)n0*ldb;
    const bf16* pBl = Bl + zb*sB + (size_t)n0*ldb;

    float acc[4][4][4] = {};
    const int nk = K/BK;

    auto issue = [&](int c, int s){
        uint32_t base = sb + s*STAGE_B;
        #pragma unroll
        for (int i = 0; i < 2; i++){
            int seg = tid + i*256;
            int row = seg >> 2, s4 = seg & 3;
            uint32_t doff = (uint32_t)(row*LDS + s4*8)*2;
            const size_t go = (size_t)row*K + c*BK + s4*8;
            const size_t gob = (size_t)row*ldb + c*BK + s4*8;
            cpasync16(base + 0*TILE_B + doff, pAh + go);
            cpasync16(base + 1*TILE_B + doff, pAl + go);
            cpasync16(base + 2*TILE_B + doff, pBh + gob);
            cpasync16(base + 3*TILE_B + doff, pBl + gob);
        }
        asm volatile("cp.async.commit_group;" ::: "memory");
    };

    issue(0, 0);
    issue(1, 1);
    const int wm = (wid>>2)*64, wn = (wid&3)*32;
    const int aRow = lane & 15, aCol = (lane >> 4)*8;
    const int bQuad = lane >> 3, bRowQ = lane & 7;
    const int ntOff = bQuad >> 1, colQ = (bQuad & 1)*8;

    int st = 0;
    for (int c = 0; c < nk; c++){
        if (c+1 < nk) asm volatile("cp.async.wait_group 1;" ::: "memory");
        else          asm volatile("cp.async.wait_group 0;" ::: "memory");
        __syncthreads();
        if (c+2 < nk){
            int s2 = st + 2; if (s2 >= 3) s2 -= 3;
            issue(c+2, s2);
        }
        uint32_t base = sb + st*STAGE_B;
        #pragma unroll
        for (int ks = 0; ks < 2; ks++){
            uint32_t a_h[4][4], a_l[4][4], b_h[4][2], b_l[4][2];
            #pragma unroll
            for (int mt = 0; mt < 4; mt++){
                uint32_t ad = base + (uint32_t)((wm + mt*16 + aRow)*LDS + ks*16 + aCol)*2;
                ldsm4(a_h[mt], ad);
                ldsm4(a_l[mt], ad + TILE_B);
            }
            #pragma unroll
            for (int p = 0; p < 2; p++){
                uint32_t bd = base + 2*TILE_B + (uint32_t)((wn + (p*2 + ntOff)*8 + bRowQ)*LDS + ks*16 + colQ)*2;
                uint32_t r4[4];
                ldsm4(r4, bd);
                b_h[p*2][0]=r4[0]; b_h[p*2][1]=r4[1]; b_h[p*2+1][0]=r4[2]; b_h[p*2+1][1]=r4[3];
                ldsm4(r4, bd + TILE_B);
                b_l[p*2][0]=r4[0]; b_l[p*2][1]=r4[1]; b_l[p*2+1][0]=r4[2]; b_l[p*2+1][1]=r4[3];
            }
            #pragma unroll
            for (int mt = 0; mt < 4; mt++)
                #pragma unroll
                for (int nt = 0; nt < 4; nt++){
                    mma16816(acc[mt][nt], a_h[mt], b_h[nt]);
                    mma16816(acc[mt][nt], a_h[mt], b_l[nt]);
                    mma16816(acc[mt][nt], a_l[mt], b_h[nt]);
                }
        }
        st++; if (st >= 3) st -= 3;
    }

    const int r0 = lane >> 2, cW = (lane & 3)*2;
    #pragma unroll
    for (int mt = 0; mt < 4; mt++)
    #pragma unroll
    for (int hh2 = 0; hh2 < 2; hh2++){
        int gm = m0 + wm + mt*16 + r0 + hh2*8;
        #pragma unroll
        for (int nt = 0; nt < 4; nt++){
            float v0 = acc[mt][nt][hh2*2+0], v1 = acc[mt][nt][hh2*2+1];
            int gn = n0 + wn + nt*8 + cW;
            size_t off = zb*sC + (size_t)gm*ldC + gn;
            if (bias){ v0 += __ldg(bias+gn); v1 += __ldg(bias+gn+1); }
            if (EPI == 1){
                split2(gelu_f(v0), Chi[off],   Clo[off]);
                split2(gelu_f(v1), Chi[off+1], Clo[off+1]);
            } else {
                if (res){ v0 += res[off]; v1 += res[off+1]; }
                if (gn   < Nreal) C[off]   = v0;
                if (gn+1 < Nreal) C[off+1] = v1;
            }
        }
    }
}

// ---------------- weight transpose + split ----------------
__global__ void wsplit_kernel(const float* __restrict__ W, bf16* oh, bf16* ol,
                              int K, int N, int Npad){
    __shared__ float sm[32][33];
    int n0 = blockIdx.x*32, k0 = blockIdx.y*32, z = blockIdx.z;
    const float* Wb = W + (size_t)z*K*N;
    size_t ob = (size_t)z*Npad*K;
    int tx = threadIdx.x, ty = threadIdx.y;
    #pragma unroll
    for (int j = 0; j < 4; j++){
        int n = n0 + tx;
        sm[ty+8*j][tx] = (n < N) ? Wb[(size_t)(k0+ty+8*j)*N + n] : 0.f;
    }
    __syncthreads();
    #pragma unroll
    for (int j = 0; j < 4; j++){
        size_t o = ob + (size_t)(n0+ty+8*j)*K + k0 + tx;
        split2(sm[tx][ty+8*j], oh[o], ol[o]);
    }
}

// ---------------- misc kernels ----------------
__global__ void embed_kernel(const float* __restrict__ R, const int* __restrict__ y,
                             const float* __restrict__ emb){
    int row = blockIdx.x, t = row & (Tt-1), b = row >> 11;
    const float4* Rr = (const float4*)(R + (size_t)row*Dd);
    float4* Or = (float4*)(g_rep + (size_t)row*Dd);
    if (t < TRAIN){
        int yv = y[b*TRAIN + t];
        const float4* E = (const float4*)(emb + (size_t)yv*Dd);
        for (int i = threadIdx.x; i < Dd/4; i += blockDim.x){
            float4 a = Rr[i]; float4 e = E[i];
            a.x += e.x; a.y += e.y; a.z += e.z; a.w += e.w;
            Or[i] = a;
        }
    } else {
        for (int i = threadIdx.x; i < Dd/4; i += blockDim.x) Or[i] = Rr[i];
    }
}

__global__ void ln_kernel(const float* __restrict__ g, const float* __restrict__ be){
    __shared__ float sh[Dd];
    __shared__ float red[4];
    int row = blockIdx.x;
    const float* xr = g_rep + (size_t)row*Dd;
    float s = 0.f;
    for (int i = threadIdx.x; i < Dd; i += 128){ float v = xr[i]; sh[i] = v; s += v; }
    #pragma unroll
    for (int o = 16; o; o >>= 1) s += __shfl_xor_sync(~0u, s, o);
    if ((threadIdx.x & 31) == 0) red[threadIdx.x >> 5] = s;
    __syncthreads();
    float mu = (red[0]+red[1]+red[2]+red[3]) * (1.f/Dd);
    float vs = 0.f;
    for (int i = threadIdx.x; i < Dd; i += 128){ float d = sh[i]-mu; vs += d*d; }
    #pragma unroll
    for (int o = 16; o; o >>= 1) vs += __shfl_xor_sync(~0u, vs, o);
    __syncthreads();
    if ((threadIdx.x & 31) == 0) red[threadIdx.x >> 5] = vs;
    __syncthreads();
    float rs = rsqrtf((red[0]+red[1]+red[2]+red[3])*(1.f/Dd) + 1e-5f);
    for (int i = threadIdx.x; i < Dd; i += 128){
        size_t o = (size_t)row*Dd + i;
        split2((sh[i]-mu)*rs*g[i] + be[i], g_hh[o], g_hl[o]);
    }
}

__global__ void rope_table_kernel(){
    int t = blockIdx.x, i = threadIdx.x;
    float inv = (float)pow(100000.0, -((double)(2*i))/64.0);
    float ang = (float)t * inv;
    g_cos[t*32+i] = cosf(ang);
    g_sin[t*32+i] = sinf(ang);
}

__global__ void rope_scatter_kernel(){
    int row = blockIdx.x, t = row & (Tt-1), b = row >> 11;
    int j = threadIdx.x, h = j >> 5, i = j & 31;
    float c = g_cos[t*32+i], s = g_sin[t*32+i];
    size_t qb = (size_t)row*1536 + h*64 + 2*i;
    float q1 = g_qkv[qb], q2 = g_qkv[qb+1];
    float r1 = (q1*c - q2*s)*0.125f, r2 = (q1*s + q2*c)*0.125f;
    g_qkv[qb] = r1; g_qkv[qb+1] = r2;
    size_t qo = ((size_t)(b*8+h)*Tt + t)*64 + 2*i;
    split2(r1, g_qh[qo], g_ql[qo]); split2(r2, g_qh[qo+1], g_ql[qo+1]);
    float k1 = g_qkv[qb+512], k2 = g_qkv[qb+513];
    float s1 = k1*c - k2*s, s2 = k1*s + k2*c;
    g_qkv[qb+512] = s1; g_qkv[qb+513] = s2;
    split2(s1, g_kh[qo], g_kl[qo]); split2(s2, g_kh[qo+1], g_kl[qo+1]);
    #pragma unroll
    for (int r = 0; r < 2; r++){
        int d = j + 256*r, h2 = d >> 6, dd = d & 63;
        float v = g_qkv[(size_t)row*1536 + 1024 + d];
        size_t vo = ((size_t)(b*8+h2)*128 + dd)*Tt + t;
        split2(v, g_Vth[vo], g_Vtl[vo]);
    }
}

__global__ void extract_kernel(){
    int r = blockIdx.x, b = r >> 9, i = r & 511;
    const float* src = g_rep + (size_t)(b*Tt + TRAIN + i)*Dd;
    for (int j = threadIdx.x; j < Dd; j += 128)
        split2(src[j], g_th[(size_t)r*Dd + j], g_tl[(size_t)r*Dd + j]);
}

// ---------------- launcher ----------------
#define SYM(p, s) cudaGetSymbolAddress((void**)&p, s)

extern "C" void kernel_launch(void* const* d_in, const int* in_sizes, int n_in,
                              void* d_out, int out_size){
    const float* R    = (const float*)d_in[0];
    const int*   y    = (const int*)  d_in[1];
    const float* emb  = (const float*)d_in[2];
    const float* Wqkv = (const float*)d_in[3];
    const float* bqkv = (const float*)d_in[4];
    const float* Wo   = (const float*)d_in[5];
    const float* bo   = (const float*)d_in[6];
    const float* ln1g = (const float*)d_in[7];
    const float* ln1b = (const float*)d_in[8];
    const float* ln2g = (const float*)d_in[9];
    const float* ln2b = (const float*)d_in[10];
    const float* W1   = (const float*)d_in[11];
    const float* b1   = (const float*)d_in[12];
    const float* W2   = (const float*)d_in[13];
    const float* b2   = (const float*)d_in[14];
    const float* pW1  = (const float*)d_in[15];
    const float* pb1  = (const float*)d_in[16];
    const float* pW2  = (const float*)d_in[17];
    const float* pb2  = (const float*)d_in[18];

    cudaFuncSetAttribute(mma_gemm, cudaFuncAttributeMaxDynamicSharedMemorySize, GSM);
    cudaFuncSetAttribute(flash_kernel, cudaFuncAttributeMaxDynamicSharedMemorySize, FSM);

    float *qkv, *rep;
    bf16 *hh,*hl,*ah,*al,*fh,*fl,*th,*tl,*gh,*gl;
    bf16 *Wqkvh,*Wqkvl,*Woh,*Wol,*W1h,*W1l,*W2h,*W2l,*pW1h,*pW1l,*pW2h,*pW2l;
    SYM(qkv,g_qkv); SYM(rep,g_rep);
    SYM(hh,g_hh); SYM(hl,g_hl); SYM(ah,g_ah); SYM(al,g_al);
    SYM(fh,g_fh); SYM(fl,g_fl);
    SYM(th,g_th); SYM(tl,g_tl);
    SYM(gh,g_gh); SYM(gl,g_gl);
    SYM(Wqkvh,g_Wqkvh); SYM(Wqkvl,g_Wqkvl); SYM(Woh,g_Woh); SYM(Wol,g_Wol);
    SYM(W1h,g_W1h); SYM(W1l,g_W1l); SYM(W2h,g_W2h); SYM(W2l,g_W2l);
    SYM(pW1h,g_pW1h); SYM(pW1l,g_pW1l); SYM(pW2h,g_pW2h); SYM(pW2l,g_pW2l);

    dim3 wb(32, 8);
    wsplit_kernel<<<dim3(48,16,12), wb>>>(Wqkv, Wqkvh, Wqkvl, 512, 1536, 1536);
    wsplit_kernel<<<dim3(16,16,12), wb>>>(Wo,   Woh,   Wol,   512, 512,  512);
    wsplit_kernel<<<dim3(64,16,12), wb>>>(W1,   W1h,   W1l,   512, 2048, 2048);
    wsplit_kernel<<<dim3(16,64,12), wb>>>(W2,   W2h,   W2l,   2048,512,  512);
    wsplit_kernel<<<dim3(32,16,1),  wb>>>(pW1,  pW1h,  pW1l,  512, 1024, 1024);
    wsplit_kernel<<<dim3(4, 32,1),  wb>>>(pW2,  pW2h,  pW2l,  1024,100,  128);

    rope_table_kernel<<<Tt, 32>>>();
    embed_kernel<<<BT, 128>>>(R, y, emb);

    for (int l = 0; l < Ll; l++){
        ln_kernel<<<BT, 128>>>(ln1g + l*Dd, ln1b + l*Dd);
        mma_gemm<<<dim3(12,64,1),256,GSM>>>(hh, hl, Wqkvh + (size_t)l*1536*512, Wqkvl + (size_t)l*1536*512,
            bqkv + l*1536, nullptr, qkv, nullptr, nullptr, 512, 512, 1536, 1536, 0,0,0, 0);
        rope_scatter_kernel<<<BT, 256>>>();
        flash_kernel<<<dim3(16, NBH), 256, FSM>>>();
        mma_gemm<<<dim3(4,64,1),256,GSM>>>(ah, al, Woh + (size_t)l*512*512, Wol + (size_t)l*512*512,
            bo + l*512, rep, rep, nullptr, nullptr, 512, 512, 512, 512, 0,0,0, 0);
        ln_kernel<<<BT, 128>>>(ln2g + l*Dd, ln2b + l*Dd);
        mma_gemm<<<dim3(16,64,1),256,GSM>>>(hh, hl, W1h + (size_t)l*2048*512, W1l + (size_t)l*2048*512,
            b1 + l*2048, nullptr, nullptr, fh, fl, 512, 512, 2048, 2048, 0,0,0, 1);
        mma_gemm<<<dim3(4,64,1),256,GSM>>>(fh, fl, W2h + (size_t)l*512*2048, W2l + (size_t)l*512*2048,
            b2 + l*512, rep, rep, nullptr, nullptr, 2048, 2048, 512, 512, 0,0,0, 0);
    }

    extract_kernel<<<MTEST, 128>>>();
    mma_gemm<<<dim3(8,16,1),256,GSM>>>(th, tl, pW1h, pW1l, pb1, nullptr,
        nullptr, gh, gl, 512, 512, 1024, 1024, 0,0,0, 1);
    mma_gemm<<<dim3(1,16,1),256,GSM>>>(gh, gl, pW2h, pW2l, pb2, nullptr,
        (float*)d_out, nullptr, nullptr, 1024, 1024, 100, 100, 0,0,0, 0);
}

// round 7
// speedup vs baseline: 1.1467x; 1.1467x over previous
#include <cuda_runtime.h>
#include <cuda_bf16.h>
#include <math.h>
#include <stdint.h>

#define Bc    4
#define Tt    2048
#define TRAIN 1536
#define Dd    512
#define Ll    12
#define FFd   2048
#define BT    (Bc*Tt)
#define NBH   32
#define MTEST 2048

typedef __nv_bfloat16 bf16;

// ---------------- static buffers ----------------
__device__ float g_rep [BT*Dd];
__device__ float g_qkv [BT*3*Dd];
__device__ bf16  g_hh[BT*Dd], g_hl[BT*Dd];
__device__ bf16  g_ah[BT*Dd], g_al[BT*Dd];
__device__ bf16  g_fh[BT*FFd], g_fl[BT*FFd];
__device__ bf16  g_qh[NBH*Tt*64], g_ql[NBH*Tt*64];
__device__ bf16  g_kh[NBH*Tt*64], g_kl[NBH*Tt*64];
__device__ bf16  g_Vth[(size_t)NBH*128*Tt], g_Vtl[(size_t)NBH*128*Tt];
__device__ bf16  g_th[MTEST*Dd], g_tl[MTEST*Dd];
__device__ bf16  g_gh[MTEST*2*Dd], g_gl[MTEST*2*Dd];
__device__ bf16  g_Wqkvh[Ll*3*Dd*Dd], g_Wqkvl[Ll*3*Dd*Dd];
__device__ bf16  g_Woh[Ll*Dd*Dd],  g_Wol[Ll*Dd*Dd];
__device__ bf16  g_W1h[Ll*FFd*Dd], g_W1l[Ll*FFd*Dd];
__device__ bf16  g_W2h[Ll*Dd*FFd], g_W2l[Ll*Dd*FFd];
__device__ bf16  g_pW1h[2*Dd*Dd],  g_pW1l[2*Dd*Dd];
__device__ bf16  g_pW2h[128*2*Dd], g_pW2l[128*2*Dd];
__device__ float g_cos[Tt*32], g_sin[Tt*32];

// ---------------- helpers ----------------
__device__ __forceinline__ float gelu_f(float x){
    float y = 0.7978845608028654f*(x + 0.044715f*x*x*x);
    float yc = fminf(fmaxf(y, -15.f), 15.f);
    float t = __expf(2.f*yc);
    float th = (t - 1.f)/(t + 1.f);
    return 0.5f*x*(1.f + th);
}
__device__ __forceinline__ void split2(float x, bf16& h, bf16& l){
    h = __float2bfloat16(x);
    l = __float2bfloat16(x - __bfloat162float(h));
}
__device__ __forceinline__ uint32_t smem_u32(const void* p){
    uint32_t a;
    asm("{ .reg .u64 t; cvta.to.shared.u64 t, %1; cvt.u32.u64 %0, t; }" : "=r"(a) : "l"(p));
    return a;
}
__device__ __forceinline__ void cpasync16(uint32_t dst, const void* src){
    asm volatile("cp.async.cg.shared.global [%0], [%1], 16;" :: "r"(dst), "l"(src) : "memory");
}
__device__ __forceinline__ void ldsm4(uint32_t* r, uint32_t a){
    asm volatile("ldmatrix.sync.aligned.m8n8.x4.shared.b16 {%0,%1,%2,%3}, [%4];"
        : "=r"(r[0]),"=r"(r[1]),"=r"(r[2]),"=r"(r[3]) : "r"(a));
}
__device__ __forceinline__ void mma16816(float* c, const uint32_t* a, const uint32_t* b){
    asm volatile("mma.sync.aligned.m16n8k16.row.col.f32.bf16.bf16.f32 "
        "{%0,%1,%2,%3}, {%4,%5,%6,%7}, {%8,%9}, {%0,%1,%2,%3};"
        : "+f"(c[0]),"+f"(c[1]),"+f"(c[2]),"+f"(c[3])
        : "r"(a[0]),"r"(a[1]),"r"(a[2]),"r"(a[3]), "r"(b[0]),"r"(b[1]));
}
__device__ __forceinline__ uint32_t packbf(float lo, float hi){
    uint32_t r;
    asm("cvt.rn.bf16x2.f32 %0, %1, %2;" : "=r"(r) : "f"(hi), "f"(lo));
    return r;
}

// ================= fused flash attention =================
#define FLDS 72
#define FTILE (64*FLDS*2)
#define FQT   (128*FLDS*2)
#define FSTG  (4*FTILE)
#define FSM   (2*FQT + 2*FSTG)

__global__ __launch_bounds__(256) void flash_kernel(){
    extern __shared__ __align__(128) char smem[];
    const uint32_t sb = smem_u32(smem);
    const int tid = threadIdx.x, lane = tid & 31, warp = tid >> 5;
    const int bh = blockIdx.y, b = bh >> 3, h = bh & 7;
    const int t0 = blockIdx.x * 128;
    const int r0 = lane >> 2, cq = lane & 3;
    const int aRow = lane & 15, aCol = (lane >> 4)*8;
    const int bQuad = lane >> 3, bRowQ = lane & 7;
    const int ntOff = bQuad >> 1, colQ = (bQuad & 1)*8;
    const uint32_t QH = sb, ST0 = sb + 2*FQT;

    {
        #pragma unroll
        for (int i = 0; i < 8; i++){
            int idx = tid + i*256;
            int tile = idx >> 10, rem = idx & 1023;
            int row = rem >> 3, ch = rem & 7;
            const bf16* src = (tile ? g_ql : g_qh) + ((size_t)bh*Tt + t0 + row)*64 + ch*8;
            cpasync16(sb + tile*FQT + (uint32_t)(row*FLDS + ch*8)*2, src);
        }
        #pragma unroll
        for (int i = 0; i < 8; i++){
            int idx = tid + i*256;
            int tile = idx >> 9, rem = idx & 511;
            int row = rem >> 3, ch = rem & 7;
            const bf16* src;
            if (tile == 0)      src = g_kh  + ((size_t)bh*Tt + row)*64 + ch*8;
            else if (tile == 1) src = g_kl  + ((size_t)bh*Tt + row)*64 + ch*8;
            else if (tile == 2) src = g_Vth + ((size_t)bh*128 + row)*Tt + ch*8;
            else                src = g_Vtl + ((size_t)bh*128 + row)*Tt + ch*8;
            cpasync16(ST0 + tile*FTILE + (uint32_t)(row*FLDS + ch*8)*2, src);
        }
        asm volatile("cp.async.commit_group;" ::: "memory");
    }

    float o[8][4] = {};
    float m0 = -INFINITY, m1 = -INFINITY, l0 = 0.f, l1 = 0.f;
    uint32_t qfh[4][4], qfl[4][4];

    for (int kt = 0; kt < 24; kt++){
        int s = kt & 1;
        if (kt + 1 < 24){
            int s2 = s ^ 1, s0n = (kt+1)*64;
            uint32_t base = ST0 + s2*FSTG;
            #pragma unroll
            for (int i = 0; i < 8; i++){
                int idx = tid + i*256;
                int tile = idx >> 9, rem = idx & 511;
                int row = rem >> 3, ch = rem & 7;
                const bf16* src;
                if (tile == 0)      src = g_kh  + ((size_t)bh*Tt + s0n + row)*64 + ch*8;
                else if (tile == 1) src = g_kl  + ((size_t)bh*Tt + s0n + row)*64 + ch*8;
                else if (tile == 2) src = g_Vth + ((size_t)bh*128 + row)*Tt + s0n + ch*8;
                else                src = g_Vtl + ((size_t)bh*128 + row)*Tt + s0n + ch*8;
                cpasync16(base + tile*FTILE + (uint32_t)(row*FLDS + ch*8)*2, src);
            }
            asm volatile("cp.async.commit_group;" ::: "memory");
            asm volatile("cp.async.wait_group 1;" ::: "memory");
        } else {
            asm volatile("cp.async.wait_group 0;" ::: "memory");
        }
        __syncthreads();

        if (kt == 0){
            #pragma unroll
            for (int ks = 0; ks < 4; ks++){
                uint32_t ad = QH + (uint32_t)((warp*16 + aRow)*FLDS + ks*16 + aCol)*2;
                ldsm4(qfh[ks], ad);
                ldsm4(qfl[ks], ad + FQT);
            }
        }

        uint32_t KB = ST0 + s*FSTG;
        float acc[8][4] = {};
        #pragma unroll
        for (int ks = 0; ks < 4; ks++){
            #pragma unroll
            for (int g = 0; g < 2; g++){
                uint32_t bfh[4][2], bfl[4][2];
                #pragma unroll
                for (int p = 0; p < 2; p++){
                    int ntb = g*4 + p*2;
                    uint32_t bd = KB + (uint32_t)(((ntb + ntOff)*8 + bRowQ)*FLDS + ks*16 + colQ)*2;
                    uint32_t r4[4];
                    ldsm4(r4, bd);
                    bfh[p*2][0]=r4[0]; bfh[p*2][1]=r4[1]; bfh[p*2+1][0]=r4[2]; bfh[p*2+1][1]=r4[3];
                    ldsm4(r4, bd + FTILE);
                    bfl[p*2][0]=r4[0]; bfl[p*2][1]=r4[1]; bfl[p*2+1][0]=r4[2]; bfl[p*2+1][1]=r4[3];
                }
                #pragma unroll
                for (int j = 0; j < 4; j++) mma16816(acc[g*4+j], qfh[ks], bfh[j]);
                #pragma unroll
                for (int j = 0; j < 4; j++) mma16816(acc[g*4+j], qfh[ks], bfl[j]);
                #pragma unroll
                for (int j = 0; j < 4; j++) mma16816(acc[g*4+j], qfl[ks], bfh[j]);
            }
        }

        // ---- online softmax ----
        float tm0 = -INFINITY, tm1 = -INFINITY;
        #pragma unroll
        for (int nt = 0; nt < 8; nt++){
            tm0 = fmaxf(tm0, fmaxf(acc[nt][0], acc[nt][1]));
            tm1 = fmaxf(tm1, fmaxf(acc[nt][2], acc[nt][3]));
        }
        tm0 = fmaxf(tm0, __shfl_xor_sync(~0u, tm0, 1));
        tm0 = fmaxf(tm0, __shfl_xor_sync(~0u, tm0, 2));
        tm1 = fmaxf(tm1, __shfl_xor_sync(~0u, tm1, 1));
        tm1 = fmaxf(tm1, __shfl_xor_sync(~0u, tm1, 2));
        float mn0 = fmaxf(m0, tm0), mn1 = fmaxf(m1, tm1);
        float al0 = __expf(m0 - mn0), al1 = __expf(m1 - mn1);
        float ps0 = 0.f, ps1 = 0.f;
        #pragma unroll
        for (int nt = 0; nt < 8; nt++){
            acc[nt][0] = __expf(acc[nt][0] - mn0);
            acc[nt][1] = __expf(acc[nt][1] - mn0);
            acc[nt][2] = __expf(acc[nt][2] - mn1);
            acc[nt][3] = __expf(acc[nt][3] - mn1);
            ps0 += acc[nt][0] + acc[nt][1];
            ps1 += acc[nt][2] + acc[nt][3];
        }
        ps0 += __shfl_xor_sync(~0u, ps0, 1); ps0 += __shfl_xor_sync(~0u, ps0, 2);
        ps1 += __shfl_xor_sync(~0u, ps1, 1); ps1 += __shfl_xor_sync(~0u, ps1, 2);
        l0 = l0*al0 + ps0; l1 = l1*al1 + ps1;
        m0 = mn0; m1 = mn1;
        #pragma unroll
        for (int nt = 0; nt < 8; nt++){
            o[nt][0] *= al0; o[nt][1] *= al0; o[nt][2] *= al1; o[nt][3] *= al1;
        }

        // ---- O += P V ----
        uint32_t VB = KB + 2*FTILE;
        #pragma unroll
        for (int kc = 0; kc < 4; kc++){
            uint32_t aph[4], apl[4];
            {
                float e[8] = {acc[2*kc][0], acc[2*kc][1], acc[2*kc][2], acc[2*kc][3],
                              acc[2*kc+1][0], acc[2*kc+1][1], acc[2*kc+1][2], acc[2*kc+1][3]};
                float hi[8], lo[8];
                #pragma unroll
                for (int e2 = 0; e2 < 8; e2++){
                    hi[e2] = __bfloat162float(__float2bfloat16(e[e2]));
                    lo[e2] = e[e2] - hi[e2];
                }
                aph[0] = packbf(hi[0], hi[1]); aph[1] = packbf(hi[2], hi[3]);
                aph[2] = packbf(hi[4], hi[5]); aph[3] = packbf(hi[6], hi[7]);
                apl[0] = packbf(lo[0], lo[1]); apl[1] = packbf(lo[2], lo[3]);
                apl[2] = packbf(lo[4], lo[5]); apl[3] = packbf(lo[6], lo[7]);
            }
            #pragma unroll
            for (int g = 0; g < 2; g++){
                uint32_t bfh[4][2], bfl[4][2];
                #pragma unroll
                for (int p = 0; p < 2; p++){
                    int ntb = g*4 + p*2;
                    uint32_t bd = VB + (uint32_t)(((ntb + ntOff)*8 + bRowQ)*FLDS + kc*16 + colQ)*2;
                    uint32_t r4[4];
                    ldsm4(r4, bd);
                    bfh[p*2][0]=r4[0]; bfh[p*2][1]=r4[1]; bfh[p*2+1][0]=r4[2]; bfh[p*2+1][1]=r4[3];
                    ldsm4(r4, bd + FTILE);
                    bfl[p*2][0]=r4[0]; bfl[p*2][1]=r4[1]; bfl[p*2+1][0]=r4[2]; bfl[p*2+1][1]=r4[3];
                }
                #pragma unroll
                for (int j = 0; j < 4; j++) mma16816(o[g*4+j], aph, bfh[j]);
                #pragma unroll
                for (int j = 0; j < 4; j++) mma16816(o[g*4+j], aph, bfl[j]);
                #pragma unroll
                for (int j = 0; j < 4; j++) mma16816(o[g*4+j], apl, bfh[j]);
            }
        }
        __syncthreads();
    }

    // ---- self-key fixup ----
    if (t0 >= TRAIN){
        float mm[2] = {m0, m1}, ll[2] = {l0, l1};
        #pragma unroll
        for (int r = 0; r < 2; r++){
            int trow = t0 + warp*16 + r0 + 8*r;
            size_t qb = ((size_t)(b*Tt + trow))*1536 + h*64;
            float part = 0.f;
            #pragma unroll
            for (int d = 0; d < 16; d++)
                part += g_qkv[qb + cq*16 + d] * g_qkv[qb + 512 + cq*16 + d];
            part += __shfl_xor_sync(~0u, part, 1);
            part += __shfl_xor_sync(~0u, part, 2);
            float mn = fmaxf(mm[r], part);
            float al = __expf(mm[r] - mn);
            float p  = __expf(part - mn);
            ll[r] = ll[r]*al + p;
            const float* vs = g_qkv + qb + 1024;
            #pragma unroll
            for (int nt = 0; nt < 8; nt++){
                o[nt][2*r+0] = o[nt][2*r+0]*al + p*vs[nt*8 + 2*cq + 0];
                o[nt][2*r+1] = o[nt][2*r+1]*al + p*vs[nt*8 + 2*cq + 1];
            }
        }
        l0 = ll[0]; l1 = ll[1];
    }

    // ---- normalize + split write ----
    float inv[2] = {1.f/l0, 1.f/l1};
    #pragma unroll
    for (int r = 0; r < 2; r++){
        int trow = t0 + warp*16 + r0 + 8*r;
        size_t ob = ((size_t)(b*Tt + trow))*Dd + h*64;
        #pragma unroll
        for (int nt = 0; nt < 8; nt++){
            #pragma unroll
            for (int j = 0; j < 2; j++){
                float v = o[nt][2*r+j]*inv[r];
                size_t off = ob + nt*8 + 2*cq + j;
                split2(v, g_ah[off], g_al[off]);
            }
        }
    }
}

// ---------------- split-bf16 HMMA GEMM (2-stage, R5 schedule) ----------------
#define BK 32
#define LDS 40
#define TILE_B (128*LDS*2)
#define STAGE_B (4*TILE_B)
#define GSM (2*STAGE_B)

__global__ __launch_bounds__(256, 2) void mma_gemm(
    const bf16* __restrict__ Ah, const bf16* __restrict__ Al,
    const bf16* __restrict__ Bh, const bf16* __restrict__ Bl,
    const float* __restrict__ bias, const float* __restrict__ res,
    float* C, bf16* Chi, bf16* Clo,
    int K, int ldb, int Nreal, int ldC, size_t sA, size_t sB, size_t sC, int EPI)
{
    extern __shared__ __align__(128) char smem[];
    const uint32_t sb = smem_u32(smem);
    const int tid = threadIdx.x, lane = tid & 31, wid = tid >> 5;
    const int m0 = blockIdx.y*128, n0 = blockIdx.x*128;
    const size_t zb = blockIdx.z;
    const bf16* pAh = Ah + zb*sA + (size_t)m0*K;
    const bf16* pAl = Al + zb*sA + (size_t)m0*K;
    const bf16* pBh = Bh + zb*sB + (size_t)n0*ldb;
    const bf16* pBl = Bl + zb*sB + (size_t)n0*ldb;

    float acc[4][4][4] = {};
    const int nk = K/BK;

    auto issue = [&](int c, int s){
        uint32_t base = sb + s*STAGE_B;
        #pragma unroll
        for (int i = 0; i < 2; i++){
            int seg = tid + i*256;
            int row = seg >> 2, s4 = seg & 3;
            uint32_t doff = (uint32_t)(row*LDS + s4*8)*2;
            const size_t go = (size_t)row*K + c*BK + s4*8;
            const size_t gob = (size_t)row*ldb + c*BK + s4*8;
            cpasync16(base + 0*TILE_B + doff, pAh + go);
            cpasync16(base + 1*TILE_B + doff, pAl + go);
            cpasync16(base + 2*TILE_B + doff, pBh + gob);
            cpasync16(base + 3*TILE_B + doff, pBl + gob);
        }
        asm volatile("cp.async.commit_group;" ::: "memory");
    };

    issue(0, 0);
    const int wm = (wid>>2)*64, wn = (wid&3)*32;
    const int aRow = lane & 15, aCol = (lane >> 4)*8;
    const int bQuad = lane >> 3, bRowQ = lane & 7;
    const int ntOff = bQuad >> 1, colQ = (bQuad & 1)*8;

    for (int c = 0; c < nk; c++){
        int s = c & 1;
        if (c+1 < nk){
            issue(c+1, s^1);
            asm volatile("cp.async.wait_group 1;" ::: "memory");
        } else {
            asm volatile("cp.async.wait_group 0;" ::: "memory");
        }
        __syncthreads();
        uint32_t base = sb + s*STAGE_B;
        #pragma unroll
        for (int ks = 0; ks < 2; ks++){
            uint32_t a_h[4][4], a_l[4][4], b_h[4][2], b_l[4][2];
            #pragma unroll
            for (int mt = 0; mt < 4; mt++){
                uint32_t ad = base + (uint32_t)((wm + mt*16 + aRow)*LDS + ks*16 + aCol)*2;
                ldsm4(a_h[mt], ad);
                ldsm4(a_l[mt], ad + TILE_B);
            }
            #pragma unroll
            for (int p = 0; p < 2; p++){
                uint32_t bd = base + 2*TILE_B + (uint32_t)((wn + (p*2 + ntOff)*8 + bRowQ)*LDS + ks*16 + colQ)*2;
                uint32_t r4[4];
                ldsm4(r4, bd);
                b_h[p*2][0]=r4[0]; b_h[p*2][1]=r4[1]; b_h[p*2+1][0]=r4[2]; b_h[p*2+1][1]=r4[3];
                ldsm4(r4, bd + TILE_B);
                b_l[p*2][0]=r4[0]; b_l[p*2][1]=r4[1]; b_l[p*2+1][0]=r4[2]; b_l[p*2+1][1]=r4[3];
            }
            #pragma unroll
            for (int mt = 0; mt < 4; mt++)
                #pragma unroll
                for (int nt = 0; nt < 4; nt++){
                    mma16816(acc[mt][nt], a_h[mt], b_h[nt]);
                    mma16816(acc[mt][nt], a_h[mt], b_l[nt]);
                    mma16816(acc[mt][nt], a_l[mt], b_h[nt]);
                }
        }
        __syncthreads();
    }

    const int r0 = lane >> 2, cW = (lane & 3)*2;
    #pragma unroll
    for (int mt = 0; mt < 4; mt++)
    #pragma unroll
    for (int hh2 = 0; hh2 < 2; hh2++){
        int gm = m0 + wm + mt*16 + r0 + hh2*8;
        #pragma unroll
        for (int nt = 0; nt < 4; nt++){
            float v0 = acc[mt][nt][hh2*2+0], v1 = acc[mt][nt][hh2*2+1];
            int gn = n0 + wn + nt*8 + cW;
            size_t off = zb*sC + (size_t)gm*ldC + gn;
            if (bias){ v0 += __ldg(bias+gn); v1 += __ldg(bias+gn+1); }
            if (EPI == 1){
                split2(gelu_f(v0), Chi[off],   Clo[off]);
                split2(gelu_f(v1), Chi[off+1], Clo[off+1]);
            } else {
                if (res){ v0 += res[off]; v1 += res[off+1]; }
                if (gn   < Nreal) C[off]   = v0;
                if (gn+1 < Nreal) C[off+1] = v1;
            }
        }
    }
}

// ---------------- weight transpose + split ----------------
__global__ void wsplit_kernel(const float* __restrict__ W, bf16* oh, bf16* ol,
                              int K, int N, int Npad){
    __shared__ float sm[32][33];
    int n0 = blockIdx.x*32, k0 = blockIdx.y*32, z = blockIdx.z;
    const float* Wb = W + (size_t)z*K*N;
    size_t ob = (size_t)z*Npad*K;
    int tx = threadIdx.x, ty = threadIdx.y;
    #pragma unroll
    for (int j = 0; j < 4; j++){
        int n = n0 + tx;
        sm[ty+8*j][tx] = (n < N) ? Wb[(size_t)(k0+ty+8*j)*N + n] : 0.f;
    }
    __syncthreads();
    #pragma unroll
    for (int j = 0; j < 4; j++){
        size_t o = ob + (size_t)(n0+ty+8*j)*K + k0 + tx;
        split2(sm[tx][ty+8*j], oh[o], ol[o]);
    }
}

// ---------------- misc kernels ----------------
__global__ void embed_kernel(const float* __restrict__ R, const int* __restrict__ y,
                             const float* __restrict__ emb){
    int row = blockIdx.x, t = row & (Tt-1), b = row >> 11;
    const float4* Rr = (const float4*)(R + (size_t)row*Dd);
    float4* Or = (float4*)(g_rep + (size_t)row*Dd);
    if (t < TRAIN){
        int yv = y[b*TRAIN + t];
        const float4* E = (const float4*)(emb + (size_t)yv*Dd);
        for (int i = threadIdx.x; i < Dd/4; i += blockDim.x){
            float4 a = Rr[i]; float4 e = E[i];
            a.x += e.x; a.y += e.y; a.z += e.z; a.w += e.w;
            Or[i] = a;
        }
    } else {
        for (int i = threadIdx.x; i < Dd/4; i += blockDim.x) Or[i] = Rr[i];
    }
}

__global__ void ln_kernel(const float* __restrict__ g, const float* __restrict__ be){
    __shared__ float sh[Dd];
    __shared__ float red[4];
    int row = blockIdx.x;
    const float* xr = g_rep + (size_t)row*Dd;
    float s = 0.f;
    for (int i = threadIdx.x; i < Dd; i += 128){ float v = xr[i]; sh[i] = v; s += v; }
    #pragma unroll
    for (int o = 16; o; o >>= 1) s += __shfl_xor_sync(~0u, s, o);
    if ((threadIdx.x & 31) == 0) red[threadIdx.x >> 5] = s;
    __syncthreads();
    float mu = (red[0]+red[1]+red[2]+red[3]) * (1.f/Dd);
    float vs = 0.f;
    for (int i = threadIdx.x; i < Dd; i += 128){ float d = sh[i]-mu; vs += d*d; }
    #pragma unroll
    for (int o = 16; o; o >>= 1) vs += __shfl_xor_sync(~0u, vs, o);
    __syncthreads();
    if ((threadIdx.x & 31) == 0) red[threadIdx.x >> 5] = vs;
    __syncthreads();
    float rs = rsqrtf((red[0]+red[1]+red[2]+red[3])*(1.f/Dd) + 1e-5f);
    for (int i = threadIdx.x; i < Dd; i += 128){
        size_t o = (size_t)row*Dd + i;
        split2((sh[i]-mu)*rs*g[i] + be[i], g_hh[o], g_hl[o]);
    }
}

__global__ void rope_table_kernel(){
    int t = blockIdx.x, i = threadIdx.x;
    float inv = (float)pow(100000.0, -((double)(2*i))/64.0);
    float ang = (float)t * inv;
    g_cos[t*32+i] = cosf(ang);
    g_sin[t*32+i] = sinf(ang);
}

__global__ void rope_scatter_kernel(){
    int row = blockIdx.x, t = row & (Tt-1), b = row >> 11;
    int j = threadIdx.x, h = j >> 5, i = j & 31;
    float c = g_cos[t*32+i], s = g_sin[t*32+i];
    size_t qb = (size_t)row*1536 + h*64 + 2*i;
    float q1 = g_qkv[qb], q2 = g_qkv[qb+1];
    float r1 = (q1*c - q2*s)*0.125f, r2 = (q1*s + q2*c)*0.125f;
    g_qkv[qb] = r1; g_qkv[qb+1] = r2;
    size_t qo = ((size_t)(b*8+h)*Tt + t)*64 + 2*i;
    split2(r1, g_qh[qo], g_ql[qo]); split2(r2, g_qh[qo+1], g_ql[qo+1]);
    float k1 = g_qkv[qb+512], k2 = g_qkv[qb+513];
    float s1 = k1*c - k2*s, s2 = k1*s + k2*c;
    g_qkv[qb+512] = s1; g_qkv[qb+513] = s2;
    split2(s1, g_kh[qo], g_kl[qo]); split2(s2, g_kh[qo+1], g_kl[qo+1]);
    #pragma unroll
    for (int r = 0; r < 2; r++){
        int d = j + 256*r, h2 = d >> 6, dd = d & 63;
        float v = g_qkv[(size_t)row*1536 + 1024 + d];
        size_t vo = ((size_t)(b*8+h2)*128 + dd)*Tt + t;
        split2(v, g_Vth[vo], g_Vtl[vo]);
    }
}

__global__ void extract_kernel(){
    int r = blockIdx.x, b = r >> 9, i = r & 511;
    const float* src = g_rep + (size_t)(b*Tt + TRAIN + i)*Dd;
    for (int j = threadIdx.x; j < Dd; j += 128)
        split2(src[j], g_th[(size_t)r*Dd + j], g_tl[(size_t)r*Dd + j]);
}

// ---------------- launcher ----------------
#define SYM(p, s) cudaGetSymbolAddress((void**)&p, s)

extern "C" void kernel_launch(void* const* d_in, const int* in_sizes, int n_in,
                              void* d_out, int out_size){
    const float* R    = (const float*)d_in[0];
    const int*   y    = (const int*)  d_in[1];
    const float* emb  = (const float*)d_in[2];
    const float* Wqkv = (const float*)d_in[3];
    const float* bqkv = (const float*)d_in[4];
    const float* Wo   = (const float*)d_in[5];
    const float* bo   = (const float*)d_in[6];
    const float* ln1g = (const float*)d_in[7];
    const float* ln1b = (const float*)d_in[8];
    const float* ln2g = (const float*)d_in[9];
    const float* ln2b = (const float*)d_in[10];
    const float* W1   = (const float*)d_in[11];
    const float* b1   = (const float*)d_in[12];
    const float* W2   = (const float*)d_in[13];
    const float* b2   = (const float*)d_in[14];
    const float* pW1  = (const float*)d_in[15];
    const float* pb1  = (const float*)d_in[16];
    const float* pW2  = (const float*)d_in[17];
    const float* pb2  = (const float*)d_in[18];

    cudaFuncSetAttribute(mma_gemm, cudaFuncAttributeMaxDynamicSharedMemorySize, GSM);
    cudaFuncSetAttribute(flash_kernel, cudaFuncAttributeMaxDynamicSharedMemorySize, FSM);

    float *qkv, *rep;
    bf16 *hh,*hl,*ah,*al,*fh,*fl,*th,*tl,*gh,*gl;
    bf16 *Wqkvh,*Wqkvl,*Woh,*Wol,*W1h,*W1l,*W2h,*W2l,*pW1h,*pW1l,*pW2h,*pW2l;
    SYM(qkv,g_qkv); SYM(rep,g_rep);
    SYM(hh,g_hh); SYM(hl,g_hl); SYM(ah,g_ah); SYM(al,g_al);
    SYM(fh,g_fh); SYM(fl,g_fl);
    SYM(th,g_th); SYM(tl,g_tl);
    SYM(gh,g_gh); SYM(gl,g_gl);
    SYM(Wqkvh,g_Wqkvh); SYM(Wqkvl,g_Wqkvl); SYM(Woh,g_Woh); SYM(Wol,g_Wol);
    SYM(W1h,g_W1h); SYM(W1l,g_W1l); SYM(W2h,g_W2h); SYM(W2l,g_W2l);
    SYM(pW1h,g_pW1h); SYM(pW1l,g_pW1l); SYM(pW2h,g_pW2h); SYM(pW2l,g_pW2l);

    dim3 wb(32, 8);
    wsplit_kernel<<<dim3(48,16,12), wb>>>(Wqkv, Wqkvh, Wqkvl, 512, 1536, 1536);
    wsplit_kernel<<<dim3(16,16,12), wb>>>(Wo,   Woh,   Wol,   512, 512,  512);
    wsplit_kernel<<<dim3(64,16,12), wb>>>(W1,   W1h,   W1l,   512, 2048, 2048);
    wsplit_kernel<<<dim3(16,64,12), wb>>>(W2,   W2h,   W2l,   2048,512,  512);
    wsplit_kernel<<<dim3(32,16,1),  wb>>>(pW1,  pW1h,  pW1l,  512, 1024, 1024);
    wsplit_kernel<<<dim3(4, 32,1),  wb>>>(pW2,  pW2h,  pW2l,  1024,100,  128);

    rope_table_kernel<<<Tt, 32>>>();
    embed_kernel<<<BT, 128>>>(R, y, emb);

    for (int l = 0; l < Ll; l++){
        ln_kernel<<<BT, 128>>>(ln1g + l*Dd, ln1b + l*Dd);
        mma_gemm<<<dim3(12,64,1),256,GSM>>>(hh, hl, Wqkvh + (size_t)l*1536*512, Wqkvl + (size_t)l*1536*512,
            bqkv + l*1536, nullptr, qkv, nullptr, nullptr, 512, 512, 1536, 1536, 0,0,0, 0);
        rope_scatter_kernel<<<BT, 256>>>();
        flash_kernel<<<dim3(16, NBH), 256, FSM>>>();
        mma_gemm<<<dim3(4,64,1),256,GSM>>>(ah, al, Woh + (size_t)l*512*512, Wol + (size_t)l*512*512,
            bo + l*512, rep, rep, nullptr, nullptr, 512, 512, 512, 512, 0,0,0, 0);
        ln_kernel<<<BT, 128>>>(ln2g + l*Dd, ln2b + l*Dd);
        mma_gemm<<<dim3(16,64,1),256,GSM>>>(hh, hl, W1h + (size_t)l*2048*512, W1l + (size_t)l*2048*512,
            b1 + l*2048, nullptr, nullptr, fh, fl, 512, 512, 2048, 2048, 0,0,0, 1);
        mma_gemm<<<dim3(4,64,1),256,GSM>>>(fh, fl, W2h + (size_t)l*512*2048, W2l + (size_t)l*512*2048,
            b2 + l*512, rep, rep, nullptr, nullptr, 2048, 2048, 512, 512, 0,0,0, 0);
    }

    extract_kernel<<<MTEST, 128>>>();
    mma_gemm<<<dim3(8,16,1),256,GSM>>>(th, tl, pW1h, pW1l, pb1, nullptr,
        nullptr, gh, gl, 512, 512, 1024, 1024, 0,0,0, 1);
    mma_gemm<<<dim3(1,16,1),256,GSM>>>(gh, gl, pW2h, pW2l, pb2, nullptr,
        (float*)d_out, nullptr, nullptr, 1024, 1024, 100, 100, 0,0,0, 0);
}

// round 8
// speedup vs baseline: 1.3489x; 1.1764x over previous
#include <cuda_runtime.h>
#include <cuda_bf16.h>
#include <math.h>
#include <stdint.h>

#define Bc    4
#define Tt    2048
#define TRAIN 1536
#define Dd    512
#define Ll    12
#define FFd   2048
#define BT    (Bc*Tt)
#define NBH   32
#define MTEST 2048

typedef __nv_bfloat16 bf16;

// ---------------- static buffers ----------------
__device__ float g_rep [BT*Dd];
__device__ float g_qkv [BT*3*Dd];
__device__ bf16  g_hh[BT*Dd], g_hl[BT*Dd];
__device__ bf16  g_ah[BT*Dd], g_al[BT*Dd];
__device__ bf16  g_fh[BT*FFd], g_fl[BT*FFd];
__device__ bf16  g_qh[NBH*Tt*64];
__device__ bf16  g_kh[NBH*Tt*64];
__device__ bf16  g_Vh[NBH*Tt*64], g_Vl[NBH*Tt*64];
__device__ bf16  g_th[MTEST*Dd], g_tl[MTEST*Dd];
__device__ bf16  g_gh[MTEST*2*Dd], g_gl[MTEST*2*Dd];
__device__ bf16  g_Wqkvh[Ll*3*Dd*Dd], g_Wqkvl[Ll*3*Dd*Dd];
__device__ bf16  g_Woh[Ll*Dd*Dd],  g_Wol[Ll*Dd*Dd];
__device__ bf16  g_W1h[Ll*FFd*Dd], g_W1l[Ll*FFd*Dd];
__device__ bf16  g_W2h[Ll*Dd*FFd], g_W2l[Ll*Dd*FFd];
__device__ bf16  g_pW1h[2*Dd*Dd],  g_pW1l[2*Dd*Dd];
__device__ bf16  g_pW2h[128*2*Dd], g_pW2l[128*2*Dd];
__device__ float g_cos[Tt*32], g_sin[Tt*32];

// ---------------- helpers ----------------
__device__ __forceinline__ float gelu_f(float x){
    float y = 0.7978845608028654f*(x + 0.044715f*x*x*x);
    float yc = fminf(fmaxf(y, -15.f), 15.f);
    float t = __expf(2.f*yc);
    float th = (t - 1.f)/(t + 1.f);
    return 0.5f*x*(1.f + th);
}
__device__ __forceinline__ void split2(float x, bf16& h, bf16& l){
    h = __float2bfloat16(x);
    l = __float2bfloat16(x - __bfloat162float(h));
}
__device__ __forceinline__ uint32_t smem_u32(const void* p){
    uint32_t a;
    asm("{ .reg .u64 t; cvta.to.shared.u64 t, %1; cvt.u32.u64 %0, t; }" : "=r"(a) : "l"(p));
    return a;
}
__device__ __forceinline__ void cpasync16(uint32_t dst, const void* src){
    asm volatile("cp.async.cg.shared.global [%0], [%1], 16;" :: "r"(dst), "l"(src) : "memory");
}
__device__ __forceinline__ void ldsm4(uint32_t* r, uint32_t a){
    asm volatile("ldmatrix.sync.aligned.m8n8.x4.shared.b16 {%0,%1,%2,%3}, [%4];"
        : "=r"(r[0]),"=r"(r[1]),"=r"(r[2]),"=r"(r[3]) : "r"(a));
}
__device__ __forceinline__ void ldsm4t(uint32_t* r, uint32_t a){
    asm volatile("ldmatrix.sync.aligned.m8n8.x4.trans.shared.b16 {%0,%1,%2,%3}, [%4];"
        : "=r"(r[0]),"=r"(r[1]),"=r"(r[2]),"=r"(r[3]) : "r"(a));
}
__device__ __forceinline__ void mma16816(float* c, const uint32_t* a, const uint32_t* b){
    asm volatile("mma.sync.aligned.m16n8k16.row.col.f32.bf16.bf16.f32 "
        "{%0,%1,%2,%3}, {%4,%5,%6,%7}, {%8,%9}, {%0,%1,%2,%3};"
        : "+f"(c[0]),"+f"(c[1]),"+f"(c[2]),"+f"(c[3])
        : "r"(a[0]),"r"(a[1]),"r"(a[2]),"r"(a[3]), "r"(b[0]),"r"(b[1]));
}
__device__ __forceinline__ uint32_t packbf(float lo, float hi){
    uint32_t r;
    asm("cvt.rn.bf16x2.f32 %0, %1, %2;" : "=r"(r) : "f"(hi), "f"(lo));
    return r;
}

// ================= fused flash attention =================
// Q-tile 128 rows (hi only). Per key-tile stages: Kh, Vh, Vl ([t][dim] layout).
// S = Qh·Kh single-term (absolute score error ~6e-4, safe).
// PV = 3-term split with ldmatrix.trans B fragments.
#define FLDS 72
#define FTILE (64*FLDS*2)
#define FQT   (128*FLDS*2)
#define FSTG  (3*FTILE)
#define FSM   (FQT + 2*FSTG)       // 73728 B

__global__ __launch_bounds__(256, 2) void flash_kernel(){
    extern __shared__ __align__(128) char smem[];
    const uint32_t sb = smem_u32(smem);
    const int tid = threadIdx.x, lane = tid & 31, warp = tid >> 5;
    const int bh = blockIdx.y, b = bh >> 3, h = bh & 7;
    const int t0 = blockIdx.x * 128;
    const int r0 = lane >> 2, cq = lane & 3;
    const int aRow = lane & 15, aCol = (lane >> 4)*8;
    const int bQuad = lane >> 3, bRowQ = lane & 7;
    const int ntOff = bQuad >> 1, colQ = (bQuad & 1)*8;
    // trans-ldsm addressing (PV): tile = lane>>3; rows key (tile&1)*8+bRowQ; dim col (tile>>1)*8
    const int tKey = (bQuad & 1)*8 + bRowQ, tDim = (bQuad >> 1)*8;
    const uint32_t ST0 = sb + FQT;

    {
        #pragma unroll
        for (int i = 0; i < 4; i++){
            int idx = tid + i*256;           // 0..1023 : Q hi 128x64
            int row = idx >> 3, ch = idx & 7;
            cpasync16(sb + (uint32_t)(row*FLDS + ch*8)*2,
                      g_qh + ((size_t)bh*Tt + t0 + row)*64 + ch*8);
        }
        #pragma unroll
        for (int i = 0; i < 6; i++){
            int idx = tid + i*256;           // 0..1535 : Kh,Vh,Vl 64x64 each
            int tile = idx >> 9, rem = idx & 511;
            int row = rem >> 3, ch = rem & 7;
            const bf16* base = (tile == 0) ? g_kh : (tile == 1 ? g_Vh : g_Vl);
            cpasync16(ST0 + tile*FTILE + (uint32_t)(row*FLDS + ch*8)*2,
                      base + ((size_t)bh*Tt + row)*64 + ch*8);
        }
        asm volatile("cp.async.commit_group;" ::: "memory");
    }

    float o[8][4] = {};
    float m0 = -INFINITY, m1 = -INFINITY, l0 = 0.f, l1 = 0.f;
    uint32_t qfh[4][4];

    for (int kt = 0; kt < 24; kt++){
        int s = kt & 1;
        if (kt + 1 < 24){
            int s2 = s ^ 1, s0n = (kt+1)*64;
            uint32_t base = ST0 + s2*FSTG;
            #pragma unroll
            for (int i = 0; i < 6; i++){
                int idx = tid + i*256;
                int tile = idx >> 9, rem = idx & 511;
                int row = rem >> 3, ch = rem & 7;
                const bf16* src = (tile == 0) ? g_kh : (tile == 1 ? g_Vh : g_Vl);
                cpasync16(base + tile*FTILE + (uint32_t)(row*FLDS + ch*8)*2,
                          src + ((size_t)bh*Tt + s0n + row)*64 + ch*8);
            }
            asm volatile("cp.async.commit_group;" ::: "memory");
            asm volatile("cp.async.wait_group 1;" ::: "memory");
        } else {
            asm volatile("cp.async.wait_group 0;" ::: "memory");
        }
        __syncthreads();

        if (kt == 0){
            #pragma unroll
            for (int ks = 0; ks < 4; ks++){
                uint32_t ad = sb + (uint32_t)((warp*16 + aRow)*FLDS + ks*16 + aCol)*2;
                ldsm4(qfh[ks], ad);
            }
        }

        uint32_t KB = ST0 + s*FSTG;
        // ---- S = Qh Kh^T ----
        float acc[8][4] = {};
        #pragma unroll
        for (int ks = 0; ks < 4; ks++){
            #pragma unroll
            for (int g = 0; g < 2; g++){
                uint32_t bfh[4][2];
                #pragma unroll
                for (int p = 0; p < 2; p++){
                    int ntb = g*4 + p*2;
                    uint32_t bd = KB + (uint32_t)(((ntb + ntOff)*8 + bRowQ)*FLDS + ks*16 + colQ)*2;
                    uint32_t r4[4];
                    ldsm4(r4, bd);
                    bfh[p*2][0]=r4[0]; bfh[p*2][1]=r4[1]; bfh[p*2+1][0]=r4[2]; bfh[p*2+1][1]=r4[3];
                }
                #pragma unroll
                for (int j = 0; j < 4; j++) mma16816(acc[g*4+j], qfh[ks], bfh[j]);
            }
        }

        // ---- online softmax ----
        float tm0 = -INFINITY, tm1 = -INFINITY;
        #pragma unroll
        for (int nt = 0; nt < 8; nt++){
            tm0 = fmaxf(tm0, fmaxf(acc[nt][0], acc[nt][1]));
            tm1 = fmaxf(tm1, fmaxf(acc[nt][2], acc[nt][3]));
        }
        tm0 = fmaxf(tm0, __shfl_xor_sync(~0u, tm0, 1));
        tm0 = fmaxf(tm0, __shfl_xor_sync(~0u, tm0, 2));
        tm1 = fmaxf(tm1, __shfl_xor_sync(~0u, tm1, 1));
        tm1 = fmaxf(tm1, __shfl_xor_sync(~0u, tm1, 2));
        float mn0 = fmaxf(m0, tm0), mn1 = fmaxf(m1, tm1);
        float al0 = __expf(m0 - mn0), al1 = __expf(m1 - mn1);
        float ps0 = 0.f, ps1 = 0.f;
        #pragma unroll
        for (int nt = 0; nt < 8; nt++){
            acc[nt][0] = __expf(acc[nt][0] - mn0);
            acc[nt][1] = __expf(acc[nt][1] - mn0);
            acc[nt][2] = __expf(acc[nt][2] - mn1);
            acc[nt][3] = __expf(acc[nt][3] - mn1);
            ps0 += acc[nt][0] + acc[nt][1];
            ps1 += acc[nt][2] + acc[nt][3];
        }
        ps0 += __shfl_xor_sync(~0u, ps0, 1); ps0 += __shfl_xor_sync(~0u, ps0, 2);
        ps1 += __shfl_xor_sync(~0u, ps1, 1); ps1 += __shfl_xor_sync(~0u, ps1, 2);
        l0 = l0*al0 + ps0; l1 = l1*al1 + ps1;
        m0 = mn0; m1 = mn1;
        #pragma unroll
        for (int nt = 0; nt < 8; nt++){
            o[nt][0] *= al0; o[nt][1] *= al0; o[nt][2] *= al1; o[nt][3] *= al1;
        }

        // ---- O += P V (P split 3-term; V [key][dim] via ldmatrix.trans) ----
        uint32_t VB = KB + FTILE;
        #pragma unroll
        for (int kc = 0; kc < 4; kc++){
            uint32_t aph[4], apl[4];
            {
                float e[8] = {acc[2*kc][0], acc[2*kc][1], acc[2*kc][2], acc[2*kc][3],
                              acc[2*kc+1][0], acc[2*kc+1][1], acc[2*kc+1][2], acc[2*kc+1][3]};
                float hi[8], lo[8];
                #pragma unroll
                for (int e2 = 0; e2 < 8; e2++){
                    hi[e2] = __bfloat162float(__float2bfloat16(e[e2]));
                    lo[e2] = e[e2] - hi[e2];
                }
                aph[0] = packbf(hi[0], hi[1]); aph[1] = packbf(hi[2], hi[3]);
                aph[2] = packbf(hi[4], hi[5]); aph[3] = packbf(hi[6], hi[7]);
                apl[0] = packbf(lo[0], lo[1]); apl[1] = packbf(lo[2], lo[3]);
                apl[2] = packbf(lo[4], lo[5]); apl[3] = packbf(lo[6], lo[7]);
            }
            #pragma unroll
            for (int g = 0; g < 2; g++){
                uint32_t bfh[4][2], bfl[4][2];
                #pragma unroll
                for (int p = 0; p < 2; p++){
                    int ntb = g*4 + p*2;      // dim-tile pair base
                    uint32_t bd = VB + (uint32_t)((kc*16 + tKey)*FLDS + ntb*8 + tDim)*2;
                    uint32_t r4[4];
                    ldsm4t(r4, bd);
                    bfh[p*2][0]=r4[0]; bfh[p*2][1]=r4[1]; bfh[p*2+1][0]=r4[2]; bfh[p*2+1][1]=r4[3];
                    ldsm4t(r4, bd + FTILE);
                    bfl[p*2][0]=r4[0]; bfl[p*2][1]=r4[1]; bfl[p*2+1][0]=r4[2]; bfl[p*2+1][1]=r4[3];
                }
                #pragma unroll
                for (int j = 0; j < 4; j++) mma16816(o[g*4+j], aph, bfh[j]);
                #pragma unroll
                for (int j = 0; j < 4; j++) mma16816(o[g*4+j], aph, bfl[j]);
                #pragma unroll
                for (int j = 0; j < 4; j++) mma16816(o[g*4+j], apl, bfh[j]);
            }
        }
        __syncthreads();
    }

    // ---- self-key fixup (fp32 exact; rows t >= TRAIN) ----
    if (t0 >= TRAIN){
        float mm[2] = {m0, m1}, ll[2] = {l0, l1};
        #pragma unroll
        for (int r = 0; r < 2; r++){
            int trow = t0 + warp*16 + r0 + 8*r;
            size_t qb = ((size_t)(b*Tt + trow))*1536 + h*64;
            float part = 0.f;
            #pragma unroll
            for (int d = 0; d < 16; d++)
                part += g_qkv[qb + cq*16 + d] * g_qkv[qb + 512 + cq*16 + d];
            part += __shfl_xor_sync(~0u, part, 1);
            part += __shfl_xor_sync(~0u, part, 2);
            float mn = fmaxf(mm[r], part);
            float al = __expf(mm[r] - mn);
            float p  = __expf(part - mn);
            ll[r] = ll[r]*al + p;
            const float* vs = g_qkv + qb + 1024;
            #pragma unroll
            for (int nt = 0; nt < 8; nt++){
                o[nt][2*r+0] = o[nt][2*r+0]*al + p*vs[nt*8 + 2*cq + 0];
                o[nt][2*r+1] = o[nt][2*r+1]*al + p*vs[nt*8 + 2*cq + 1];
            }
        }
        l0 = ll[0]; l1 = ll[1];
    }

    // ---- normalize + split write ----
    float inv[2] = {1.f/l0, 1.f/l1};
    #pragma unroll
    for (int r = 0; r < 2; r++){
        int trow = t0 + warp*16 + r0 + 8*r;
        size_t ob = ((size_t)(b*Tt + trow))*Dd + h*64;
        #pragma unroll
        for (int nt = 0; nt < 8; nt++){
            #pragma unroll
            for (int j = 0; j < 2; j++){
                float v = o[nt][2*r+j]*inv[r];
                size_t off = ob + nt*8 + 2*cq + j;
                split2(v, g_ah[off], g_al[off]);
            }
        }
    }
}

// ---------------- split-bf16 HMMA GEMM (2-stage, R7 config) ----------------
#define BK 32
#define LDS 40
#define TILE_B (128*LDS*2)
#define STAGE_B (4*TILE_B)
#define GSM (2*STAGE_B)

__global__ __launch_bounds__(256, 2) void mma_gemm(
    const bf16* __restrict__ Ah, const bf16* __restrict__ Al,
    const bf16* __restrict__ Bh, const bf16* __restrict__ Bl,
    const float* __restrict__ bias, const float* __restrict__ res,
    float* C, bf16* Chi, bf16* Clo,
    int K, int ldb, int Nreal, int ldC, size_t sA, size_t sB, size_t sC, int EPI)
{
    extern __shared__ __align__(128) char smem[];
    const uint32_t sb = smem_u32(smem);
    const int tid = threadIdx.x, lane = tid & 31, wid = tid >> 5;
    const int m0 = blockIdx.y*128, n0 = blockIdx.x*128;
    const size_t zb = blockIdx.z;
    const bf16* pAh = Ah + zb*sA + (size_t)m0*K;
    const bf16* pAl = Al + zb*sA + (size_t)m0*K;
    const bf16* pBh = Bh + zb*sB + (size_t)n0*ldb;
    const bf16* pBl = Bl + zb*sB + (size_t)n0*ldb;

    float acc[4][4][4] = {};
    const int nk = K/BK;

    auto issue = [&](int c, int s){
        uint32_t base = sb + s*STAGE_B;
        #pragma unroll
        for (int i = 0; i < 2; i++){
            int seg = tid + i*256;
            int row = seg >> 2, s4 = seg & 3;
            uint32_t doff = (uint32_t)(row*LDS + s4*8)*2;
            const size_t go = (size_t)row*K + c*BK + s4*8;
            const size_t gob = (size_t)row*ldb + c*BK + s4*8;
            cpasync16(base + 0*TILE_B + doff, pAh + go);
            cpasync16(base + 1*TILE_B + doff, pAl + go);
            cpasync16(base + 2*TILE_B + doff, pBh + gob);
            cpasync16(base + 3*TILE_B + doff, pBl + gob);
        }
        asm volatile("cp.async.commit_group;" ::: "memory");
    };

    issue(0, 0);
    const int wm = (wid>>2)*64, wn = (wid&3)*32;
    const int aRow = lane & 15, aCol = (lane >> 4)*8;
    const int bQuad = lane >> 3, bRowQ = lane & 7;
    const int ntOff = bQuad >> 1, colQ = (bQuad & 1)*8;

    for (int c = 0; c < nk; c++){
        int s = c & 1;
        if (c+1 < nk){
            issue(c+1, s^1);
            asm volatile("cp.async.wait_group 1;" ::: "memory");
        } else {
            asm volatile("cp.async.wait_group 0;" ::: "memory");
        }
        __syncthreads();
        uint32_t base = sb + s*STAGE_B;
        #pragma unroll
        for (int ks = 0; ks < 2; ks++){
            uint32_t a_h[4][4], a_l[4][4], b_h[4][2], b_l[4][2];
            #pragma unroll
            for (int mt = 0; mt < 4; mt++){
                uint32_t ad = base + (uint32_t)((wm + mt*16 + aRow)*LDS + ks*16 + aCol)*2;
                ldsm4(a_h[mt], ad);
                ldsm4(a_l[mt], ad + TILE_B);
            }
            #pragma unroll
            for (int p = 0; p < 2; p++){
                uint32_t bd = base + 2*TILE_B + (uint32_t)((wn + (p*2 + ntOff)*8 + bRowQ)*LDS + ks*16 + colQ)*2;
                uint32_t r4[4];
                ldsm4(r4, bd);
                b_h[p*2][0]=r4[0]; b_h[p*2][1]=r4[1]; b_h[p*2+1][0]=r4[2]; b_h[p*2+1][1]=r4[3];
                ldsm4(r4, bd + TILE_B);
                b_l[p*2][0]=r4[0]; b_l[p*2][1]=r4[1]; b_l[p*2+1][0]=r4[2]; b_l[p*2+1][1]=r4[3];
            }
            #pragma unroll
            for (int mt = 0; mt < 4; mt++)
                #pragma unroll
                for (int nt = 0; nt < 4; nt++){
                    mma16816(acc[mt][nt], a_h[mt], b_h[nt]);
                    mma16816(acc[mt][nt], a_h[mt], b_l[nt]);
                    mma16816(acc[mt][nt], a_l[mt], b_h[nt]);
                }
        }
        __syncthreads();
    }

    const int r0 = lane >> 2, cW = (lane & 3)*2;
    #pragma unroll
    for (int mt = 0; mt < 4; mt++)
    #pragma unroll
    for (int hh2 = 0; hh2 < 2; hh2++){
        int gm = m0 + wm + mt*16 + r0 + hh2*8;
        #pragma unroll
        for (int nt = 0; nt < 4; nt++){
            float v0 = acc[mt][nt][hh2*2+0], v1 = acc[mt][nt][hh2*2+1];
            int gn = n0 + wn + nt*8 + cW;
            size_t off = zb*sC + (size_t)gm*ldC + gn;
            if (bias){ v0 += __ldg(bias+gn); v1 += __ldg(bias+gn+1); }
            if (EPI == 1){
                split2(gelu_f(v0), Chi[off],   Clo[off]);
                split2(gelu_f(v1), Chi[off+1], Clo[off+1]);
            } else {
                if (res){ v0 += res[off]; v1 += res[off+1]; }
                if (gn   < Nreal) C[off]   = v0;
                if (gn+1 < Nreal) C[off+1] = v1;
            }
        }
    }
}

// ---------------- weight transpose + split ----------------
__global__ void wsplit_kernel(const float* __restrict__ W, bf16* oh, bf16* ol,
                              int K, int N, int Npad){
    __shared__ float sm[32][33];
    int n0 = blockIdx.x*32, k0 = blockIdx.y*32, z = blockIdx.z;
    const float* Wb = W + (size_t)z*K*N;
    size_t ob = (size_t)z*Npad*K;
    int tx = threadIdx.x, ty = threadIdx.y;
    #pragma unroll
    for (int j = 0; j < 4; j++){
        int n = n0 + tx;
        sm[ty+8*j][tx] = (n < N) ? Wb[(size_t)(k0+ty+8*j)*N + n] : 0.f;
    }
    __syncthreads();
    #pragma unroll
    for (int j = 0; j < 4; j++){
        size_t o = ob + (size_t)(n0+ty+8*j)*K + k0 + tx;
        split2(sm[tx][ty+8*j], oh[o], ol[o]);
    }
}

// ---------------- misc kernels ----------------
__global__ void embed_kernel(const float* __restrict__ R, const int* __restrict__ y,
                             const float* __restrict__ emb){
    int row = blockIdx.x, t = row & (Tt-1), b = row >> 11;
    const float4* Rr = (const float4*)(R + (size_t)row*Dd);
    float4* Or = (float4*)(g_rep + (size_t)row*Dd);
    if (t < TRAIN){
        int yv = y[b*TRAIN + t];
        const float4* E = (const float4*)(emb + (size_t)yv*Dd);
        for (int i = threadIdx.x; i < Dd/4; i += blockDim.x){
            float4 a = Rr[i]; float4 e = E[i];
            a.x += e.x; a.y += e.y; a.z += e.z; a.w += e.w;
            Or[i] = a;
        }
    } else {
        for (int i = threadIdx.x; i < Dd/4; i += blockDim.x) Or[i] = Rr[i];
    }
}

__global__ void ln_kernel(const float* __restrict__ g, const float* __restrict__ be){
    __shared__ float sh[Dd];
    __shared__ float red[4];
    int row = blockIdx.x;
    const float* xr = g_rep + (size_t)row*Dd;
    float s = 0.f;
    for (int i = threadIdx.x; i < Dd; i += 128){ float v = xr[i]; sh[i] = v; s += v; }
    #pragma unroll
    for (int o = 16; o; o >>= 1) s += __shfl_xor_sync(~0u, s, o);
    if ((threadIdx.x & 31) == 0) red[threadIdx.x >> 5] = s;
    __syncthreads();
    float mu = (red[0]+red[1]+red[2]+red[3]) * (1.f/Dd);
    float vs = 0.f;
    for (int i = threadIdx.x; i < Dd; i += 128){ float d = sh[i]-mu; vs += d*d; }
    #pragma unroll
    for (int o = 16; o; o >>= 1) vs += __shfl_xor_sync(~0u, vs, o);
    __syncthreads();
    if ((threadIdx.x & 31) == 0) red[threadIdx.x >> 5] = vs;
    __syncthreads();
    float rs = rsqrtf((red[0]+red[1]+red[2]+red[3])*(1.f/Dd) + 1e-5f);
    for (int i = threadIdx.x; i < Dd; i += 128){
        size_t o = (size_t)row*Dd + i;
        split2((sh[i]-mu)*rs*g[i] + be[i], g_hh[o], g_hl[o]);
    }
}

__global__ void rope_table_kernel(){
    int t = blockIdx.x, i = threadIdx.x;
    float inv = (float)pow(100000.0, -((double)(2*i))/64.0);
    float ang = (float)t * inv;
    g_cos[t*32+i] = cosf(ang);
    g_sin[t*32+i] = sinf(ang);
}

__global__ void rope_scatter_kernel(){
    int row = blockIdx.x, t = row & (Tt-1), b = row >> 11;
    int j = threadIdx.x, h = j >> 5, i = j & 31;
    float c = g_cos[t*32+i], s = g_sin[t*32+i];
    size_t qb = (size_t)row*1536 + h*64 + 2*i;
    float q1 = g_qkv[qb], q2 = g_qkv[qb+1];
    float r1 = (q1*c - q2*s)*0.125f, r2 = (q1*s + q2*c)*0.125f;
    size_t qo = ((size_t)(b*8+h)*Tt + t)*64 + 2*i;
    g_qh[qo]   = __float2bfloat16(r1);
    g_qh[qo+1] = __float2bfloat16(r2);
    float k1 = g_qkv[qb+512], k2 = g_qkv[qb+513];
    float s1 = k1*c - k2*s, s2 = k1*s + k2*c;
    g_kh[qo]   = __float2bfloat16(s1);
    g_kh[qo+1] = __float2bfloat16(s2);
    if (t >= TRAIN){                 // fp32 writeback only for self-key fixup rows
        g_qkv[qb] = r1; g_qkv[qb+1] = r2;
        g_qkv[qb+512] = s1; g_qkv[qb+513] = s2;
    }
    #pragma unroll
    for (int r = 0; r < 2; r++){
        int d = j + 256*r, h2 = d >> 6, dd = d & 63;
        float v = g_qkv[(size_t)row*1536 + 1024 + d];
        size_t vo = ((size_t)(b*8+h2)*Tt + t)*64 + dd;   // [bh][t][dim] — coalesced
        split2(v, g_Vh[vo], g_Vl[vo]);
    }
}

__global__ void extract_kernel(){
    int r = blockIdx.x, b = r >> 9, i = r & 511;
    const float* src = g_rep + (size_t)(b*Tt + TRAIN + i)*Dd;
    for (int j = threadIdx.x; j < Dd; j += 128)
        split2(src[j], g_th[(size_t)r*Dd + j], g_tl[(size_t)r*Dd + j]);
}

// ---------------- launcher ----------------
#define SYM(p, s) cudaGetSymbolAddress((void**)&p, s)

extern "C" void kernel_launch(void* const* d_in, const int* in_sizes, int n_in,
                              void* d_out, int out_size){
    const float* R    = (const float*)d_in[0];
    const int*   y    = (const int*)  d_in[1];
    const float* emb  = (const float*)d_in[2];
    const float* Wqkv = (const float*)d_in[3];
    const float* bqkv = (const float*)d_in[4];
    const float* Wo   = (const float*)d_in[5];
    const float* bo   = (const float*)d_in[6];
    const float* ln1g = (const float*)d_in[7];
    const float* ln1b = (const float*)d_in[8];
    const float* ln2g = (const float*)d_in[9];
    const float* ln2b = (const float*)d_in[10];
    const float* W1   = (const float*)d_in[11];
    const float* b1   = (const float*)d_in[12];
    const float* W2   = (const float*)d_in[13];
    const float* b2   = (const float*)d_in[14];
    const float* pW1  = (const float*)d_in[15];
    const float* pb1  = (const float*)d_in[16];
    const float* pW2  = (const float*)d_in[17];
    const float* pb2  = (const float*)d_in[18];

    cudaFuncSetAttribute(mma_gemm, cudaFuncAttributeMaxDynamicSharedMemorySize, GSM);
    cudaFuncSetAttribute(flash_kernel, cudaFuncAttributeMaxDynamicSharedMemorySize, FSM);

    float *qkv, *rep;
    bf16 *hh,*hl,*ah,*al,*fh,*fl,*th,*tl,*gh,*gl;
    bf16 *Wqkvh,*Wqkvl,*Woh,*Wol,*W1h,*W1l,*W2h,*W2l,*pW1h,*pW1l,*pW2h,*pW2l;
    SYM(qkv,g_qkv); SYM(rep,g_rep);
    SYM(hh,g_hh); SYM(hl,g_hl); SYM(ah,g_ah); SYM(al,g_al);
    SYM(fh,g_fh); SYM(fl,g_fl);
    SYM(th,g_th); SYM(tl,g_tl);
    SYM(gh,g_gh); SYM(gl,g_gl);
    SYM(Wqkvh,g_Wqkvh); SYM(Wqkvl,g_Wqkvl); SYM(Woh,g_Woh); SYM(Wol,g_Wol);
    SYM(W1h,g_W1h); SYM(W1l,g_W1l); SYM(W2h,g_W2h); SYM(W2l,g_W2l);
    SYM(pW1h,g_pW1h); SYM(pW1l,g_pW1l); SYM(pW2h,g_pW2h); SYM(pW2l,g_pW2l);

    dim3 wb(32, 8);
    wsplit_kernel<<<dim3(48,16,12), wb>>>(Wqkv, Wqkvh, Wqkvl, 512, 1536, 1536);
    wsplit_kernel<<<dim3(16,16,12), wb>>>(Wo,   Woh,   Wol,   512, 512,  512);
    wsplit_kernel<<<dim3(64,16,12), wb>>>(W1,   W1h,   W1l,   512, 2048, 2048);
    wsplit_kernel<<<dim3(16,64,12), wb>>>(W2,   W2h,   W2l,   2048,512,  512);
    wsplit_kernel<<<dim3(32,16,1),  wb>>>(pW1,  pW1h,  pW1l,  512, 1024, 1024);
    wsplit_kernel<<<dim3(4, 32,1),  wb>>>(pW2,  pW2h,  pW2l,  1024,100,  128);

    rope_table_kernel<<<Tt, 32>>>();
    embed_kernel<<<BT, 128>>>(R, y, emb);

    for (int l = 0; l < Ll; l++){
        ln_kernel<<<BT, 128>>>(ln1g + l*Dd, ln1b + l*Dd);
        mma_gemm<<<dim3(12,64,1),256,GSM>>>(hh, hl, Wqkvh + (size_t)l*1536*512, Wqkvl + (size_t)l*1536*512,
            bqkv + l*1536, nullptr, qkv, nullptr, nullptr, 512, 512, 1536, 1536, 0,0,0, 0);
        rope_scatter_kernel<<<BT, 256>>>();
        flash_kernel<<<dim3(16, NBH), 256, FSM>>>();
        mma_gemm<<<dim3(4,64,1),256,GSM>>>(ah, al, Woh + (size_t)l*512*512, Wol + (size_t)l*512*512,
            bo + l*512, rep, rep, nullptr, nullptr, 512, 512, 512, 512, 0,0,0, 0);
        ln_kernel<<<BT, 128>>>(ln2g + l*Dd, ln2b + l*Dd);
        mma_gemm<<<dim3(16,64,1),256,GSM>>>(hh, hl, W1h + (size_t)l*2048*512, W1l + (size_t)l*2048*512,
            b1 + l*2048, nullptr, nullptr, fh, fl, 512, 512, 2048, 2048, 0,0,0, 1);
        mma_gemm<<<dim3(4,64,1),256,GSM>>>(fh, fl, W2h + (size_t)l*512*2048, W2l + (size_t)l*512*2048,
            b2 + l*512, rep, rep, nullptr, nullptr, 2048, 2048, 512, 512, 0,0,0, 0);
    }

    extract_kernel<<<MTEST, 128>>>();
    mma_gemm<<<dim3(8,16,1),256,GSM>>>(th, tl, pW1h, pW1l, pb1, nullptr,
        nullptr, gh, gl, 512, 512, 1024, 1024, 0,0,0, 1);
    mma_gemm<<<dim3(1,16,1),256,GSM>>>(gh, gl, pW2h, pW2l, pb2, nullptr,
        (float*)d_out, nullptr, nullptr, 1024, 1024, 100, 100, 0,0,0, 0);
}

// round 9
// speedup vs baseline: 1.4175x; 1.0509x over previous
#include <cuda_runtime.h>
#include <cuda_bf16.h>
#include <math.h>
#include <stdint.h>

#define Bc    4
#define Tt    2048
#define TRAIN 1536
#define Dd    512
#define Ll    12
#define FFd   2048
#define BT    (Bc*Tt)
#define NBH   32
#define MTEST 2048

typedef __nv_bfloat16 bf16;

// ---------------- static buffers ----------------
__device__ float g_rep [BT*Dd];
__device__ float g_qkv [BT*3*Dd];          // fp32 qkv, written only for t>=TRAIN (fixup)
__device__ bf16  g_hh[BT*Dd], g_hl[BT*Dd];
__device__ bf16  g_ah[BT*Dd], g_al[BT*Dd];
__device__ bf16  g_fh[BT*FFd], g_fl[BT*FFd];
__device__ bf16  g_qh[NBH*Tt*64];
__device__ bf16  g_kh[NBH*Tt*64];
__device__ bf16  g_Vh[NBH*Tt*64], g_Vl[NBH*Tt*64];
__device__ bf16  g_th[MTEST*Dd], g_tl[MTEST*Dd];
__device__ bf16  g_gh[MTEST*2*Dd], g_gl[MTEST*2*Dd];
__device__ bf16  g_Wqkvh[Ll*3*Dd*Dd], g_Wqkvl[Ll*3*Dd*Dd];
__device__ bf16  g_Woh[Ll*Dd*Dd],  g_Wol[Ll*Dd*Dd];
__device__ bf16  g_W1h[Ll*FFd*Dd], g_W1l[Ll*FFd*Dd];
__device__ bf16  g_W2h[Ll*Dd*FFd], g_W2l[Ll*Dd*FFd];
__device__ bf16  g_pW1h[2*Dd*Dd],  g_pW1l[2*Dd*Dd];
__device__ bf16  g_pW2h[128*2*Dd], g_pW2l[128*2*Dd];
__device__ float g_cos[Tt*32], g_sin[Tt*32];

// ---------------- helpers ----------------
__device__ __forceinline__ float gelu_f(float x){
    float y = 0.7978845608028654f*(x + 0.044715f*x*x*x);
    float yc = fminf(fmaxf(y, -15.f), 15.f);
    float t = __expf(2.f*yc);
    float th = (t - 1.f)/(t + 1.f);
    return 0.5f*x*(1.f + th);
}
__device__ __forceinline__ void split2(float x, bf16& h, bf16& l){
    h = __float2bfloat16(x);
    l = __float2bfloat16(x - __bfloat162float(h));
}
__device__ __forceinline__ uint32_t smem_u32(const void* p){
    uint32_t a;
    asm("{ .reg .u64 t; cvta.to.shared.u64 t, %1; cvt.u32.u64 %0, t; }" : "=r"(a) : "l"(p));
    return a;
}
__device__ __forceinline__ void cpasync16(uint32_t dst, const void* src){
    asm volatile("cp.async.cg.shared.global [%0], [%1], 16;" :: "r"(dst), "l"(src) : "memory");
}
__device__ __forceinline__ void ldsm4(uint32_t* r, uint32_t a){
    asm volatile("ldmatrix.sync.aligned.m8n8.x4.shared.b16 {%0,%1,%2,%3}, [%4];"
        : "=r"(r[0]),"=r"(r[1]),"=r"(r[2]),"=r"(r[3]) : "r"(a));
}
__device__ __forceinline__ void ldsm4t(uint32_t* r, uint32_t a){
    asm volatile("ldmatrix.sync.aligned.m8n8.x4.trans.shared.b16 {%0,%1,%2,%3}, [%4];"
        : "=r"(r[0]),"=r"(r[1]),"=r"(r[2]),"=r"(r[3]) : "r"(a));
}
__device__ __forceinline__ void mma16816(float* c, const uint32_t* a, const uint32_t* b){
    asm volatile("mma.sync.aligned.m16n8k16.row.col.f32.bf16.bf16.f32 "
        "{%0,%1,%2,%3}, {%4,%5,%6,%7}, {%8,%9}, {%0,%1,%2,%3};"
        : "+f"(c[0]),"+f"(c[1]),"+f"(c[2]),"+f"(c[3])
        : "r"(a[0]),"r"(a[1]),"r"(a[2]),"r"(a[3]), "r"(b[0]),"r"(b[1]));
}
__device__ __forceinline__ uint32_t packbf(float lo, float hi){
    uint32_t r;
    asm("cvt.rn.bf16x2.f32 %0, %1, %2;" : "=r"(r) : "f"(hi), "f"(lo));
    return r;
}
// packed split: write hi-pair and lo-pair as single u32 stores
__device__ __forceinline__ void split_store2(float v0, float v1, bf16* ph, bf16* pl){
    float h0 = __bfloat162float(__float2bfloat16(v0));
    float h1 = __bfloat162float(__float2bfloat16(v1));
    *(uint32_t*)ph = packbf(v0, v1);
    *(uint32_t*)pl = packbf(v0 - h0, v1 - h1);
}

// ================= fused flash attention =================
#define FLDS 72
#define FTILE (64*FLDS*2)
#define FQT   (128*FLDS*2)
#define FSTG  (3*FTILE)
#define FSM   (FQT + 2*FSTG)       // 73728 B

__global__ __launch_bounds__(256, 2) void flash_kernel(){
    extern __shared__ __align__(128) char smem[];
    const uint32_t sb = smem_u32(smem);
    const int tid = threadIdx.x, lane = tid & 31, warp = tid >> 5;
    const int bh = blockIdx.y, b = bh >> 3, h = bh & 7;
    const int t0 = blockIdx.x * 128;
    const int r0 = lane >> 2, cq = lane & 3;
    const int aRow = lane & 15, aCol = (lane >> 4)*8;
    const int bQuad = lane >> 3, bRowQ = lane & 7;
    const int ntOff = bQuad >> 1, colQ = (bQuad & 1)*8;
    const int tKey = (bQuad & 1)*8 + bRowQ, tDim = (bQuad >> 1)*8;
    const uint32_t ST0 = sb + FQT;

    {
        #pragma unroll
        for (int i = 0; i < 4; i++){
            int idx = tid + i*256;
            int row = idx >> 3, ch = idx & 7;
            cpasync16(sb + (uint32_t)(row*FLDS + ch*8)*2,
                      g_qh + ((size_t)bh*Tt + t0 + row)*64 + ch*8);
        }
        #pragma unroll
        for (int i = 0; i < 6; i++){
            int idx = tid + i*256;
            int tile = idx >> 9, rem = idx & 511;
            int row = rem >> 3, ch = rem & 7;
            const bf16* base = (tile == 0) ? g_kh : (tile == 1 ? g_Vh : g_Vl);
            cpasync16(ST0 + tile*FTILE + (uint32_t)(row*FLDS + ch*8)*2,
                      base + ((size_t)bh*Tt + row)*64 + ch*8);
        }
        asm volatile("cp.async.commit_group;" ::: "memory");
    }

    float o[8][4] = {};
    float m0 = -INFINITY, m1 = -INFINITY, l0 = 0.f, l1 = 0.f;
    uint32_t qfh[4][4];

    for (int kt = 0; kt < 24; kt++){
        int s = kt & 1;
        if (kt + 1 < 24){
            int s2 = s ^ 1, s0n = (kt+1)*64;
            uint32_t base = ST0 + s2*FSTG;
            #pragma unroll
            for (int i = 0; i < 6; i++){
                int idx = tid + i*256;
                int tile = idx >> 9, rem = idx & 511;
                int row = rem >> 3, ch = rem & 7;
                const bf16* src = (tile == 0) ? g_kh : (tile == 1 ? g_Vh : g_Vl);
                cpasync16(base + tile*FTILE + (uint32_t)(row*FLDS + ch*8)*2,
                          src + ((size_t)bh*Tt + s0n + row)*64 + ch*8);
            }
            asm volatile("cp.async.commit_group;" ::: "memory");
            asm volatile("cp.async.wait_group 1;" ::: "memory");
        } else {
            asm volatile("cp.async.wait_group 0;" ::: "memory");
        }
        __syncthreads();

        if (kt == 0){
            #pragma unroll
            for (int ks = 0; ks < 4; ks++){
                uint32_t ad = sb + (uint32_t)((warp*16 + aRow)*FLDS + ks*16 + aCol)*2;
                ldsm4(qfh[ks], ad);
            }
        }

        uint32_t KB = ST0 + s*FSTG;
        float acc[8][4] = {};
        #pragma unroll
        for (int ks = 0; ks < 4; ks++){
            #pragma unroll
            for (int g = 0; g < 2; g++){
                uint32_t bfh[4][2];
                #pragma unroll
                for (int p = 0; p < 2; p++){
                    int ntb = g*4 + p*2;
                    uint32_t bd = KB + (uint32_t)(((ntb + ntOff)*8 + bRowQ)*FLDS + ks*16 + colQ)*2;
                    uint32_t r4[4];
                    ldsm4(r4, bd);
                    bfh[p*2][0]=r4[0]; bfh[p*2][1]=r4[1]; bfh[p*2+1][0]=r4[2]; bfh[p*2+1][1]=r4[3];
                }
                #pragma unroll
                for (int j = 0; j < 4; j++) mma16816(acc[g*4+j], qfh[ks], bfh[j]);
            }
        }

        float tm0 = -INFINITY, tm1 = -INFINITY;
        #pragma unroll
        for (int nt = 0; nt < 8; nt++){
            tm0 = fmaxf(tm0, fmaxf(acc[nt][0], acc[nt][1]));
            tm1 = fmaxf(tm1, fmaxf(acc[nt][2], acc[nt][3]));
        }
        tm0 = fmaxf(tm0, __shfl_xor_sync(~0u, tm0, 1));
        tm0 = fmaxf(tm0, __shfl_xor_sync(~0u, tm0, 2));
        tm1 = fmaxf(tm1, __shfl_xor_sync(~0u, tm1, 1));
        tm1 = fmaxf(tm1, __shfl_xor_sync(~0u, tm1, 2));
        float mn0 = fmaxf(m0, tm0), mn1 = fmaxf(m1, tm1);
        float al0 = __expf(m0 - mn0), al1 = __expf(m1 - mn1);
        float ps0 = 0.f, ps1 = 0.f;
        #pragma unroll
        for (int nt = 0; nt < 8; nt++){
            acc[nt][0] = __expf(acc[nt][0] - mn0);
            acc[nt][1] = __expf(acc[nt][1] - mn0);
            acc[nt][2] = __expf(acc[nt][2] - mn1);
            acc[nt][3] = __expf(acc[nt][3] - mn1);
            ps0 += acc[nt][0] + acc[nt][1];
            ps1 += acc[nt][2] + acc[nt][3];
        }
        ps0 += __shfl_xor_sync(~0u, ps0, 1); ps0 += __shfl_xor_sync(~0u, ps0, 2);
        ps1 += __shfl_xor_sync(~0u, ps1, 1); ps1 += __shfl_xor_sync(~0u, ps1, 2);
        l0 = l0*al0 + ps0; l1 = l1*al1 + ps1;
        m0 = mn0; m1 = mn1;
        #pragma unroll
        for (int nt = 0; nt < 8; nt++){
            o[nt][0] *= al0; o[nt][1] *= al0; o[nt][2] *= al1; o[nt][3] *= al1;
        }

        uint32_t VB = KB + FTILE;
        #pragma unroll
        for (int kc = 0; kc < 4; kc++){
            uint32_t aph[4], apl[4];
            {
                float e[8] = {acc[2*kc][0], acc[2*kc][1], acc[2*kc][2], acc[2*kc][3],
                              acc[2*kc+1][0], acc[2*kc+1][1], acc[2*kc+1][2], acc[2*kc+1][3]};
                float hi[8], lo[8];
                #pragma unroll
                for (int e2 = 0; e2 < 8; e2++){
                    hi[e2] = __bfloat162float(__float2bfloat16(e[e2]));
                    lo[e2] = e[e2] - hi[e2];
                }
                aph[0] = packbf(hi[0], hi[1]); aph[1] = packbf(hi[2], hi[3]);
                aph[2] = packbf(hi[4], hi[5]); aph[3] = packbf(hi[6], hi[7]);
                apl[0] = packbf(lo[0], lo[1]); apl[1] = packbf(lo[2], lo[3]);
                apl[2] = packbf(lo[4], lo[5]); apl[3] = packbf(lo[6], lo[7]);
            }
            #pragma unroll
            for (int g = 0; g < 2; g++){
                uint32_t bfh[4][2], bfl[4][2];
                #pragma unroll
                for (int p = 0; p < 2; p++){
                    int ntb = g*4 + p*2;
                    uint32_t bd = VB + (uint32_t)((kc*16 + tKey)*FLDS + ntb*8 + tDim)*2;
                    uint32_t r4[4];
                    ldsm4t(r4, bd);
                    bfh[p*2][0]=r4[0]; bfh[p*2][1]=r4[1]; bfh[p*2+1][0]=r4[2]; bfh[p*2+1][1]=r4[3];
                    ldsm4t(r4, bd + FTILE);
                    bfl[p*2][0]=r4[0]; bfl[p*2][1]=r4[1]; bfl[p*2+1][0]=r4[2]; bfl[p*2+1][1]=r4[3];
                }
                #pragma unroll
                for (int j = 0; j < 4; j++) mma16816(o[g*4+j], aph, bfh[j]);
                #pragma unroll
                for (int j = 0; j < 4; j++) mma16816(o[g*4+j], aph, bfl[j]);
                #pragma unroll
                for (int j = 0; j < 4; j++) mma16816(o[g*4+j], apl, bfh[j]);
            }
        }
        __syncthreads();
    }

    // ---- self-key fixup (fp32 exact; rows t >= TRAIN) ----
    if (t0 >= TRAIN){
        float mm[2] = {m0, m1}, ll[2] = {l0, l1};
        #pragma unroll
        for (int r = 0; r < 2; r++){
            int trow = t0 + warp*16 + r0 + 8*r;
            size_t qb = ((size_t)(b*Tt + trow))*1536 + h*64;
            float part = 0.f;
            #pragma unroll
            for (int d = 0; d < 16; d++)
                part += g_qkv[qb + cq*16 + d] * g_qkv[qb + 512 + cq*16 + d];
            part += __shfl_xor_sync(~0u, part, 1);
            part += __shfl_xor_sync(~0u, part, 2);
            float mn = fmaxf(mm[r], part);
            float al = __expf(mm[r] - mn);
            float p  = __expf(part - mn);
            ll[r] = ll[r]*al + p;
            const float* vs = g_qkv + qb + 1024;
            #pragma unroll
            for (int nt = 0; nt < 8; nt++){
                o[nt][2*r+0] = o[nt][2*r+0]*al + p*vs[nt*8 + 2*cq + 0];
                o[nt][2*r+1] = o[nt][2*r+1]*al + p*vs[nt*8 + 2*cq + 1];
            }
        }
        l0 = ll[0]; l1 = ll[1];
    }

    // ---- normalize + packed split write ----
    float inv[2] = {1.f/l0, 1.f/l1};
    #pragma unroll
    for (int r = 0; r < 2; r++){
        int trow = t0 + warp*16 + r0 + 8*r;
        size_t ob = ((size_t)(b*Tt + trow))*Dd + h*64;
        #pragma unroll
        for (int nt = 0; nt < 8; nt++){
            size_t off = ob + nt*8 + 2*cq;
            split_store2(o[nt][2*r]*inv[r], o[nt][2*r+1]*inv[r], g_ah + off, g_al + off);
        }
    }
}

// ---------------- split-bf16 HMMA GEMM ----------------
// EPI: 0 = fp32 C (+bias,+res), 1 = gelu -> split bf16, 2 = QKV rope scatter
#define BK 32
#define LDS 40
#define TILE_B (128*LDS*2)
#define STAGE_B (4*TILE_B)
#define GSM (2*STAGE_B)

__global__ __launch_bounds__(256, 2) void mma_gemm(
    const bf16* __restrict__ Ah, const bf16* __restrict__ Al,
    const bf16* __restrict__ Bh, const bf16* __restrict__ Bl,
    const float* __restrict__ bias, const float* __restrict__ res,
    float* C, bf16* Chi, bf16* Clo,
    int K, int ldb, int Nreal, int ldC, size_t sA, size_t sB, size_t sC, int EPI)
{
    extern __shared__ __align__(128) char smem[];
    const uint32_t sb = smem_u32(smem);
    const int tid = threadIdx.x, lane = tid & 31, wid = tid >> 5;
    const int m0 = blockIdx.y*128, n0 = blockIdx.x*128;
    const size_t zb = blockIdx.z;
    const bf16* pAh = Ah + zb*sA + (size_t)m0*K;
    const bf16* pAl = Al + zb*sA + (size_t)m0*K;
    const bf16* pBh = Bh + zb*sB + (size_t)n0*ldb;
    const bf16* pBl = Bl + zb*sB + (size_t)n0*ldb;

    float acc[4][4][4] = {};
    const int nk = K/BK;

    auto issue = [&](int c, int s){
        uint32_t base = sb + s*STAGE_B;
        #pragma unroll
        for (int i = 0; i < 2; i++){
            int seg = tid + i*256;
            int row = seg >> 2, s4 = seg & 3;
            uint32_t doff = (uint32_t)(row*LDS + s4*8)*2;
            const size_t go = (size_t)row*K + c*BK + s4*8;
            const size_t gob = (size_t)row*ldb + c*BK + s4*8;
            cpasync16(base + 0*TILE_B + doff, pAh + go);
            cpasync16(base + 1*TILE_B + doff, pAl + go);
            cpasync16(base + 2*TILE_B + doff, pBh + gob);
            cpasync16(base + 3*TILE_B + doff, pBl + gob);
        }
        asm volatile("cp.async.commit_group;" ::: "memory");
    };

    issue(0, 0);
    const int wm = (wid>>2)*64, wn = (wid&3)*32;
    const int aRow = lane & 15, aCol = (lane >> 4)*8;
    const int bQuad = lane >> 3, bRowQ = lane & 7;
    const int ntOff = bQuad >> 1, colQ = (bQuad & 1)*8;

    for (int c = 0; c < nk; c++){
        int s = c & 1;
        if (c+1 < nk){
            issue(c+1, s^1);
            asm volatile("cp.async.wait_group 1;" ::: "memory");
        } else {
            asm volatile("cp.async.wait_group 0;" ::: "memory");
        }
        __syncthreads();
        uint32_t base = sb + s*STAGE_B;
        #pragma unroll
        for (int ks = 0; ks < 2; ks++){
            uint32_t a_h[4][4], a_l[4][4], b_h[4][2], b_l[4][2];
            #pragma unroll
            for (int mt = 0; mt < 4; mt++){
                uint32_t ad = base + (uint32_t)((wm + mt*16 + aRow)*LDS + ks*16 + aCol)*2;
                ldsm4(a_h[mt], ad);
                ldsm4(a_l[mt], ad + TILE_B);
            }
            #pragma unroll
            for (int p = 0; p < 2; p++){
                uint32_t bd = base + 2*TILE_B + (uint32_t)((wn + (p*2 + ntOff)*8 + bRowQ)*LDS + ks*16 + colQ)*2;
                uint32_t r4[4];
                ldsm4(r4, bd);
                b_h[p*2][0]=r4[0]; b_h[p*2][1]=r4[1]; b_h[p*2+1][0]=r4[2]; b_h[p*2+1][1]=r4[3];
                ldsm4(r4, bd + TILE_B);
                b_l[p*2][0]=r4[0]; b_l[p*2][1]=r4[1]; b_l[p*2+1][0]=r4[2]; b_l[p*2+1][1]=r4[3];
            }
            #pragma unroll
            for (int mt = 0; mt < 4; mt++)
                #pragma unroll
                for (int nt = 0; nt < 4; nt++){
                    mma16816(acc[mt][nt], a_h[mt], b_h[nt]);
                    mma16816(acc[mt][nt], a_h[mt], b_l[nt]);
                    mma16816(acc[mt][nt], a_l[mt], b_h[nt]);
                }
        }
        __syncthreads();
    }

    const int r0 = lane >> 2, cW = (lane & 3)*2;
    #pragma unroll
    for (int mt = 0; mt < 4; mt++)
    #pragma unroll
    for (int hh2 = 0; hh2 < 2; hh2++){
        int gm = m0 + wm + mt*16 + r0 + hh2*8;
        #pragma unroll
        for (int nt = 0; nt < 4; nt++){
            float v0 = acc[mt][nt][hh2*2+0], v1 = acc[mt][nt][hh2*2+1];
            int gn = n0 + wn + nt*8 + cW;
            if (bias){ v0 += __ldg(bias+gn); v1 += __ldg(bias+gn+1); }
            if (EPI == 2){
                // fused RoPE + scatter for QKV (N=1536)
                int b = gm >> 11, t = gm & (Tt-1);
                if (gn < 1024){
                    int hq = (gn & 511) >> 6;
                    int i = (gn & 63) >> 1;
                    float cc = g_cos[t*32+i], ss = g_sin[t*32+i];
                    float r1 = v0*cc - v1*ss, r2 = v0*ss + v1*cc;
                    if (gn < 512){ r1 *= 0.125f; r2 *= 0.125f; }
                    size_t qo = ((size_t)(b*8+hq)*Tt + t)*64 + (gn & 63);
                    if (gn < 512) *(uint32_t*)(g_qh + qo) = packbf(r1, r2);
                    else          *(uint32_t*)(g_kh + qo) = packbf(r1, r2);
                    if (t >= TRAIN){
                        size_t fo = (size_t)gm*1536 + gn;
                        g_qkv[fo] = r1; g_qkv[fo+1] = r2;
                    }
                } else {
                    int h2 = (gn - 1024) >> 6, dd = (gn - 1024) & 63;
                    size_t vo = ((size_t)(b*8+h2)*Tt + t)*64 + dd;
                    split_store2(v0, v1, g_Vh + vo, g_Vl + vo);
                    if (t >= TRAIN){
                        size_t fo = (size_t)gm*1536 + gn;
                        g_qkv[fo] = v0; g_qkv[fo+1] = v1;
                    }
                }
            } else if (EPI == 1){
                size_t off = zb*sC + (size_t)gm*ldC + gn;
                split_store2(gelu_f(v0), gelu_f(v1), Chi + off, Clo + off);
            } else {
                size_t off = zb*sC + (size_t)gm*ldC + gn;
                if (res){ v0 += res[off]; v1 += res[off+1]; }
                if (gn   < Nreal) C[off]   = v0;
                if (gn+1 < Nreal) C[off+1] = v1;
            }
        }
    }
}

// ---------------- weight transpose + split ----------------
__global__ void wsplit_kernel(const float* __restrict__ W, bf16* oh, bf16* ol,
                              int K, int N, int Npad){
    __shared__ float sm[32][33];
    int n0 = blockIdx.x*32, k0 = blockIdx.y*32, z = blockIdx.z;
    const float* Wb = W + (size_t)z*K*N;
    size_t ob = (size_t)z*Npad*K;
    int tx = threadIdx.x, ty = threadIdx.y;
    #pragma unroll
    for (int j = 0; j < 4; j++){
        int n = n0 + tx;
        sm[ty+8*j][tx] = (n < N) ? Wb[(size_t)(k0+ty+8*j)*N + n] : 0.f;
    }
    __syncthreads();
    #pragma unroll
    for (int j = 0; j < 4; j++){
        size_t o = ob + (size_t)(n0+ty+8*j)*K + k0 + tx;
        split2(sm[tx][ty+8*j], oh[o], ol[o]);
    }
}

// ---------------- misc kernels ----------------
__global__ void embed_kernel(const float* __restrict__ R, const int* __restrict__ y,
                             const float* __restrict__ emb){
    int row = blockIdx.x, t = row & (Tt-1), b = row >> 11;
    const float4* Rr = (const float4*)(R + (size_t)row*Dd);
    float4* Or = (float4*)(g_rep + (size_t)row*Dd);
    if (t < TRAIN){
        int yv = y[b*TRAIN + t];
        const float4* E = (const float4*)(emb + (size_t)yv*Dd);
        for (int i = threadIdx.x; i < Dd/4; i += blockDim.x){
            float4 a = Rr[i]; float4 e = E[i];
            a.x += e.x; a.y += e.y; a.z += e.z; a.w += e.w;
            Or[i] = a;
        }
    } else {
        for (int i = threadIdx.x; i < Dd/4; i += blockDim.x) Or[i] = Rr[i];
    }
}

__global__ void ln_kernel(const float* __restrict__ g, const float* __restrict__ be){
    __shared__ float sh[Dd];
    __shared__ float red[4];
    int row = blockIdx.x;
    const float* xr = g_rep + (size_t)row*Dd;
    float s = 0.f;
    for (int i = threadIdx.x; i < Dd; i += 128){ float v = xr[i]; sh[i] = v; s += v; }
    #pragma unroll
    for (int o = 16; o; o >>= 1) s += __shfl_xor_sync(~0u, s, o);
    if ((threadIdx.x & 31) == 0) red[threadIdx.x >> 5] = s;
    __syncthreads();
    float mu = (red[0]+red[1]+red[2]+red[3]) * (1.f/Dd);
    float vs = 0.f;
    for (int i = threadIdx.x; i < Dd; i += 128){ float d = sh[i]-mu; vs += d*d; }
    #pragma unroll
    for (int o = 16; o; o >>= 1) vs += __shfl_xor_sync(~0u, vs, o);
    __syncthreads();
    if ((threadIdx.x & 31) == 0) red[threadIdx.x >> 5] = vs;
    __syncthreads();
    float rs = rsqrtf((red[0]+red[1]+red[2]+red[3])*(1.f/Dd) + 1e-5f);
    for (int i = threadIdx.x; i < Dd; i += 128){
        size_t o = (size_t)row*Dd + i;
        split2((sh[i]-mu)*rs*g[i] + be[i], g_hh[o], g_hl[o]);
    }
}

__global__ void rope_table_kernel(){
    int t = blockIdx.x, i = threadIdx.x;
    float inv = (float)pow(100000.0, -((double)(2*i))/64.0);
    float ang = (float)t * inv;
    g_cos[t*32+i] = cosf(ang);
    g_sin[t*32+i] = sinf(ang);
}

__global__ void extract_kernel(){
    int r = blockIdx.x, b = r >> 9, i = r & 511;
    const float* src = g_rep + (size_t)(b*Tt + TRAIN + i)*Dd;
    for (int j = threadIdx.x; j < Dd; j += 128)
        split2(src[j], g_th[(size_t)r*Dd + j], g_tl[(size_t)r*Dd + j]);
}

// ---------------- launcher ----------------
#define SYM(p, s) cudaGetSymbolAddress((void**)&p, s)

extern "C" void kernel_launch(void* const* d_in, const int* in_sizes, int n_in,
                              void* d_out, int out_size){
    const float* R    = (const float*)d_in[0];
    const int*   y    = (const int*)  d_in[1];
    const float* emb  = (const float*)d_in[2];
    const float* Wqkv = (const float*)d_in[3];
    const float* bqkv = (const float*)d_in[4];
    const float* Wo   = (const float*)d_in[5];
    const float* bo   = (const float*)d_in[6];
    const float* ln1g = (const float*)d_in[7];
    const float* ln1b = (const float*)d_in[8];
    const float* ln2g = (const float*)d_in[9];
    const float* ln2b = (const float*)d_in[10];
    const float* W1   = (const float*)d_in[11];
    const float* b1   = (const float*)d_in[12];
    const float* W2   = (const float*)d_in[13];
    const float* b2   = (const float*)d_in[14];
    const float* pW1  = (const float*)d_in[15];
    const float* pb1  = (const float*)d_in[16];
    const float* pW2  = (const float*)d_in[17];
    const float* pb2  = (const float*)d_in[18];

    cudaFuncSetAttribute(mma_gemm, cudaFuncAttributeMaxDynamicSharedMemorySize, GSM);
    cudaFuncSetAttribute(flash_kernel, cudaFuncAttributeMaxDynamicSharedMemorySize, FSM);

    float *qkv, *rep;
    bf16 *hh,*hl,*ah,*al,*fh,*fl,*th,*tl,*gh,*gl;
    bf16 *Wqkvh,*Wqkvl,*Woh,*Wol,*W1h,*W1l,*W2h,*W2l,*pW1h,*pW1l,*pW2h,*pW2l;
    SYM(qkv,g_qkv); SYM(rep,g_rep);
    SYM(hh,g_hh); SYM(hl,g_hl); SYM(ah,g_ah); SYM(al,g_al);
    SYM(fh,g_fh); SYM(fl,g_fl);
    SYM(th,g_th); SYM(tl,g_tl);
    SYM(gh,g_gh); SYM(gl,g_gl);
    SYM(Wqkvh,g_Wqkvh); SYM(Wqkvl,g_Wqkvl); SYM(Woh,g_Woh); SYM(Wol,g_Wol);
    SYM(W1h,g_W1h); SYM(W1l,g_W1l); SYM(W2h,g_W2h); SYM(W2l,g_W2l);
    SYM(pW1h,g_pW1h); SYM(pW1l,g_pW1l); SYM(pW2h,g_pW2h); SYM(pW2l,g_pW2l);

    dim3 wb(32, 8);
    // launch order arranged so ncu (-s 5 -c 1) profiles the first QKV mma_gemm
    wsplit_kernel<<<dim3(48,16,12), wb>>>(Wqkv, Wqkvh, Wqkvl, 512, 1536, 1536);   // 0
    rope_table_kernel<<<Tt, 32>>>();                                               // 1
    embed_kernel<<<BT, 128>>>(R, y, emb);                                          // 2
    wsplit_kernel<<<dim3(16,16,12), wb>>>(Wo, Woh, Wol, 512, 512, 512);            // 3

    for (int l = 0; l < Ll; l++){
        ln_kernel<<<BT, 128>>>(ln1g + l*Dd, ln1b + l*Dd);                          // 4
        mma_gemm<<<dim3(12,64,1),256,GSM>>>(hh, hl, Wqkvh + (size_t)l*1536*512, Wqkvl + (size_t)l*1536*512,
            bqkv + l*1536, nullptr, nullptr, nullptr, nullptr, 512, 512, 1536, 1536, 0,0,0, 2);  // 5 (profiled)
        if (l == 0){
            wsplit_kernel<<<dim3(64,16,12), wb>>>(W1, W1h, W1l, 512, 2048, 2048);
            wsplit_kernel<<<dim3(16,64,12), wb>>>(W2, W2h, W2l, 2048, 512, 512);
            wsplit_kernel<<<dim3(32,16,1),  wb>>>(pW1, pW1h, pW1l, 512, 1024, 1024);
            wsplit_kernel<<<dim3(4, 32,1),  wb>>>(pW2, pW2h, pW2l, 1024, 100, 128);
        }
        flash_kernel<<<dim3(16, NBH), 256, FSM>>>();
        mma_gemm<<<dim3(4,64,1),256,GSM>>>(ah, al, Woh + (size_t)l*512*512, Wol + (size_t)l*512*512,
            bo + l*512, rep, rep, nullptr, nullptr, 512, 512, 512, 512, 0,0,0, 0);
        ln_kernel<<<BT, 128>>>(ln2g + l*Dd, ln2b + l*Dd);
        mma_gemm<<<dim3(16,64,1),256,GSM>>>(hh, hl, W1h + (size_t)l*2048*512, W1l + (size_t)l*2048*512,
            b1 + l*2048, nullptr, nullptr, fh, fl, 512, 512, 2048, 2048, 0,0,0, 1);
        mma_gemm<<<dim3(4,64,1),256,GSM>>>(fh, fl, W2h + (size_t)l*512*2048, W2l + (size_t)l*512*2048,
            b2 + l*512, rep, rep, nullptr, nullptr, 2048, 2048, 512, 512, 0,0,0, 0);
    }

    extract_kernel<<<MTEST, 128>>>();
    mma_gemm<<<dim3(8,16,1),256,GSM>>>(th, tl, pW1h, pW1l, pb1, nullptr,
        nullptr, gh, gl, 512, 512, 1024, 1024, 0,0,0, 1);
    mma_gemm<<<dim3(1,16,1),256,GSM>>>(gh, gl, pW2h, pW2l, pb2, nullptr,
        (float*)d_out, nullptr, nullptr, 1024, 1024, 100, 100, 0,0,0, 0);
}

// round 11
// speedup vs baseline: 1.5778x; 1.1131x over previous
#include <cuda_runtime.h>
#include <cuda_bf16.h>
#include <math.h>
#include <stdint.h>

#define Bc    4
#define Tt    2048
#define TRAIN 1536
#define Dd    512
#define Ll    12
#define FFd   2048
#define BT    (Bc*Tt)
#define NBH   32
#define MTEST 2048

typedef __nv_bfloat16 bf16;

// ---------------- static buffers ----------------
__device__ float g_rep [BT*Dd];
__device__ float g_qkv [BT*3*Dd];          // fp32 qkv, written only for t>=TRAIN (fixup)
__device__ bf16  g_hh[BT*Dd], g_hl[BT*Dd];
__device__ bf16  g_ah[BT*Dd], g_al[BT*Dd];
__device__ bf16  g_fh[BT*FFd], g_fl[BT*FFd];
__device__ bf16  g_qh[NBH*Tt*64];
__device__ bf16  g_kh[NBH*Tt*64];
__device__ bf16  g_Vh[NBH*Tt*64], g_Vl[NBH*Tt*64];
__device__ bf16  g_th[MTEST*Dd], g_tl[MTEST*Dd];
__device__ bf16  g_gh[MTEST*2*Dd], g_gl[MTEST*2*Dd];
__device__ bf16  g_Wqkvh[Ll*3*Dd*Dd], g_Wqkvl[Ll*3*Dd*Dd];
__device__ bf16  g_Woh[Ll*Dd*Dd],  g_Wol[Ll*Dd*Dd];
__device__ bf16  g_W1h[Ll*FFd*Dd], g_W1l[Ll*FFd*Dd];
__device__ bf16  g_W2h[Ll*Dd*FFd], g_W2l[Ll*Dd*FFd];
__device__ bf16  g_pW1h[2*Dd*Dd],  g_pW1l[2*Dd*Dd];
__device__ bf16  g_pW2h[128*2*Dd], g_pW2l[128*2*Dd];
__device__ float g_cos[Tt*32], g_sin[Tt*32];

// ---------------- helpers ----------------
__device__ __forceinline__ float gelu_f(float x){
    float y = 0.7978845608028654f*(x + 0.044715f*x*x*x);
    float yc = fminf(fmaxf(y, -15.f), 15.f);
    float t = __expf(2.f*yc);
    float th = (t - 1.f)/(t + 1.f);
    return 0.5f*x*(1.f + th);
}
__device__ __forceinline__ void split2(float x, bf16& h, bf16& l){
    h = __float2bfloat16(x);
    l = __float2bfloat16(x - __bfloat162float(h));
}
__device__ __forceinline__ uint32_t smem_u32(const void* p){
    uint32_t a;
    asm("{ .reg .u64 t; cvta.to.shared.u64 t, %1; cvt.u32.u64 %0, t; }" : "=r"(a) : "l"(p));
    return a;
}
__device__ __forceinline__ void cpasync16(uint32_t dst, const void* src){
    asm volatile("cp.async.cg.shared.global [%0], [%1], 16;" :: "r"(dst), "l"(src) : "memory");
}
__device__ __forceinline__ void ldsm4(uint32_t* r, uint32_t a){
    asm volatile("ldmatrix.sync.aligned.m8n8.x4.shared.b16 {%0,%1,%2,%3}, [%4];"
        : "=r"(r[0]),"=r"(r[1]),"=r"(r[2]),"=r"(r[3]) : "r"(a));
}
__device__ __forceinline__ void ldsm4t(uint32_t* r, uint32_t a){
    asm volatile("ldmatrix.sync.aligned.m8n8.x4.trans.shared.b16 {%0,%1,%2,%3}, [%4];"
        : "=r"(r[0]),"=r"(r[1]),"=r"(r[2]),"=r"(r[3]) : "r"(a));
}
__device__ __forceinline__ void mma16816(float* c, const uint32_t* a, const uint32_t* b){
    asm volatile("mma.sync.aligned.m16n8k16.row.col.f32.bf16.bf16.f32 "
        "{%0,%1,%2,%3}, {%4,%5,%6,%7}, {%8,%9}, {%0,%1,%2,%3};"
        : "+f"(c[0]),"+f"(c[1]),"+f"(c[2]),"+f"(c[3])
        : "r"(a[0]),"r"(a[1]),"r"(a[2]),"r"(a[3]), "r"(b[0]),"r"(b[1]));
}
__device__ __forceinline__ uint32_t packbf(float lo, float hi){
    uint32_t r;
    asm("cvt.rn.bf16x2.f32 %0, %1, %2;" : "=r"(r) : "f"(hi), "f"(lo));
    return r;
}
__device__ __forceinline__ void split_store2(float v0, float v1, bf16* ph, bf16* pl){
    float h0 = __bfloat162float(__float2bfloat16(v0));
    float h1 = __bfloat162float(__float2bfloat16(v1));
    *(uint32_t*)ph = packbf(v0, v1);
    *(uint32_t*)pl = packbf(v0 - h0, v1 - h1);
}

// ================= fused flash attention (unchanged from R9) =================
#define FLDS 72
#define FTILE (64*FLDS*2)
#define FQT   (128*FLDS*2)
#define FSTG  (3*FTILE)
#define FSM   (FQT + 2*FSTG)       // 73728 B

__global__ __launch_bounds__(256, 2) void flash_kernel(){
    extern __shared__ __align__(128) char smem[];
    const uint32_t sb = smem_u32(smem);
    const int tid = threadIdx.x, lane = tid & 31, warp = tid >> 5;
    const int bh = blockIdx.y, b = bh >> 3, h = bh & 7;
    const int t0 = blockIdx.x * 128;
    const int r0 = lane >> 2, cq = lane & 3;
    const int aRow = lane & 15, aCol = (lane >> 4)*8;
    const int bQuad = lane >> 3, bRowQ = lane & 7;
    const int ntOff = bQuad >> 1, colQ = (bQuad & 1)*8;
    const int tKey = (bQuad & 1)*8 + bRowQ, tDim = (bQuad >> 1)*8;
    const uint32_t ST0 = sb + FQT;

    {
        #pragma unroll
        for (int i = 0; i < 4; i++){
            int idx = tid + i*256;
            int row = idx >> 3, ch = idx & 7;
            cpasync16(sb + (uint32_t)(row*FLDS + ch*8)*2,
                      g_qh + ((size_t)bh*Tt + t0 + row)*64 + ch*8);
        }
        #pragma unroll
        for (int i = 0; i < 6; i++){
            int idx = tid + i*256;
            int tile = idx >> 9, rem = idx & 511;
            int row = rem >> 3, ch = rem & 7;
            const bf16* base = (tile == 0) ? g_kh : (tile == 1 ? g_Vh : g_Vl);
            cpasync16(ST0 + tile*FTILE + (uint32_t)(row*FLDS + ch*8)*2,
                      base + ((size_t)bh*Tt + row)*64 + ch*8);
        }
        asm volatile("cp.async.commit_group;" ::: "memory");
    }

    float o[8][4] = {};
    float m0 = -INFINITY, m1 = -INFINITY, l0 = 0.f, l1 = 0.f;
    uint32_t qfh[4][4];

    for (int kt = 0; kt < 24; kt++){
        int s = kt & 1;
        if (kt + 1 < 24){
            int s2 = s ^ 1, s0n = (kt+1)*64;
            uint32_t base = ST0 + s2*FSTG;
            #pragma unroll
            for (int i = 0; i < 6; i++){
                int idx = tid + i*256;
                int tile = idx >> 9, rem = idx & 511;
                int row = rem >> 3, ch = rem & 7;
                const bf16* src = (tile == 0) ? g_kh : (tile == 1 ? g_Vh : g_Vl);
                cpasync16(base + tile*FTILE + (uint32_t)(row*FLDS + ch*8)*2,
                          src + ((size_t)bh*Tt + s0n + row)*64 + ch*8);
            }
            asm volatile("cp.async.commit_group;" ::: "memory");
            asm volatile("cp.async.wait_group 1;" ::: "memory");
        } else {
            asm volatile("cp.async.wait_group 0;" ::: "memory");
        }
        __syncthreads();

        if (kt == 0){
            #pragma unroll
            for (int ks = 0; ks < 4; ks++){
                uint32_t ad = sb + (uint32_t)((warp*16 + aRow)*FLDS + ks*16 + aCol)*2;
                ldsm4(qfh[ks], ad);
            }
        }

        uint32_t KB = ST0 + s*FSTG;
        float acc[8][4] = {};
        #pragma unroll
        for (int ks = 0; ks < 4; ks++){
            #pragma unroll
            for (int g = 0; g < 2; g++){
                uint32_t bfh[4][2];
                #pragma unroll
                for (int p = 0; p < 2; p++){
                    int ntb = g*4 + p*2;
                    uint32_t bd = KB + (uint32_t)(((ntb + ntOff)*8 + bRowQ)*FLDS + ks*16 + colQ)*2;
                    uint32_t r4[4];
                    ldsm4(r4, bd);
                    bfh[p*2][0]=r4[0]; bfh[p*2][1]=r4[1]; bfh[p*2+1][0]=r4[2]; bfh[p*2+1][1]=r4[3];
                }
                #pragma unroll
                for (int j = 0; j < 4; j++) mma16816(acc[g*4+j], qfh[ks], bfh[j]);
            }
        }

        float tm0 = -INFINITY, tm1 = -INFINITY;
        #pragma unroll
        for (int nt = 0; nt < 8; nt++){
            tm0 = fmaxf(tm0, fmaxf(acc[nt][0], acc[nt][1]));
            tm1 = fmaxf(tm1, fmaxf(acc[nt][2], acc[nt][3]));
        }
        tm0 = fmaxf(tm0, __shfl_xor_sync(~0u, tm0, 1));
        tm0 = fmaxf(tm0, __shfl_xor_sync(~0u, tm0, 2));
        tm1 = fmaxf(tm1, __shfl_xor_sync(~0u, tm1, 1));
        tm1 = fmaxf(tm1, __shfl_xor_sync(~0u, tm1, 2));
        float mn0 = fmaxf(m0, tm0), mn1 = fmaxf(m1, tm1);
        float al0 = __expf(m0 - mn0), al1 = __expf(m1 - mn1);
        float ps0 = 0.f, ps1 = 0.f;
        #pragma unroll
        for (int nt = 0; nt < 8; nt++){
            acc[nt][0] = __expf(acc[nt][0] - mn0);
            acc[nt][1] = __expf(acc[nt][1] - mn0);
            acc[nt][2] = __expf(acc[nt][2] - mn1);
            acc[nt][3] = __expf(acc[nt][3] - mn1);
            ps0 += acc[nt][0] + acc[nt][1];
            ps1 += acc[nt][2] + acc[nt][3];
        }
        ps0 += __shfl_xor_sync(~0u, ps0, 1); ps0 += __shfl_xor_sync(~0u, ps0, 2);
        ps1 += __shfl_xor_sync(~0u, ps1, 1); ps1 += __shfl_xor_sync(~0u, ps1, 2);
        l0 = l0*al0 + ps0; l1 = l1*al1 + ps1;
        m0 = mn0; m1 = mn1;
        #pragma unroll
        for (int nt = 0; nt < 8; nt++){
            o[nt][0] *= al0; o[nt][1] *= al0; o[nt][2] *= al1; o[nt][3] *= al1;
        }

        uint32_t VB = KB + FTILE;
        #pragma unroll
        for (int kc = 0; kc < 4; kc++){
            uint32_t aph[4], apl[4];
            {
                float e[8] = {acc[2*kc][0], acc[2*kc][1], acc[2*kc][2], acc[2*kc][3],
                              acc[2*kc+1][0], acc[2*kc+1][1], acc[2*kc+1][2], acc[2*kc+1][3]};
                float hi[8], lo[8];
                #pragma unroll
                for (int e2 = 0; e2 < 8; e2++){
                    hi[e2] = __bfloat162float(__float2bfloat16(e[e2]));
                    lo[e2] = e[e2] - hi[e2];
                }
                aph[0] = packbf(hi[0], hi[1]); aph[1] = packbf(hi[2], hi[3]);
                aph[2] = packbf(hi[4], hi[5]); aph[3] = packbf(hi[6], hi[7]);
                apl[0] = packbf(lo[0], lo[1]); apl[1] = packbf(lo[2], lo[3]);
                apl[2] = packbf(lo[4], lo[5]); apl[3] = packbf(lo[6], lo[7]);
            }
            #pragma unroll
            for (int g = 0; g < 2; g++){
                uint32_t bfh[4][2], bfl[4][2];
                #pragma unroll
                for (int p = 0; p < 2; p++){
                    int ntb = g*4 + p*2;
                    uint32_t bd = VB + (uint32_t)((kc*16 + tKey)*FLDS + ntb*8 + tDim)*2;
                    uint32_t r4[4];
                    ldsm4t(r4, bd);
                    bfh[p*2][0]=r4[0]; bfh[p*2][1]=r4[1]; bfh[p*2+1][0]=r4[2]; bfh[p*2+1][1]=r4[3];
                    ldsm4t(r4, bd + FTILE);
                    bfl[p*2][0]=r4[0]; bfl[p*2][1]=r4[1]; bfl[p*2+1][0]=r4[2]; bfl[p*2+1][1]=r4[3];
                }
                #pragma unroll
                for (int j = 0; j < 4; j++) mma16816(o[g*4+j], aph, bfh[j]);
                #pragma unroll
                for (int j = 0; j < 4; j++) mma16816(o[g*4+j], aph, bfl[j]);
                #pragma unroll
                for (int j = 0; j < 4; j++) mma16816(o[g*4+j], apl, bfh[j]);
            }
        }
        __syncthreads();
    }

    if (t0 >= TRAIN){
        float mm[2] = {m0, m1}, ll[2] = {l0, l1};
        #pragma unroll
        for (int r = 0; r < 2; r++){
            int trow = t0 + warp*16 + r0 + 8*r;
            size_t qb = ((size_t)(b*Tt + trow))*1536 + h*64;
            float part = 0.f;
            #pragma unroll
            for (int d = 0; d < 16; d++)
                part += g_qkv[qb + cq*16 + d] * g_qkv[qb + 512 + cq*16 + d];
            part += __shfl_xor_sync(~0u, part, 1);
            part += __shfl_xor_sync(~0u, part, 2);
            float mn = fmaxf(mm[r], part);
            float al = __expf(mm[r] - mn);
            float p  = __expf(part - mn);
            ll[r] = ll[r]*al + p;
            const float* vs = g_qkv + qb + 1024;
            #pragma unroll
            for (int nt = 0; nt < 8; nt++){
                o[nt][2*r+0] = o[nt][2*r+0]*al + p*vs[nt*8 + 2*cq + 0];
                o[nt][2*r+1] = o[nt][2*r+1]*al + p*vs[nt*8 + 2*cq + 1];
            }
        }
        l0 = ll[0]; l1 = ll[1];
    }

    float inv[2] = {1.f/l0, 1.f/l1};
    #pragma unroll
    for (int r = 0; r < 2; r++){
        int trow = t0 + warp*16 + r0 + 8*r;
        size_t ob = ((size_t)(b*Tt + trow))*Dd + h*64;
        #pragma unroll
        for (int nt = 0; nt < 8; nt++){
            size_t off = ob + nt*8 + 2*cq;
            split_store2(o[nt][2*r]*inv[r], o[nt][2*r+1]*inv[r], g_ah + off, g_al + off);
        }
    }
}

// ---------------- split-bf16 HMMA GEMM (3-stage, XOR-swizzled 64B rows) ----------------
// smem tile: 128 rows x 32 bf16 (64 B). physical chunk = logical ^ ((row>>1)&3).
// EPI: 0 = fp32 C (+bias,+res), 1 = gelu -> split bf16, 2 = QKV rope scatter
#define BK 32
#define TILE_B (128*64)             // 8192 B
#define STAGE_B (4*TILE_B)          // 32768 B
#define GSM (3*STAGE_B)             // 98304 B

__global__ __launch_bounds__(256, 2) void mma_gemm(
    const bf16* __restrict__ Ah, const bf16* __restrict__ Al,
    const bf16* __restrict__ Bh, const bf16* __restrict__ Bl,
    const float* __restrict__ bias, const float* __restrict__ res,
    float* C, bf16* Chi, bf16* Clo,
    int K, int ldb, int Nreal, int ldC, size_t sA, size_t sB, size_t sC, int EPI)
{
    extern __shared__ __align__(128) char smem[];
    const uint32_t sb = smem_u32(smem);
    const int tid = threadIdx.x, lane = tid & 31, wid = tid >> 5;
    const int m0 = blockIdx.y*128, n0 = blockIdx.x*128;
    const size_t zb = blockIdx.z;
    const bf16* pAh = Ah + zb*sA + (size_t)m0*K;
    const bf16* pAl = Al + zb*sA + (size_t)m0*K;
    const bf16* pBh = Bh + zb*sB + (size_t)n0*ldb;
    const bf16* pBl = Bl + zb*sB + (size_t)n0*ldb;

    float acc[4][4][4] = {};
    const int nk = K/BK;

    auto issue = [&](int c, int s){
        uint32_t base = sb + s*STAGE_B;
        #pragma unroll
        for (int i = 0; i < 2; i++){
            int seg = tid + i*256;
            int row = seg >> 2, s4 = seg & 3;
            int phys = s4 ^ ((row >> 1) & 3);
            uint32_t doff = (uint32_t)(row*64 + phys*16);
            const size_t go = (size_t)row*K + c*BK + s4*8;
            const size_t gob = (size_t)row*ldb + c*BK + s4*8;
            cpasync16(base + 0*TILE_B + doff, pAh + go);
            cpasync16(base + 1*TILE_B + doff, pAl + go);
            cpasync16(base + 2*TILE_B + doff, pBh + gob);
            cpasync16(base + 3*TILE_B + doff, pBl + gob);
        }
        asm volatile("cp.async.commit_group;" ::: "memory");
    };

    issue(0, 0);
    if (nk > 1) issue(1, 1);
    const int wm = (wid>>2)*64, wn = (wid&3)*32;
    const int aRow = lane & 15, aChu = lane >> 4;       // chunk sub-index for A
    const int bQuad = lane >> 3, bRowQ = lane & 7;
    const int ntOff = bQuad >> 1, bChu = bQuad & 1;     // chunk sub-index for B

    int st = 0;
    for (int c = 0; c < nk; c++){
        if (c+1 < nk) asm volatile("cp.async.wait_group 1;" ::: "memory");
        else          asm volatile("cp.async.wait_group 0;" ::: "memory");
        __syncthreads();
        if (c+2 < nk){
            int s2 = st + 2; if (s2 >= 3) s2 -= 3;
            issue(c+2, s2);
        }
        uint32_t base = sb + st*STAGE_B;
        #pragma unroll
        for (int ks = 0; ks < 2; ks++){
            uint32_t a_h[4][4], a_l[4][4], b_h[4][2], b_l[4][2];
            #pragma unroll
            for (int mt = 0; mt < 4; mt++){
                int row = wm + mt*16 + aRow;
                int phys = (2*ks + aChu) ^ ((row >> 1) & 3);
                uint32_t ad = base + (uint32_t)(row*64 + phys*16);
                ldsm4(a_h[mt], ad);
                ldsm4(a_l[mt], ad + TILE_B);
            }
            #pragma unroll
            for (int p = 0; p < 2; p++){
                int row = wn + (p*2 + ntOff)*8 + bRowQ;
                int phys = (2*ks + bChu) ^ ((row >> 1) & 3);
                uint32_t bd = base + 2*TILE_B + (uint32_t)(row*64 + phys*16);
                uint32_t r4[4];
                ldsm4(r4, bd);
                b_h[p*2][0]=r4[0]; b_h[p*2][1]=r4[1]; b_h[p*2+1][0]=r4[2]; b_h[p*2+1][1]=r4[3];
                ldsm4(r4, bd + TILE_B);
                b_l[p*2][0]=r4[0]; b_l[p*2][1]=r4[1]; b_l[p*2+1][0]=r4[2]; b_l[p*2+1][1]=r4[3];
            }
            #pragma unroll
            for (int mt = 0; mt < 4; mt++)
                #pragma unroll
                for (int nt = 0; nt < 4; nt++){
                    mma16816(acc[mt][nt], a_h[mt], b_h[nt]);
                    mma16816(acc[mt][nt], a_h[mt], b_l[nt]);
                    mma16816(acc[mt][nt], a_l[mt], b_h[nt]);
                }
        }
        st++; if (st >= 3) st -= 3;
    }

    const int r0 = lane >> 2, cW = (lane & 3)*2;
    #pragma unroll
    for (int mt = 0; mt < 4; mt++)
    #pragma unroll
    for (int hh2 = 0; hh2 < 2; hh2++){
        int gm = m0 + wm + mt*16 + r0 + hh2*8;
        #pragma unroll
        for (int nt = 0; nt < 4; nt++){
            float v0 = acc[mt][nt][hh2*2+0], v1 = acc[mt][nt][hh2*2+1];
            int gn = n0 + wn + nt*8 + cW;
            if (bias){ v0 += __ldg(bias+gn); v1 += __ldg(bias+gn+1); }
            if (EPI == 2){
                int b = gm >> 11, t = gm & (Tt-1);
                if (gn < 1024){
                    int hq = (gn & 511) >> 6;
                    int i = (gn & 63) >> 1;
                    float cc = g_cos[t*32+i], ss = g_sin[t*32+i];
                    float r1 = v0*cc - v1*ss, r2 = v0*ss + v1*cc;
                    if (gn < 512){ r1 *= 0.125f; r2 *= 0.125f; }
                    size_t qo = ((size_t)(b*8+hq)*Tt + t)*64 + (gn & 63);
                    if (gn < 512) *(uint32_t*)(g_qh + qo) = packbf(r1, r2);
                    else          *(uint32_t*)(g_kh + qo) = packbf(r1, r2);
                    if (t >= TRAIN){
                        size_t fo = (size_t)gm*1536 + gn;
                        g_qkv[fo] = r1; g_qkv[fo+1] = r2;
                    }
                } else {
                    int h2 = (gn - 1024) >> 6, dd = (gn - 1024) & 63;
                    size_t vo = ((size_t)(b*8+h2)*Tt + t)*64 + dd;
                    split_store2(v0, v1, g_Vh + vo, g_Vl + vo);
                    if (t >= TRAIN){
                        size_t fo = (size_t)gm*1536 + gn;
                        g_qkv[fo] = v0; g_qkv[fo+1] = v1;
                    }
                }
            } else if (EPI == 1){
                size_t off = zb*sC + (size_t)gm*ldC + gn;
                split_store2(gelu_f(v0), gelu_f(v1), Chi + off, Clo + off);
            } else {
                size_t off = zb*sC + (size_t)gm*ldC + gn;
                if (res){ v0 += res[off]; v1 += res[off+1]; }
                if (gn+1 < Nreal){
                    *(float2*)(C + off) = make_float2(v0, v1);
                } else {
                    if (gn < Nreal) C[off] = v0;
                }
            }
        }
    }
}

// ---------------- weight transpose + split ----------------
__global__ void wsplit_kernel(const float* __restrict__ W, bf16* oh, bf16* ol,
                              int K, int N, int Npad){
    __shared__ float sm[32][33];
    int n0 = blockIdx.x*32, k0 = blockIdx.y*32, z = blockIdx.z;
    const float* Wb = W + (size_t)z*K*N;
    size_t ob = (size_t)z*Npad*K;
    int tx = threadIdx.x, ty = threadIdx.y;
    #pragma unroll
    for (int j = 0; j < 4; j++){
        int n = n0 + tx;
        sm[ty+8*j][tx] = (n < N) ? Wb[(size_t)(k0+ty+8*j)*N + n] : 0.f;
    }
    __syncthreads();
    #pragma unroll
    for (int j = 0; j < 4; j++){
        size_t o = ob + (size_t)(n0+ty+8*j)*K + k0 + tx;
        split2(sm[tx][ty+8*j], oh[o], ol[o]);
    }
}

// ---------------- misc kernels ----------------
__global__ void embed_kernel(const float* __restrict__ R, const int* __restrict__ y,
                             const float* __restrict__ emb){
    int row = blockIdx.x, t = row & (Tt-1), b = row >> 11;
    const float4* Rr = (const float4*)(R + (size_t)row*Dd);
    float4* Or = (float4*)(g_rep + (size_t)row*Dd);
    if (t < TRAIN){
        int yv = y[b*TRAIN + t];
        const float4* E = (const float4*)(emb + (size_t)yv*Dd);
        for (int i = threadIdx.x; i < Dd/4; i += blockDim.x){
            float4 a = Rr[i]; float4 e = E[i];
            a.x += e.x; a.y += e.y; a.z += e.z; a.w += e.w;
            Or[i] = a;
        }
    } else {
        for (int i = threadIdx.x; i < Dd/4; i += blockDim.x) Or[i] = Rr[i];
    }
}

__global__ void ln_kernel(const float* __restrict__ g, const float* __restrict__ be){
    __shared__ float sh[Dd];
    __shared__ float red[4];
    int row = blockIdx.x;
    const float* xr = g_rep + (size_t)row*Dd;
    float s = 0.f;
    for (int i = threadIdx.x; i < Dd; i += 128){ float v = xr[i]; sh[i] = v; s += v; }
    #pragma unroll
    for (int o = 16; o; o >>= 1) s += __shfl_xor_sync(~0u, s, o);
    if ((threadIdx.x & 31) == 0) red[threadIdx.x >> 5] = s;
    __syncthreads();
    float mu = (red[0]+red[1]+red[2]+red[3]) * (1.f/Dd);
    float vs = 0.f;
    for (int i = threadIdx.x; i < Dd; i += 128){ float d = sh[i]-mu; vs += d*d; }
    #pragma unroll
    for (int o = 16; o; o >>= 1) vs += __shfl_xor_sync(~0u, vs, o);
    __syncthreads();
    if ((threadIdx.x & 31) == 0) red[threadIdx.x >> 5] = vs;
    __syncthreads();
    float rs = rsqrtf((red[0]+red[1]+red[2]+red[3])*(1.f/Dd) + 1e-5f);
    for (int i = threadIdx.x; i < Dd; i += 128){
        size_t o = (size_t)row*Dd + i;
        split2((sh[i]-mu)*rs*g[i] + be[i], g_hh[o], g_hl[o]);
    }
}

__global__ void rope_table_kernel(){
    int t = blockIdx.x, i = threadIdx.x;
    float inv = (float)pow(100000.0, -((double)(2*i))/64.0);
    float ang = (float)t * inv;
    g_cos[t*32+i] = cosf(ang);
    g_sin[t*32+i] = sinf(ang);
}

__global__ void extract_kernel(){
    int r = blockIdx.x, b = r >> 9, i = r & 511;
    const float* src = g_rep + (size_t)(b*Tt + TRAIN + i)*Dd;
    for (int j = threadIdx.x; j < Dd; j += 128)
        split2(src[j], g_th[(size_t)r*Dd + j], g_tl[(size_t)r*Dd + j]);
}

// ---------------- launcher ----------------
#define SYM(p, s) cudaGetSymbolAddress((void**)&p, s)

extern "C" void kernel_launch(void* const* d_in, const int* in_sizes, int n_in,
                              void* d_out, int out_size){
    const float* R    = (const float*)d_in[0];
    const int*   y    = (const int*)  d_in[1];
    const float* emb  = (const float*)d_in[2];
    const float* Wqkv = (const float*)d_in[3];
    const float* bqkv = (const float*)d_in[4];
    const float* Wo   = (const float*)d_in[5];
    const float* bo   = (const float*)d_in[6];
    const float* ln1g = (const float*)d_in[7];
    const float* ln1b = (const float*)d_in[8];
    const float* ln2g = (const float*)d_in[9];
    const float* ln2b = (const float*)d_in[10];
    const float* W1   = (const float*)d_in[11];
    const float* b1   = (const float*)d_in[12];
    const float* W2   = (const float*)d_in[13];
    const float* b2   = (const float*)d_in[14];
    const float* pW1  = (const float*)d_in[15];
    const float* pb1  = (const float*)d_in[16];
    const float* pW2  = (const float*)d_in[17];
    const float* pb2  = (const float*)d_in[18];

    cudaFuncSetAttribute(mma_gemm, cudaFuncAttributeMaxDynamicSharedMemorySize, GSM);
    cudaFuncSetAttribute(flash_kernel, cudaFuncAttributeMaxDynamicSharedMemorySize, FSM);

    float *qkv, *rep;
    bf16 *hh,*hl,*ah,*al,*fh,*fl,*th,*tl,*gh,*gl;
    bf16 *Wqkvh,*Wqkvl,*Woh,*Wol,*W1h,*W1l,*W2h,*W2l,*pW1h,*pW1l,*pW2h,*pW2l;
    SYM(qkv,g_qkv); SYM(rep,g_rep);
    SYM(hh,g_hh); SYM(hl,g_hl); SYM(ah,g_ah); SYM(al,g_al);
    SYM(fh,g_fh); SYM(fl,g_fl);
    SYM(th,g_th); SYM(tl,g_tl);
    SYM(gh,g_gh); SYM(gl,g_gl);
    SYM(Wqkvh,g_Wqkvh); SYM(Wqkvl,g_Wqkvl); SYM(Woh,g_Woh); SYM(Wol,g_Wol);
    SYM(W1h,g_W1h); SYM(W1l,g_W1l); SYM(W2h,g_W2h); SYM(W2l,g_W2l);
    SYM(pW1h,g_pW1h); SYM(pW1l,g_pW1l); SYM(pW2h,g_pW2h); SYM(pW2l,g_pW2l);

    dim3 wb(32, 8);
    wsplit_kernel<<<dim3(48,16,12), wb>>>(Wqkv, Wqkvh, Wqkvl, 512, 1536, 1536);
    rope_table_kernel<<<Tt, 32>>>();
    embed_kernel<<<BT, 128>>>(R, y, emb);
    wsplit_kernel<<<dim3(16,16,12), wb>>>(Wo, Woh, Wol, 512, 512, 512);

    for (int l = 0; l < Ll; l++){
        ln_kernel<<<BT, 128>>>(ln1g + l*Dd, ln1b + l*Dd);
        mma_gemm<<<dim3(12,64,1),256,GSM>>>(hh, hl, Wqkvh + (size_t)l*1536*512, Wqkvl + (size_t)l*1536*512,
            bqkv + l*1536, nullptr, nullptr, nullptr, nullptr, 512, 512, 1536, 1536, 0,0,0, 2);
        if (l == 0){
            wsplit_kernel<<<dim3(64,16,12), wb>>>(W1, W1h, W1l, 512, 2048, 2048);
            wsplit_kernel<<<dim3(16,64,12), wb>>>(W2, W2h, W2l, 2048, 512, 512);
            wsplit_kernel<<<dim3(32,16,1),  wb>>>(pW1, pW1h, pW1l, 512, 1024, 1024);
            wsplit_kernel<<<dim3(4, 32,1),  wb>>>(pW2, pW2h, pW2l, 1024, 100, 128);
        }
        flash_kernel<<<dim3(16, NBH), 256, FSM>>>();
        mma_gemm<<<dim3(4,64,1),256,GSM>>>(ah, al, Woh + (size_t)l*512*512, Wol + (size_t)l*512*512,
            bo + l*512, rep, rep, nullptr, nullptr, 512, 512, 512, 512, 0,0,0, 0);
        ln_kernel<<<BT, 128>>>(ln2g + l*Dd, ln2b + l*Dd);
        mma_gemm<<<dim3(16,64,1),256,GSM>>>(hh, hl, W1h + (size_t)l*2048*512, W1l + (size_t)l*2048*512,
            b1 + l*2048, nullptr, nullptr, fh, fl, 512, 512, 2048, 2048, 0,0,0, 1);
        mma_gemm<<<dim3(4,64,1),256,GSM>>>(fh, fl, W2h + (size_t)l*512*2048, W2l + (size_t)l*512*2048,
            b2 + l*512, rep, rep, nullptr, nullptr, 2048, 2048, 512, 512, 0,0,0, 0);
    }

    extract_kernel<<<MTEST, 128>>>();
    mma_gemm<<<dim3(8,16,1),256,GSM>>>(th, tl, pW1h, pW1l, pb1, nullptr,
        nullptr, gh, gl, 512, 512, 1024, 1024, 0,0,0, 1);
    mma_gemm<<<dim3(1,16,1),256,GSM>>>(gh, gl, pW2h, pW2l, pb2, nullptr,
        (float*)d_out, nullptr, nullptr, 1024, 1024, 100, 100, 0,0,0, 0);
}

// round 12
// speedup vs baseline: 1.6501x; 1.0458x over previous
#include <cuda_runtime.h>
#include <cuda_bf16.h>
#include <cuda_fp16.h>
#include <math.h>
#include <stdint.h>

#define Bc    4
#define Tt    2048
#define TRAIN 1536
#define Dd    512
#define Ll    12
#define FFd   2048
#define BT    (Bc*Tt)
#define NBH   32
#define MTEST 2048

typedef __nv_bfloat16 bf16;

// ---------------- static buffers ----------------
__device__ float g_rep [BT*Dd];
__device__ float g_qkv [BT*3*Dd];          // fp32 qkv, written only for t>=TRAIN (fixup)
__device__ bf16  g_hh[BT*Dd], g_hl[BT*Dd];
__device__ bf16  g_ah[BT*Dd], g_al[BT*Dd];
__device__ bf16  g_fh[BT*FFd], g_fl[BT*FFd];
__device__ bf16  g_qh[NBH*Tt*64];
__device__ bf16  g_kh[NBH*Tt*64];
__device__ __half g_Vh[NBH*Tt*64], g_Vl[NBH*Tt*64];   // V stored fp16 hi/lo
__device__ bf16  g_th[MTEST*Dd], g_tl[MTEST*Dd];
__device__ bf16  g_gh[MTEST*2*Dd], g_gl[MTEST*2*Dd];
__device__ bf16  g_Wqkvh[Ll*3*Dd*Dd], g_Wqkvl[Ll*3*Dd*Dd];
__device__ bf16  g_Woh[Ll*Dd*Dd],  g_Wol[Ll*Dd*Dd];
__device__ bf16  g_W1h[Ll*FFd*Dd], g_W1l[Ll*FFd*Dd];
__device__ bf16  g_W2h[Ll*Dd*FFd], g_W2l[Ll*Dd*FFd];
__device__ bf16  g_pW1h[2*Dd*Dd],  g_pW1l[2*Dd*Dd];
__device__ bf16  g_pW2h[128*2*Dd], g_pW2l[128*2*Dd];
__device__ float g_cos[Tt*32], g_sin[Tt*32];

// ---------------- helpers ----------------
__device__ __forceinline__ float gelu_f(float x){
    float y = 0.7978845608028654f*(x + 0.044715f*x*x*x);
    float yc = fminf(fmaxf(y, -15.f), 15.f);
    float t = __expf(2.f*yc);
    float th = (t - 1.f)/(t + 1.f);
    return 0.5f*x*(1.f + th);
}
__device__ __forceinline__ void split2(float x, bf16& h, bf16& l){
    h = __float2bfloat16(x);
    l = __float2bfloat16(x - __bfloat162float(h));
}
__device__ __forceinline__ uint32_t smem_u32(const void* p){
    uint32_t a;
    asm("{ .reg .u64 t; cvta.to.shared.u64 t, %1; cvt.u32.u64 %0, t; }" : "=r"(a) : "l"(p));
    return a;
}
__device__ __forceinline__ void cpasync16(uint32_t dst, const void* src){
    asm volatile("cp.async.cg.shared.global [%0], [%1], 16;" :: "r"(dst), "l"(src) : "memory");
}
__device__ __forceinline__ void ldsm4(uint32_t* r, uint32_t a){
    asm volatile("ldmatrix.sync.aligned.m8n8.x4.shared.b16 {%0,%1,%2,%3}, [%4];"
        : "=r"(r[0]),"=r"(r[1]),"=r"(r[2]),"=r"(r[3]) : "r"(a));
}
__device__ __forceinline__ void ldsm4t(uint32_t* r, uint32_t a){
    asm volatile("ldmatrix.sync.aligned.m8n8.x4.trans.shared.b16 {%0,%1,%2,%3}, [%4];"
        : "=r"(r[0]),"=r"(r[1]),"=r"(r[2]),"=r"(r[3]) : "r"(a));
}
__device__ __forceinline__ void mma16816(float* c, const uint32_t* a, const uint32_t* b){
    asm volatile("mma.sync.aligned.m16n8k16.row.col.f32.bf16.bf16.f32 "
        "{%0,%1,%2,%3}, {%4,%5,%6,%7}, {%8,%9}, {%0,%1,%2,%3};"
        : "+f"(c[0]),"+f"(c[1]),"+f"(c[2]),"+f"(c[3])
        : "r"(a[0]),"r"(a[1]),"r"(a[2]),"r"(a[3]), "r"(b[0]),"r"(b[1]));
}
__device__ __forceinline__ void mma16816h(float* c, const uint32_t* a, const uint32_t* b){
    asm volatile("mma.sync.aligned.m16n8k16.row.col.f32.f16.f16.f32 "
        "{%0,%1,%2,%3}, {%4,%5,%6,%7}, {%8,%9}, {%0,%1,%2,%3};"
        : "+f"(c[0]),"+f"(c[1]),"+f"(c[2]),"+f"(c[3])
        : "r"(a[0]),"r"(a[1]),"r"(a[2]),"r"(a[3]), "r"(b[0]),"r"(b[1]));
}
__device__ __forceinline__ uint32_t packbf(float lo, float hi){
    uint32_t r;
    asm("cvt.rn.bf16x2.f32 %0, %1, %2;" : "=r"(r) : "f"(hi), "f"(lo));
    return r;
}
__device__ __forceinline__ uint32_t packh(float lo, float hi){
    uint32_t r;
    asm("cvt.rn.f16x2.f32 %0, %1, %2;" : "=r"(r) : "f"(hi), "f"(lo));
    return r;
}
__device__ __forceinline__ void split_store2(float v0, float v1, bf16* ph, bf16* pl){
    float h0 = __bfloat162float(__float2bfloat16(v0));
    float h1 = __bfloat162float(__float2bfloat16(v1));
    *(uint32_t*)ph = packbf(v0, v1);
    *(uint32_t*)pl = packbf(v0 - h0, v1 - h1);
}

// ================= fused flash attention =================
// 3-stage pipeline, one sync per key-tile. S = bf16 QK (single term).
// PV = fp16: single P term x (Vh + Vl fp16 split) -> 64 MMAs/tile.
#define FLDS 72
#define FTILE (64*FLDS*2)          // 9216
#define FQT   (128*FLDS*2)         // 18432
#define FSTG  (3*FTILE)            // 27648
#define FSM   (FQT + 3*FSTG)       // 101376

__global__ __launch_bounds__(256, 2) void flash_kernel(){
    extern __shared__ __align__(128) char smem[];
    const uint32_t sb = smem_u32(smem);
    const int tid = threadIdx.x, lane = tid & 31, warp = tid >> 5;
    const int bh = blockIdx.y, b = bh >> 3, h = bh & 7;
    const int t0 = blockIdx.x * 128;
    const int r0 = lane >> 2, cq = lane & 3;
    const int aRow = lane & 15, aCol = (lane >> 4)*8;
    const int bQuad = lane >> 3, bRowQ = lane & 7;
    const int ntOff = bQuad >> 1, colQ = (bQuad & 1)*8;
    const int tKey = (bQuad & 1)*8 + bRowQ, tDim = (bQuad >> 1)*8;
    const uint32_t ST0 = sb + FQT;

    auto issueKV = [&](int kt, int st){
        int s0n = kt*64;
        uint32_t base = ST0 + st*FSTG;
        #pragma unroll
        for (int i = 0; i < 6; i++){
            int idx = tid + i*256;
            int tile = idx >> 9, rem = idx & 511;
            int row = rem >> 3, ch = rem & 7;
            const void* src;
            if (tile == 0)      src = g_kh + ((size_t)bh*Tt + s0n + row)*64 + ch*8;
            else if (tile == 1) src = g_Vh + ((size_t)bh*Tt + s0n + row)*64 + ch*8;
            else                src = g_Vl + ((size_t)bh*Tt + s0n + row)*64 + ch*8;
            cpasync16(base + tile*FTILE + (uint32_t)(row*FLDS + ch*8)*2, src);
        }
        asm volatile("cp.async.commit_group;" ::: "memory");
    };

    {   // group 0: Q + stage 0
        #pragma unroll
        for (int i = 0; i < 4; i++){
            int idx = tid + i*256;
            int row = idx >> 3, ch = idx & 7;
            cpasync16(sb + (uint32_t)(row*FLDS + ch*8)*2,
                      g_qh + ((size_t)bh*Tt + t0 + row)*64 + ch*8);
        }
        issueKV(0, 0);          // commits group 0 (Q + stage0)
        issueKV(1, 1);          // group 1
    }

    float o[8][4] = {};
    float m0 = -INFINITY, m1 = -INFINITY, l0 = 0.f, l1 = 0.f;
    uint32_t qfh[4][4];

    int st = 0;
    for (int kt = 0; kt < 24; kt++){
        if (kt + 1 < 24) asm volatile("cp.async.wait_group 1;" ::: "memory");
        else             asm volatile("cp.async.wait_group 0;" ::: "memory");
        __syncthreads();
        if (kt + 2 < 24){
            int s2 = st + 2; if (s2 >= 3) s2 -= 3;
            issueKV(kt + 2, s2);
        }

        if (kt == 0){
            #pragma unroll
            for (int ks = 0; ks < 4; ks++){
                uint32_t ad = sb + (uint32_t)((warp*16 + aRow)*FLDS + ks*16 + aCol)*2;
                ldsm4(qfh[ks], ad);
            }
        }

        uint32_t KB = ST0 + st*FSTG;
        // ---- S = Qh Kh^T (bf16) ----
        float acc[8][4] = {};
        #pragma unroll
        for (int ks = 0; ks < 4; ks++){
            #pragma unroll
            for (int g = 0; g < 2; g++){
                uint32_t bfh[4][2];
                #pragma unroll
                for (int p = 0; p < 2; p++){
                    int ntb = g*4 + p*2;
                    uint32_t bd = KB + (uint32_t)(((ntb + ntOff)*8 + bRowQ)*FLDS + ks*16 + colQ)*2;
                    uint32_t r4[4];
                    ldsm4(r4, bd);
                    bfh[p*2][0]=r4[0]; bfh[p*2][1]=r4[1]; bfh[p*2+1][0]=r4[2]; bfh[p*2+1][1]=r4[3];
                }
                #pragma unroll
                for (int j = 0; j < 4; j++) mma16816(acc[g*4+j], qfh[ks], bfh[j]);
            }
        }

        // ---- online softmax ----
        float tm0 = -INFINITY, tm1 = -INFINITY;
        #pragma unroll
        for (int nt = 0; nt < 8; nt++){
            tm0 = fmaxf(tm0, fmaxf(acc[nt][0], acc[nt][1]));
            tm1 = fmaxf(tm1, fmaxf(acc[nt][2], acc[nt][3]));
        }
        tm0 = fmaxf(tm0, __shfl_xor_sync(~0u, tm0, 1));
        tm0 = fmaxf(tm0, __shfl_xor_sync(~0u, tm0, 2));
        tm1 = fmaxf(tm1, __shfl_xor_sync(~0u, tm1, 1));
        tm1 = fmaxf(tm1, __shfl_xor_sync(~0u, tm1, 2));
        float mn0 = fmaxf(m0, tm0), mn1 = fmaxf(m1, tm1);
        float al0 = __expf(m0 - mn0), al1 = __expf(m1 - mn1);
        float ps0 = 0.f, ps1 = 0.f;
        #pragma unroll
        for (int nt = 0; nt < 8; nt++){
            acc[nt][0] = __expf(acc[nt][0] - mn0);
            acc[nt][1] = __expf(acc[nt][1] - mn0);
            acc[nt][2] = __expf(acc[nt][2] - mn1);
            acc[nt][3] = __expf(acc[nt][3] - mn1);
            ps0 += acc[nt][0] + acc[nt][1];
            ps1 += acc[nt][2] + acc[nt][3];
        }
        ps0 += __shfl_xor_sync(~0u, ps0, 1); ps0 += __shfl_xor_sync(~0u, ps0, 2);
        ps1 += __shfl_xor_sync(~0u, ps1, 1); ps1 += __shfl_xor_sync(~0u, ps1, 2);
        l0 = l0*al0 + ps0; l1 = l1*al1 + ps1;
        m0 = mn0; m1 = mn1;
        #pragma unroll
        for (int nt = 0; nt < 8; nt++){
            o[nt][0] *= al0; o[nt][1] *= al0; o[nt][2] *= al1; o[nt][3] *= al1;
        }

        // ---- O += P V (fp16: P single term, V hi+lo) ----
        uint32_t VB = KB + FTILE;
        #pragma unroll
        for (int kc = 0; kc < 4; kc++){
            uint32_t ap[4];
            ap[0] = packh(acc[2*kc][0],   acc[2*kc][1]);
            ap[1] = packh(acc[2*kc][2],   acc[2*kc][3]);
            ap[2] = packh(acc[2*kc+1][0], acc[2*kc+1][1]);
            ap[3] = packh(acc[2*kc+1][2], acc[2*kc+1][3]);
            #pragma unroll
            for (int g = 0; g < 2; g++){
                uint32_t bfh[4][2], bfl[4][2];
                #pragma unroll
                for (int p = 0; p < 2; p++){
                    int ntb = g*4 + p*2;
                    uint32_t bd = VB + (uint32_t)((kc*16 + tKey)*FLDS + ntb*8 + tDim)*2;
                    uint32_t r4[4];
                    ldsm4t(r4, bd);
                    bfh[p*2][0]=r4[0]; bfh[p*2][1]=r4[1]; bfh[p*2+1][0]=r4[2]; bfh[p*2+1][1]=r4[3];
                    ldsm4t(r4, bd + FTILE);
                    bfl[p*2][0]=r4[0]; bfl[p*2][1]=r4[1]; bfl[p*2+1][0]=r4[2]; bfl[p*2+1][1]=r4[3];
                }
                #pragma unroll
                for (int j = 0; j < 4; j++) mma16816h(o[g*4+j], ap, bfh[j]);
                #pragma unroll
                for (int j = 0; j < 4; j++) mma16816h(o[g*4+j], ap, bfl[j]);
            }
        }
        st++; if (st >= 3) st -= 3;
    }

    // ---- self-key fixup (fp32 exact; rows t >= TRAIN) ----
    if (t0 >= TRAIN){
        float mm[2] = {m0, m1}, ll[2] = {l0, l1};
        #pragma unroll
        for (int r = 0; r < 2; r++){
            int trow = t0 + warp*16 + r0 + 8*r;
            size_t qb = ((size_t)(b*Tt + trow))*1536 + h*64;
            float part = 0.f;
            #pragma unroll
            for (int d = 0; d < 16; d++)
                part += g_qkv[qb + cq*16 + d] * g_qkv[qb + 512 + cq*16 + d];
            part += __shfl_xor_sync(~0u, part, 1);
            part += __shfl_xor_sync(~0u, part, 2);
            float mn = fmaxf(mm[r], part);
            float al = __expf(mm[r] - mn);
            float p  = __expf(part - mn);
            ll[r] = ll[r]*al + p;
            const float* vs = g_qkv + qb + 1024;
            #pragma unroll
            for (int nt = 0; nt < 8; nt++){
                o[nt][2*r+0] = o[nt][2*r+0]*al + p*vs[nt*8 + 2*cq + 0];
                o[nt][2*r+1] = o[nt][2*r+1]*al + p*vs[nt*8 + 2*cq + 1];
            }
        }
        l0 = ll[0]; l1 = ll[1];
    }

    // ---- normalize + packed split write ----
    float inv[2] = {1.f/l0, 1.f/l1};
    #pragma unroll
    for (int r = 0; r < 2; r++){
        int trow = t0 + warp*16 + r0 + 8*r;
        size_t ob = ((size_t)(b*Tt + trow))*Dd + h*64;
        #pragma unroll
        for (int nt = 0; nt < 8; nt++){
            size_t off = ob + nt*8 + 2*cq;
            split_store2(o[nt][2*r]*inv[r], o[nt][2*r+1]*inv[r], g_ah + off, g_al + off);
        }
    }
}

// ---------------- split-bf16 HMMA GEMM (3-stage, XOR-swizzled 64B rows) ----------------
// EPI: 0 = fp32 C (+bias,+res), 1 = gelu -> split bf16, 2 = QKV rope scatter
#define BK 32
#define TILE_B (128*64)             // 8192 B
#define STAGE_B (4*TILE_B)          // 32768 B
#define GSM (3*STAGE_B)             // 98304 B

__global__ __launch_bounds__(256, 2) void mma_gemm(
    const bf16* __restrict__ Ah, const bf16* __restrict__ Al,
    const bf16* __restrict__ Bh, const bf16* __restrict__ Bl,
    const float* __restrict__ bias, const float* __restrict__ res,
    float* C, bf16* Chi, bf16* Clo,
    int K, int ldb, int Nreal, int ldC, size_t sA, size_t sB, size_t sC, int EPI)
{
    extern __shared__ __align__(128) char smem[];
    const uint32_t sb = smem_u32(smem);
    const int tid = threadIdx.x, lane = tid & 31, wid = tid >> 5;
    const int m0 = blockIdx.y*128, n0 = blockIdx.x*128;
    const size_t zb = blockIdx.z;
    const bf16* pAh = Ah + zb*sA + (size_t)m0*K;
    const bf16* pAl = Al + zb*sA + (size_t)m0*K;
    const bf16* pBh = Bh + zb*sB + (size_t)n0*ldb;
    const bf16* pBl = Bl + zb*sB + (size_t)n0*ldb;

    float acc[4][4][4] = {};
    const int nk = K/BK;

    auto issue = [&](int c, int s){
        uint32_t base = sb + s*STAGE_B;
        #pragma unroll
        for (int i = 0; i < 2; i++){
            int seg = tid + i*256;
            int row = seg >> 2, s4 = seg & 3;
            int phys = s4 ^ ((row >> 1) & 3);
            uint32_t doff = (uint32_t)(row*64 + phys*16);
            const size_t go = (size_t)row*K + c*BK + s4*8;
            const size_t gob = (size_t)row*ldb + c*BK + s4*8;
            cpasync16(base + 0*TILE_B + doff, pAh + go);
            cpasync16(base + 1*TILE_B + doff, pAl + go);
            cpasync16(base + 2*TILE_B + doff, pBh + gob);
            cpasync16(base + 3*TILE_B + doff, pBl + gob);
        }
        asm volatile("cp.async.commit_group;" ::: "memory");
    };

    issue(0, 0);
    if (nk > 1) issue(1, 1);
    const int wm = (wid>>2)*64, wn = (wid&3)*32;
    const int aRow = lane & 15, aChu = lane >> 4;
    const int bQuad = lane >> 3, bRowQ = lane & 7;
    const int ntOff = bQuad >> 1, bChu = bQuad & 1;

    int st = 0;
    for (int c = 0; c < nk; c++){
        if (c+1 < nk) asm volatile("cp.async.wait_group 1;" ::: "memory");
        else          asm volatile("cp.async.wait_group 0;" ::: "memory");
        __syncthreads();
        if (c+2 < nk){
            int s2 = st + 2; if (s2 >= 3) s2 -= 3;
            issue(c+2, s2);
        }
        uint32_t base = sb + st*STAGE_B;
        #pragma unroll
        for (int ks = 0; ks < 2; ks++){
            uint32_t a_h[4][4], a_l[4][4], b_h[4][2], b_l[4][2];
            #pragma unroll
            for (int mt = 0; mt < 4; mt++){
                int row = wm + mt*16 + aRow;
                int phys = (2*ks + aChu) ^ ((row >> 1) & 3);
                uint32_t ad = base + (uint32_t)(row*64 + phys*16);
                ldsm4(a_h[mt], ad);
                ldsm4(a_l[mt], ad + TILE_B);
            }
            #pragma unroll
            for (int p = 0; p < 2; p++){
                int row = wn + (p*2 + ntOff)*8 + bRowQ;
                int phys = (2*ks + bChu) ^ ((row >> 1) & 3);
                uint32_t bd = base + 2*TILE_B + (uint32_t)(row*64 + phys*16);
                uint32_t r4[4];
                ldsm4(r4, bd);
                b_h[p*2][0]=r4[0]; b_h[p*2][1]=r4[1]; b_h[p*2+1][0]=r4[2]; b_h[p*2+1][1]=r4[3];
                ldsm4(r4, bd + TILE_B);
                b_l[p*2][0]=r4[0]; b_l[p*2][1]=r4[1]; b_l[p*2+1][0]=r4[2]; b_l[p*2+1][1]=r4[3];
            }
            #pragma unroll
            for (int mt = 0; mt < 4; mt++)
                #pragma unroll
                for (int nt = 0; nt < 4; nt++){
                    mma16816(acc[mt][nt], a_h[mt], b_h[nt]);
                    mma16816(acc[mt][nt], a_h[mt], b_l[nt]);
                    mma16816(acc[mt][nt], a_l[mt], b_h[nt]);
                }
        }
        st++; if (st >= 3) st -= 3;
    }

    const int r0 = lane >> 2, cW = (lane & 3)*2;
    #pragma unroll
    for (int mt = 0; mt < 4; mt++)
    #pragma unroll
    for (int hh2 = 0; hh2 < 2; hh2++){
        int gm = m0 + wm + mt*16 + r0 + hh2*8;
        #pragma unroll
        for (int nt = 0; nt < 4; nt++){
            float v0 = acc[mt][nt][hh2*2+0], v1 = acc[mt][nt][hh2*2+1];
            int gn = n0 + wn + nt*8 + cW;
            if (bias){ v0 += __ldg(bias+gn); v1 += __ldg(bias+gn+1); }
            if (EPI == 2){
                int b = gm >> 11, t = gm & (Tt-1);
                if (gn < 1024){
                    int hq = (gn & 511) >> 6;
                    int i = (gn & 63) >> 1;
                    float cc = g_cos[t*32+i], ss = g_sin[t*32+i];
                    float r1 = v0*cc - v1*ss, r2 = v0*ss + v1*cc;
                    if (gn < 512){ r1 *= 0.125f; r2 *= 0.125f; }
                    size_t qo = ((size_t)(b*8+hq)*Tt + t)*64 + (gn & 63);
                    if (gn < 512) *(uint32_t*)(g_qh + qo) = packbf(r1, r2);
                    else          *(uint32_t*)(g_kh + qo) = packbf(r1, r2);
                    if (t >= TRAIN){
                        size_t fo = (size_t)gm*1536 + gn;
                        g_qkv[fo] = r1; g_qkv[fo+1] = r2;
                    }
                } else {
                    int h2 = (gn - 1024) >> 6, dd = (gn - 1024) & 63;
                    size_t vo = ((size_t)(b*8+h2)*Tt + t)*64 + dd;
                    float h0f = __half2float(__float2half_rn(v0));
                    float h1f = __half2float(__float2half_rn(v1));
                    *(uint32_t*)(g_Vh + vo) = packh(v0, v1);
                    *(uint32_t*)(g_Vl + vo) = packh(v0 - h0f, v1 - h1f);
                    if (t >= TRAIN){
                        size_t fo = (size_t)gm*1536 + gn;
                        g_qkv[fo] = v0; g_qkv[fo+1] = v1;
                    }
                }
            } else if (EPI == 1){
                size_t off = zb*sC + (size_t)gm*ldC + gn;
                split_store2(gelu_f(v0), gelu_f(v1), Chi + off, Clo + off);
            } else {
                size_t off = zb*sC + (size_t)gm*ldC + gn;
                if (res){ v0 += res[off]; v1 += res[off+1]; }
                if (gn+1 < Nreal){
                    *(float2*)(C + off) = make_float2(v0, v1);
                } else {
                    if (gn < Nreal) C[off] = v0;
                }
            }
        }
    }
}

// ---------------- weight transpose + split ----------------
__global__ void wsplit_kernel(const float* __restrict__ W, bf16* oh, bf16* ol,
                              int K, int N, int Npad){
    __shared__ float sm[32][33];
    int n0 = blockIdx.x*32, k0 = blockIdx.y*32, z = blockIdx.z;
    const float* Wb = W + (size_t)z*K*N;
    size_t ob = (size_t)z*Npad*K;
    int tx = threadIdx.x, ty = threadIdx.y;
    #pragma unroll
    for (int j = 0; j < 4; j++){
        int n = n0 + tx;
        sm[ty+8*j][tx] = (n < N) ? Wb[(size_t)(k0+ty+8*j)*N + n] : 0.f;
    }
    __syncthreads();
    #pragma unroll
    for (int j = 0; j < 4; j++){
        size_t o = ob + (size_t)(n0+ty+8*j)*K + k0 + tx;
        split2(sm[tx][ty+8*j], oh[o], ol[o]);
    }
}

// ---------------- misc kernels ----------------
__global__ void embed_kernel(const float* __restrict__ R, const int* __restrict__ y,
                             const float* __restrict__ emb){
    int row = blockIdx.x, t = row & (Tt-1), b = row >> 11;
    const float4* Rr = (const float4*)(R + (size_t)row*Dd);
    float4* Or = (float4*)(g_rep + (size_t)row*Dd);
    if (t < TRAIN){
        int yv = y[b*TRAIN + t];
        const float4* E = (const float4*)(emb + (size_t)yv*Dd);
        for (int i = threadIdx.x; i < Dd/4; i += blockDim.x){
            float4 a = Rr[i]; float4 e = E[i];
            a.x += e.x; a.y += e.y; a.z += e.z; a.w += e.w;
            Or[i] = a;
        }
    } else {
        for (int i = threadIdx.x; i < Dd/4; i += blockDim.x) Or[i] = Rr[i];
    }
}

__global__ void ln_kernel(const float* __restrict__ g, const float* __restrict__ be){
    __shared__ float sh[Dd];
    __shared__ float red[4];
    int row = blockIdx.x;
    const float* xr = g_rep + (size_t)row*Dd;
    float s = 0.f;
    for (int i = threadIdx.x; i < Dd; i += 128){ float v = xr[i]; sh[i] = v; s += v; }
    #pragma unroll
    for (int o = 16; o; o >>= 1) s += __shfl_xor_sync(~0u, s, o);
    if ((threadIdx.x & 31) == 0) red[threadIdx.x >> 5] = s;
    __syncthreads();
    float mu = (red[0]+red[1]+red[2]+red[3]) * (1.f/Dd);
    float vs = 0.f;
    for (int i = threadIdx.x; i < Dd; i += 128){ float d = sh[i]-mu; vs += d*d; }
    #pragma unroll
    for (int o = 16; o; o >>= 1) vs += __shfl_xor_sync(~0u, vs, o);
    __syncthreads();
    if ((threadIdx.x & 31) == 0) red[threadIdx.x >> 5] = vs;
    __syncthreads();
    float rs = rsqrtf((red[0]+red[1]+red[2]+red[3])*(1.f/Dd) + 1e-5f);
    for (int i = threadIdx.x; i < Dd; i += 128){
        size_t o = (size_t)row*Dd + i;
        split2((sh[i]-mu)*rs*g[i] + be[i], g_hh[o], g_hl[o]);
    }
}

__global__ void rope_table_kernel(){
    int t = blockIdx.x, i = threadIdx.x;
    float inv = (float)pow(100000.0, -((double)(2*i))/64.0);
    float ang = (float)t * inv;
    g_cos[t*32+i] = cosf(ang);
    g_sin[t*32+i] = sinf(ang);
}

__global__ void extract_kernel(){
    int r = blockIdx.x, b = r >> 9, i = r & 511;
    const float* src = g_rep + (size_t)(b*Tt + TRAIN + i)*Dd;
    for (int j = threadIdx.x; j < Dd; j += 128)
        split2(src[j], g_th[(size_t)r*Dd + j], g_tl[(size_t)r*Dd + j]);
}

// ---------------- launcher ----------------
#define SYM(p, s) cudaGetSymbolAddress((void**)&p, s)

extern "C" void kernel_launch(void* const* d_in, const int* in_sizes, int n_in,
                              void* d_out, int out_size){
    const float* R    = (const float*)d_in[0];
    const int*   y    = (const int*)  d_in[1];
    const float* emb  = (const float*)d_in[2];
    const float* Wqkv = (const float*)d_in[3];
    const float* bqkv = (const float*)d_in[4];
    const float* Wo   = (const float*)d_in[5];
    const float* bo   = (const float*)d_in[6];
    const float* ln1g = (const float*)d_in[7];
    const float* ln1b = (const float*)d_in[8];
    const float* ln2g = (const float*)d_in[9];
    const float* ln2b = (const float*)d_in[10];
    const float* W1   = (const float*)d_in[11];
    const float* b1   = (const float*)d_in[12];
    const float* W2   = (const float*)d_in[13];
    const float* b2   = (const float*)d_in[14];
    const float* pW1  = (const float*)d_in[15];
    const float* pb1  = (const float*)d_in[16];
    const float* pW2  = (const float*)d_in[17];
    const float* pb2  = (const float*)d_in[18];

    cudaFuncSetAttribute(mma_gemm, cudaFuncAttributeMaxDynamicSharedMemorySize, GSM);
    cudaFuncSetAttribute(flash_kernel, cudaFuncAttributeMaxDynamicSharedMemorySize, FSM);

    float *qkv, *rep;
    bf16 *hh,*hl,*ah,*al,*fh,*fl,*th,*tl,*gh,*gl;
    bf16 *Wqkvh,*Wqkvl,*Woh,*Wol,*W1h,*W1l,*W2h,*W2l,*pW1h,*pW1l,*pW2h,*pW2l;
    SYM(qkv,g_qkv); SYM(rep,g_rep);
    SYM(hh,g_hh); SYM(hl,g_hl); SYM(ah,g_ah); SYM(al,g_al);
    SYM(fh,g_fh); SYM(fl,g_fl);
    SYM(th,g_th); SYM(tl,g_tl);
    SYM(gh,g_gh); SYM(gl,g_gl);
    SYM(Wqkvh,g_Wqkvh); SYM(Wqkvl,g_Wqkvl); SYM(Woh,g_Woh); SYM(Wol,g_Wol);
    SYM(W1h,g_W1h); SYM(W1l,g_W1l); SYM(W2h,g_W2h); SYM(W2l,g_W2l);
    SYM(pW1h,g_pW1h); SYM(pW1l,g_pW1l); SYM(pW2h,g_pW2h); SYM(pW2l,g_pW2l);

    dim3 wb(32, 8);
    wsplit_kernel<<<dim3(48,16,12), wb>>>(Wqkv, Wqkvh, Wqkvl, 512, 1536, 1536);
    rope_table_kernel<<<Tt, 32>>>();
    embed_kernel<<<BT, 128>>>(R, y, emb);
    wsplit_kernel<<<dim3(16,16,12), wb>>>(Wo, Woh, Wol, 512, 512, 512);

    for (int l = 0; l < Ll; l++){
        ln_kernel<<<BT, 128>>>(ln1g + l*Dd, ln1b + l*Dd);
        mma_gemm<<<dim3(12,64,1),256,GSM>>>(hh, hl, Wqkvh + (size_t)l*1536*512, Wqkvl + (size_t)l*1536*512,
            bqkv + l*1536, nullptr, nullptr, nullptr, nullptr, 512, 512, 1536, 1536, 0,0,0, 2);
        if (l == 0){
            wsplit_kernel<<<dim3(64,16,12), wb>>>(W1, W1h, W1l, 512, 2048, 2048);
            wsplit_kernel<<<dim3(16,64,12), wb>>>(W2, W2h, W2l, 2048, 512, 512);
            wsplit_kernel<<<dim3(32,16,1),  wb>>>(pW1, pW1h, pW1l, 512, 1024, 1024);
            wsplit_kernel<<<dim3(4, 32,1),  wb>>>(pW2, pW2h, pW2l, 1024, 100, 128);
        }
        flash_kernel<<<dim3(16, NBH), 256, FSM>>>();
        mma_gemm<<<dim3(4,64,1),256,GSM>>>(ah, al, Woh + (size_t)l*512*512, Wol + (size_t)l*512*512,
            bo + l*512, rep, rep, nullptr, nullptr, 512, 512, 512, 512, 0,0,0, 0);
        ln_kernel<<<BT, 128>>>(ln2g + l*Dd, ln2b + l*Dd);
        mma_gemm<<<dim3(16,64,1),256,GSM>>>(hh, hl, W1h + (size_t)l*2048*512, W1l + (size_t)l*2048*512,
            b1 + l*2048, nullptr, nullptr, fh, fl, 512, 512, 2048, 2048, 0,0,0, 1);
        mma_gemm<<<dim3(4,64,1),256,GSM>>>(fh, fl, W2h + (size_t)l*512*2048, W2l + (size_t)l*512*2048,
            b2 + l*512, rep, rep, nullptr, nullptr, 2048, 2048, 512, 512, 0,0,0, 0);
    }

    extract_kernel<<<MTEST, 128>>>();
    mma_gemm<<<dim3(8,16,1),256,GSM>>>(th, tl, pW1h, pW1l, pb1, nullptr,
        nullptr, gh, gl, 512, 512, 1024, 1024, 0,0,0, 1);
    mma_gemm<<<dim3(1,16,1),256,GSM>>>(gh, gl, pW2h, pW2l, pb2, nullptr,
        (float*)d_out, nullptr, nullptr, 1024, 1024, 100, 100, 0,0,0, 0);
}

// round 13
// speedup vs baseline: 1.7500x; 1.0606x over previous
#include <cuda_runtime.h>
#include <cuda_bf16.h>
#include <cuda_fp16.h>
#include <math.h>
#include <stdint.h>

#define Bc    4
#define Tt    2048
#define TRAIN 1536
#define Dd    512
#define Ll    12
#define FFd   2048
#define BT    (Bc*Tt)
#define NBH   32
#define MTEST 2048

typedef __nv_bfloat16 bf16;

// ---------------- static buffers ----------------
__device__ float g_rep [BT*Dd];
__device__ float g_qkv [BT*3*Dd];          // fp32 qkv, written only for t>=TRAIN (fixup)
__device__ bf16  g_hh[BT*Dd], g_hl[BT*Dd];
__device__ bf16  g_ah[BT*Dd], g_al[BT*Dd];
__device__ bf16  g_fh[BT*FFd], g_fl[BT*FFd];
__device__ bf16  g_qh[NBH*Tt*64];
__device__ bf16  g_kh[NBH*Tt*64];
__device__ __half g_Vh[NBH*Tt*64];         // V stored fp16 (single term)
__device__ bf16  g_th[MTEST*Dd], g_tl[MTEST*Dd];
__device__ bf16  g_gh[MTEST*2*Dd], g_gl[MTEST*2*Dd];
__device__ bf16  g_Wqkvh[Ll*3*Dd*Dd], g_Wqkvl[Ll*3*Dd*Dd];
__device__ bf16  g_Woh[Ll*Dd*Dd],  g_Wol[Ll*Dd*Dd];
__device__ bf16  g_W1h[Ll*FFd*Dd], g_W1l[Ll*FFd*Dd];
__device__ bf16  g_W2h[Ll*Dd*FFd], g_W2l[Ll*Dd*FFd];
__device__ bf16  g_pW1h[2*Dd*Dd],  g_pW1l[2*Dd*Dd];
__device__ bf16  g_pW2h[128*2*Dd], g_pW2l[128*2*Dd];
__device__ float g_cos[Tt*32], g_sin[Tt*32];

// ---------------- helpers ----------------
__device__ __forceinline__ float gelu_f(float x){
    float y = 0.7978845608028654f*(x + 0.044715f*x*x*x);
    float yc = fminf(fmaxf(y, -15.f), 15.f);
    float t = __expf(2.f*yc);
    float th = (t - 1.f)/(t + 1.f);
    return 0.5f*x*(1.f + th);
}
__device__ __forceinline__ void split2(float x, bf16& h, bf16& l){
    h = __float2bfloat16(x);
    l = __float2bfloat16(x - __bfloat162float(h));
}
__device__ __forceinline__ uint32_t smem_u32(const void* p){
    uint32_t a;
    asm("{ .reg .u64 t; cvta.to.shared.u64 t, %1; cvt.u32.u64 %0, t; }" : "=r"(a) : "l"(p));
    return a;
}
__device__ __forceinline__ void cpasync16(uint32_t dst, const void* src){
    asm volatile("cp.async.cg.shared.global [%0], [%1], 16;" :: "r"(dst), "l"(src) : "memory");
}
__device__ __forceinline__ void ldsm4(uint32_t* r, uint32_t a){
    asm volatile("ldmatrix.sync.aligned.m8n8.x4.shared.b16 {%0,%1,%2,%3}, [%4];"
        : "=r"(r[0]),"=r"(r[1]),"=r"(r[2]),"=r"(r[3]) : "r"(a));
}
__device__ __forceinline__ void ldsm4t(uint32_t* r, uint32_t a){
    asm volatile("ldmatrix.sync.aligned.m8n8.x4.trans.shared.b16 {%0,%1,%2,%3}, [%4];"
        : "=r"(r[0]),"=r"(r[1]),"=r"(r[2]),"=r"(r[3]) : "r"(a));
}
__device__ __forceinline__ void mma16816(float* c, const uint32_t* a, const uint32_t* b){
    asm volatile("mma.sync.aligned.m16n8k16.row.col.f32.bf16.bf16.f32 "
        "{%0,%1,%2,%3}, {%4,%5,%6,%7}, {%8,%9}, {%0,%1,%2,%3};"
        : "+f"(c[0]),"+f"(c[1]),"+f"(c[2]),"+f"(c[3])
        : "r"(a[0]),"r"(a[1]),"r"(a[2]),"r"(a[3]), "r"(b[0]),"r"(b[1]));
}
__device__ __forceinline__ void mma16816h(float* c, const uint32_t* a, const uint32_t* b){
    asm volatile("mma.sync.aligned.m16n8k16.row.col.f32.f16.f16.f32 "
        "{%0,%1,%2,%3}, {%4,%5,%6,%7}, {%8,%9}, {%0,%1,%2,%3};"
        : "+f"(c[0]),"+f"(c[1]),"+f"(c[2]),"+f"(c[3])
        : "r"(a[0]),"r"(a[1]),"r"(a[2]),"r"(a[3]), "r"(b[0]),"r"(b[1]));
}
__device__ __forceinline__ uint32_t packbf(float lo, float hi){
    uint32_t r;
    asm("cvt.rn.bf16x2.f32 %0, %1, %2;" : "=r"(r) : "f"(hi), "f"(lo));
    return r;
}
__device__ __forceinline__ uint32_t packh(float lo, float hi){
    uint32_t r;
    asm("cvt.rn.f16x2.f32 %0, %1, %2;" : "=r"(r) : "f"(hi), "f"(lo));
    return r;
}
__device__ __forceinline__ void split_store2(float v0, float v1, bf16* ph, bf16* pl){
    float h0 = __bfloat162float(__float2bfloat16(v0));
    float h1 = __bfloat162float(__float2bfloat16(v1));
    *(uint32_t*)ph = packbf(v0, v1);
    *(uint32_t*)pl = packbf(v0 - h0, v1 - h1);
}

// ================= fused flash attention =================
// 3-stage pipeline, one sync per key-tile. S = bf16 QK (single term).
// PV = fp16 single term -> 32 MMAs/tile. Stage = {Kh, Vh}.
#define FLDS 72
#define FTILE (64*FLDS*2)          // 9216
#define FQT   (128*FLDS*2)         // 18432
#define FSTG  (2*FTILE)            // 18432
#define FSM   (FQT + 3*FSTG)       // 73728

__global__ __launch_bounds__(256, 2) void flash_kernel(){
    extern __shared__ __align__(128) char smem[];
    const uint32_t sb = smem_u32(smem);
    const int tid = threadIdx.x, lane = tid & 31, warp = tid >> 5;
    const int bh = blockIdx.y, b = bh >> 3, h = bh & 7;
    const int t0 = blockIdx.x * 128;
    const int r0 = lane >> 2, cq = lane & 3;
    const int aRow = lane & 15, aCol = (lane >> 4)*8;
    const int bQuad = lane >> 3, bRowQ = lane & 7;
    const int ntOff = bQuad >> 1, colQ = (bQuad & 1)*8;
    const int tKey = (bQuad & 1)*8 + bRowQ, tDim = (bQuad >> 1)*8;
    const uint32_t ST0 = sb + FQT;

    auto issueKV = [&](int kt, int st){
        int s0n = kt*64;
        uint32_t base = ST0 + st*FSTG;
        #pragma unroll
        for (int i = 0; i < 4; i++){
            int idx = tid + i*256;           // 0..1023
            int tile = idx >> 9, rem = idx & 511;
            int row = rem >> 3, ch = rem & 7;
            const void* src = tile
                ? (const void*)(g_Vh + ((size_t)bh*Tt + s0n + row)*64 + ch*8)
                : (const void*)(g_kh + ((size_t)bh*Tt + s0n + row)*64 + ch*8);
            cpasync16(base + tile*FTILE + (uint32_t)(row*FLDS + ch*8)*2, src);
        }
        asm volatile("cp.async.commit_group;" ::: "memory");
    };

    {   // group 0: Q + stage 0
        #pragma unroll
        for (int i = 0; i < 4; i++){
            int idx = tid + i*256;
            int row = idx >> 3, ch = idx & 7;
            cpasync16(sb + (uint32_t)(row*FLDS + ch*8)*2,
                      g_qh + ((size_t)bh*Tt + t0 + row)*64 + ch*8);
        }
        issueKV(0, 0);
        issueKV(1, 1);
    }

    float o[8][4] = {};
    float m0 = -INFINITY, m1 = -INFINITY, l0 = 0.f, l1 = 0.f;
    uint32_t qfh[4][4];

    int st = 0;
    for (int kt = 0; kt < 24; kt++){
        if (kt + 1 < 24) asm volatile("cp.async.wait_group 1;" ::: "memory");
        else             asm volatile("cp.async.wait_group 0;" ::: "memory");
        __syncthreads();
        if (kt + 2 < 24){
            int s2 = st + 2; if (s2 >= 3) s2 -= 3;
            issueKV(kt + 2, s2);
        }

        if (kt == 0){
            #pragma unroll
            for (int ks = 0; ks < 4; ks++){
                uint32_t ad = sb + (uint32_t)((warp*16 + aRow)*FLDS + ks*16 + aCol)*2;
                ldsm4(qfh[ks], ad);
            }
        }

        uint32_t KB = ST0 + st*FSTG;
        // ---- S = Qh Kh^T (bf16) ----
        float acc[8][4] = {};
        #pragma unroll
        for (int ks = 0; ks < 4; ks++){
            #pragma unroll
            for (int g = 0; g < 2; g++){
                uint32_t bfh[4][2];
                #pragma unroll
                for (int p = 0; p < 2; p++){
                    int ntb = g*4 + p*2;
                    uint32_t bd = KB + (uint32_t)(((ntb + ntOff)*8 + bRowQ)*FLDS + ks*16 + colQ)*2;
                    uint32_t r4[4];
                    ldsm4(r4, bd);
                    bfh[p*2][0]=r4[0]; bfh[p*2][1]=r4[1]; bfh[p*2+1][0]=r4[2]; bfh[p*2+1][1]=r4[3];
                }
                #pragma unroll
                for (int j = 0; j < 4; j++) mma16816(acc[g*4+j], qfh[ks], bfh[j]);
            }
        }

        // ---- online softmax ----
        float tm0 = -INFINITY, tm1 = -INFINITY;
        #pragma unroll
        for (int nt = 0; nt < 8; nt++){
            tm0 = fmaxf(tm0, fmaxf(acc[nt][0], acc[nt][1]));
            tm1 = fmaxf(tm1, fmaxf(acc[nt][2], acc[nt][3]));
        }
        tm0 = fmaxf(tm0, __shfl_xor_sync(~0u, tm0, 1));
        tm0 = fmaxf(tm0, __shfl_xor_sync(~0u, tm0, 2));
        tm1 = fmaxf(tm1, __shfl_xor_sync(~0u, tm1, 1));
        tm1 = fmaxf(tm1, __shfl_xor_sync(~0u, tm1, 2));
        float mn0 = fmaxf(m0, tm0), mn1 = fmaxf(m1, tm1);
        float al0 = __expf(m0 - mn0), al1 = __expf(m1 - mn1);
        float ps0 = 0.f, ps1 = 0.f;
        #pragma unroll
        for (int nt = 0; nt < 8; nt++){
            acc[nt][0] = __expf(acc[nt][0] - mn0);
            acc[nt][1] = __expf(acc[nt][1] - mn0);
            acc[nt][2] = __expf(acc[nt][2] - mn1);
            acc[nt][3] = __expf(acc[nt][3] - mn1);
            ps0 += acc[nt][0] + acc[nt][1];
            ps1 += acc[nt][2] + acc[nt][3];
        }
        ps0 += __shfl_xor_sync(~0u, ps0, 1); ps0 += __shfl_xor_sync(~0u, ps0, 2);
        ps1 += __shfl_xor_sync(~0u, ps1, 1); ps1 += __shfl_xor_sync(~0u, ps1, 2);
        l0 = l0*al0 + ps0; l1 = l1*al1 + ps1;
        m0 = mn0; m1 = mn1;
        // warp-uniform rescale guard: exact skip when all alphas are 1 (max unchanged)
        if (__any_sync(~0u, (al0 != 1.f) || (al1 != 1.f))){
            #pragma unroll
            for (int nt = 0; nt < 8; nt++){
                o[nt][0] *= al0; o[nt][1] *= al0; o[nt][2] *= al1; o[nt][3] *= al1;
            }
        }

        // ---- O += P V (fp16, single V term) ----
        uint32_t VB = KB + FTILE;
        #pragma unroll
        for (int kc = 0; kc < 4; kc++){
            uint32_t ap[4];
            ap[0] = packh(acc[2*kc][0],   acc[2*kc][1]);
            ap[1] = packh(acc[2*kc][2],   acc[2*kc][3]);
            ap[2] = packh(acc[2*kc+1][0], acc[2*kc+1][1]);
            ap[3] = packh(acc[2*kc+1][2], acc[2*kc+1][3]);
            #pragma unroll
            for (int g = 0; g < 2; g++){
                uint32_t bfh[4][2];
                #pragma unroll
                for (int p = 0; p < 2; p++){
                    int ntb = g*4 + p*2;
                    uint32_t bd = VB + (uint32_t)((kc*16 + tKey)*FLDS + ntb*8 + tDim)*2;
                    uint32_t r4[4];
                    ldsm4t(r4, bd);
                    bfh[p*2][0]=r4[0]; bfh[p*2][1]=r4[1]; bfh[p*2+1][0]=r4[2]; bfh[p*2+1][1]=r4[3];
                }
                #pragma unroll
                for (int j = 0; j < 4; j++) mma16816h(o[g*4+j], ap, bfh[j]);
            }
        }
        st++; if (st >= 3) st -= 3;
    }

    // ---- self-key fixup (fp32 exact; rows t >= TRAIN) ----
    if (t0 >= TRAIN){
        float mm[2] = {m0, m1}, ll[2] = {l0, l1};
        #pragma unroll
        for (int r = 0; r < 2; r++){
            int trow = t0 + warp*16 + r0 + 8*r;
            size_t qb = ((size_t)(b*Tt + trow))*1536 + h*64;
            float part = 0.f;
            #pragma unroll
            for (int d = 0; d < 16; d++)
                part += g_qkv[qb + cq*16 + d] * g_qkv[qb + 512 + cq*16 + d];
            part += __shfl_xor_sync(~0u, part, 1);
            part += __shfl_xor_sync(~0u, part, 2);
            float mn = fmaxf(mm[r], part);
            float al = __expf(mm[r] - mn);
            float p  = __expf(part - mn);
            ll[r] = ll[r]*al + p;
            const float* vs = g_qkv + qb + 1024;
            #pragma unroll
            for (int nt = 0; nt < 8; nt++){
                o[nt][2*r+0] = o[nt][2*r+0]*al + p*vs[nt*8 + 2*cq + 0];
                o[nt][2*r+1] = o[nt][2*r+1]*al + p*vs[nt*8 + 2*cq + 1];
            }
        }
        l0 = ll[0]; l1 = ll[1];
    }

    // ---- normalize + packed split write ----
    float inv[2] = {1.f/l0, 1.f/l1};
    #pragma unroll
    for (int r = 0; r < 2; r++){
        int trow = t0 + warp*16 + r0 + 8*r;
        size_t ob = ((size_t)(b*Tt + trow))*Dd + h*64;
        #pragma unroll
        for (int nt = 0; nt < 8; nt++){
            size_t off = ob + nt*8 + 2*cq;
            split_store2(o[nt][2*r]*inv[r], o[nt][2*r+1]*inv[r], g_ah + off, g_al + off);
        }
    }
}

// ---------------- split-bf16 HMMA GEMM (3-stage, XOR-swizzled 64B rows) ----------------
// EPI: 0 = fp32 C (+bias,+res), 1 = gelu -> split bf16, 2 = QKV rope scatter
#define BK 32
#define TILE_B (128*64)             // 8192 B
#define STAGE_B (4*TILE_B)          // 32768 B
#define GSM (3*STAGE_B)             // 98304 B

__global__ __launch_bounds__(256, 2) void mma_gemm(
    const bf16* __restrict__ Ah, const bf16* __restrict__ Al,
    const bf16* __restrict__ Bh, const bf16* __restrict__ Bl,
    const float* __restrict__ bias, const float* __restrict__ res,
    float* C, bf16* Chi, bf16* Clo,
    int K, int ldb, int Nreal, int ldC, size_t sA, size_t sB, size_t sC, int EPI)
{
    extern __shared__ __align__(128) char smem[];
    const uint32_t sb = smem_u32(smem);
    const int tid = threadIdx.x, lane = tid & 31, wid = tid >> 5;
    const int m0 = blockIdx.y*128, n0 = blockIdx.x*128;
    const size_t zb = blockIdx.z;
    const bf16* pAh = Ah + zb*sA + (size_t)m0*K;
    const bf16* pAl = Al + zb*sA + (size_t)m0*K;
    const bf16* pBh = Bh + zb*sB + (size_t)n0*ldb;
    const bf16* pBl = Bl + zb*sB + (size_t)n0*ldb;

    float acc[4][4][4] = {};
    const int nk = K/BK;

    auto issue = [&](int c, int s){
        uint32_t base = sb + s*STAGE_B;
        #pragma unroll
        for (int i = 0; i < 2; i++){
            int seg = tid + i*256;
            int row = seg >> 2, s4 = seg & 3;
            int phys = s4 ^ ((row >> 1) & 3);
            uint32_t doff = (uint32_t)(row*64 + phys*16);
            const size_t go = (size_t)row*K + c*BK + s4*8;
            const size_t gob = (size_t)row*ldb + c*BK + s4*8;
            cpasync16(base + 0*TILE_B + doff, pAh + go);
            cpasync16(base + 1*TILE_B + doff, pAl + go);
            cpasync16(base + 2*TILE_B + doff, pBh + gob);
            cpasync16(base + 3*TILE_B + doff, pBl + gob);
        }
        asm volatile("cp.async.commit_group;" ::: "memory");
    };

    issue(0, 0);
    if (nk > 1) issue(1, 1);
    const int wm = (wid>>2)*64, wn = (wid&3)*32;
    const int aRow = lane & 15, aChu = lane >> 4;
    const int bQuad = lane >> 3, bRowQ = lane & 7;
    const int ntOff = bQuad >> 1, bChu = bQuad & 1;

    int st = 0;
    for (int c = 0; c < nk; c++){
        if (c+1 < nk) asm volatile("cp.async.wait_group 1;" ::: "memory");
        else          asm volatile("cp.async.wait_group 0;" ::: "memory");
        __syncthreads();
        if (c+2 < nk){
            int s2 = st + 2; if (s2 >= 3) s2 -= 3;
            issue(c+2, s2);
        }
        uint32_t base = sb + st*STAGE_B;
        #pragma unroll
        for (int ks = 0; ks < 2; ks++){
            uint32_t a_h[4][4], a_l[4][4], b_h[4][2], b_l[4][2];
            #pragma unroll
            for (int mt = 0; mt < 4; mt++){
                int row = wm + mt*16 + aRow;
                int phys = (2*ks + aChu) ^ ((row >> 1) & 3);
                uint32_t ad = base + (uint32_t)(row*64 + phys*16);
                ldsm4(a_h[mt], ad);
                ldsm4(a_l[mt], ad + TILE_B);
            }
            #pragma unroll
            for (int p = 0; p < 2; p++){
                int row = wn + (p*2 + ntOff)*8 + bRowQ;
                int phys = (2*ks + bChu) ^ ((row >> 1) & 3);
                uint32_t bd = base + 2*TILE_B + (uint32_t)(row*64 + phys*16);
                uint32_t r4[4];
                ldsm4(r4, bd);
                b_h[p*2][0]=r4[0]; b_h[p*2][1]=r4[1]; b_h[p*2+1][0]=r4[2]; b_h[p*2+1][1]=r4[3];
                ldsm4(r4, bd + TILE_B);
                b_l[p*2][0]=r4[0]; b_l[p*2][1]=r4[1]; b_l[p*2+1][0]=r4[2]; b_l[p*2+1][1]=r4[3];
            }
            #pragma unroll
            for (int mt = 0; mt < 4; mt++)
                #pragma unroll
                for (int nt = 0; nt < 4; nt++){
                    mma16816(acc[mt][nt], a_h[mt], b_h[nt]);
                    mma16816(acc[mt][nt], a_h[mt], b_l[nt]);
                    mma16816(acc[mt][nt], a_l[mt], b_h[nt]);
                }
        }
        st++; if (st >= 3) st -= 3;
    }

    const int r0 = lane >> 2, cW = (lane & 3)*2;
    #pragma unroll
    for (int mt = 0; mt < 4; mt++)
    #pragma unroll
    for (int hh2 = 0; hh2 < 2; hh2++){
        int gm = m0 + wm + mt*16 + r0 + hh2*8;
        #pragma unroll
        for (int nt = 0; nt < 4; nt++){
            float v0 = acc[mt][nt][hh2*2+0], v1 = acc[mt][nt][hh2*2+1];
            int gn = n0 + wn + nt*8 + cW;
            if (bias){ v0 += __ldg(bias+gn); v1 += __ldg(bias+gn+1); }
            if (EPI == 2){
                int b = gm >> 11, t = gm & (Tt-1);
                if (gn < 1024){
                    int hq = (gn & 511) >> 6;
                    int i = (gn & 63) >> 1;
                    float cc = g_cos[t*32+i], ss = g_sin[t*32+i];
                    float r1 = v0*cc - v1*ss, r2 = v0*ss + v1*cc;
                    if (gn < 512){ r1 *= 0.125f; r2 *= 0.125f; }
                    size_t qo = ((size_t)(b*8+hq)*Tt + t)*64 + (gn & 63);
                    if (gn < 512) *(uint32_t*)(g_qh + qo) = packbf(r1, r2);
                    else          *(uint32_t*)(g_kh + qo) = packbf(r1, r2);
                    if (t >= TRAIN){
                        size_t fo = (size_t)gm*1536 + gn;
                        g_qkv[fo] = r1; g_qkv[fo+1] = r2;
                    }
                } else {
                    int h2 = (gn - 1024) >> 6, dd = (gn - 1024) & 63;
                    size_t vo = ((size_t)(b*8+h2)*Tt + t)*64 + dd;
                    *(uint32_t*)(g_Vh + vo) = packh(v0, v1);
                    if (t >= TRAIN){
                        size_t fo = (size_t)gm*1536 + gn;
                        g_qkv[fo] = v0; g_qkv[fo+1] = v1;
                    }
                }
            } else if (EPI == 1){
                size_t off = zb*sC + (size_t)gm*ldC + gn;
                split_store2(gelu_f(v0), gelu_f(v1), Chi + off, Clo + off);
            } else {
                size_t off = zb*sC + (size_t)gm*ldC + gn;
                if (res){ v0 += res[off]; v1 += res[off+1]; }
                if (gn+1 < Nreal){
                    *(float2*)(C + off) = make_float2(v0, v1);
                } else {
                    if (gn < Nreal) C[off] = v0;
                }
            }
        }
    }
}

// ---------------- weight transpose + split ----------------
__global__ void wsplit_kernel(const float* __restrict__ W, bf16* oh, bf16* ol,
                              int K, int N, int Npad){
    __shared__ float sm[32][33];
    int n0 = blockIdx.x*32, k0 = blockIdx.y*32, z = blockIdx.z;
    const float* Wb = W + (size_t)z*K*N;
    size_t ob = (size_t)z*Npad*K;
    int tx = threadIdx.x, ty = threadIdx.y;
    #pragma unroll
    for (int j = 0; j < 4; j++){
        int n = n0 + tx;
        sm[ty+8*j][tx] = (n < N) ? Wb[(size_t)(k0+ty+8*j)*N + n] : 0.f;
    }
    __syncthreads();
    #pragma unroll
    for (int j = 0; j < 4; j++){
        size_t o = ob + (size_t)(n0+ty+8*j)*K + k0 + tx;
        split2(sm[tx][ty+8*j], oh[o], ol[o]);
    }
}

// ---------------- misc kernels ----------------
__global__ void embed_kernel(const float* __restrict__ R, const int* __restrict__ y,
                             const float* __restrict__ emb){
    int row = blockIdx.x, t = row & (Tt-1), b = row >> 11;
    const float4* Rr = (const float4*)(R + (size_t)row*Dd);
    float4* Or = (float4*)(g_rep + (size_t)row*Dd);
    if (t < TRAIN){
        int yv = y[b*TRAIN + t];
        const float4* E = (const float4*)(emb + (size_t)yv*Dd);
        for (int i = threadIdx.x; i < Dd/4; i += blockDim.x){
            float4 a = Rr[i]; float4 e = E[i];
            a.x += e.x; a.y += e.y; a.z += e.z; a.w += e.w;
            Or[i] = a;
        }
    } else {
        for (int i = threadIdx.x; i < Dd/4; i += blockDim.x) Or[i] = Rr[i];
    }
}

__global__ void ln_kernel(const float* __restrict__ g, const float* __restrict__ be){
    __shared__ float sh[Dd];
    __shared__ float red[4];
    int row = blockIdx.x;
    const float* xr = g_rep + (size_t)row*Dd;
    float s = 0.f;
    for (int i = threadIdx.x; i < Dd; i += 128){ float v = xr[i]; sh[i] = v; s += v; }
    #pragma unroll
    for (int o = 16; o; o >>= 1) s += __shfl_xor_sync(~0u, s, o);
    if ((threadIdx.x & 31) == 0) red[threadIdx.x >> 5] = s;
    __syncthreads();
    float mu = (red[0]+red[1]+red[2]+red[3]) * (1.f/Dd);
    float vs = 0.f;
    for (int i = threadIdx.x; i < Dd; i += 128){ float d = sh[i]-mu; vs += d*d; }
    #pragma unroll
    for (int o = 16; o; o >>= 1) vs += __shfl_xor_sync(~0u, vs, o);
    __syncthreads();
    if ((threadIdx.x & 31) == 0) red[threadIdx.x >> 5] = vs;
    __syncthreads();
    float rs = rsqrtf((red[0]+red[1]+red[2]+red[3])*(1.f/Dd) + 1e-5f);
    // packed pair stores
    for (int i = threadIdx.x*2; i < Dd; i += 256){
        size_t o = (size_t)row*Dd + i;
        float a0 = (sh[i]-mu)*rs*g[i] + be[i];
        float a1 = (sh[i+1]-mu)*rs*g[i+1] + be[i+1];
        split_store2(a0, a1, g_hh + o, g_hl + o);
    }
}

__global__ void rope_table_kernel(){
    int t = blockIdx.x, i = threadIdx.x;
    float inv = (float)pow(100000.0, -((double)(2*i))/64.0);
    float ang = (float)t * inv;
    g_cos[t*32+i] = cosf(ang);
    g_sin[t*32+i] = sinf(ang);
}

__global__ void extract_kernel(){
    int r = blockIdx.x, b = r >> 9, i = r & 511;
    const float* src = g_rep + (size_t)(b*Tt + TRAIN + i)*Dd;
    for (int j = threadIdx.x*2; j < Dd; j += 256){
        split_store2(src[j], src[j+1], g_th + (size_t)r*Dd + j, g_tl + (size_t)r*Dd + j);
    }
}

// ---------------- launcher ----------------
#define SYM(p, s) cudaGetSymbolAddress((void**)&p, s)

extern "C" void kernel_launch(void* const* d_in, const int* in_sizes, int n_in,
                              void* d_out, int out_size){
    const float* R    = (const float*)d_in[0];
    const int*   y    = (const int*)  d_in[1];
    const float* emb  = (const float*)d_in[2];
    const float* Wqkv = (const float*)d_in[3];
    const float* bqkv = (const float*)d_in[4];
    const float* Wo   = (const float*)d_in[5];
    const float* bo   = (const float*)d_in[6];
    const float* ln1g = (const float*)d_in[7];
    const float* ln1b = (const float*)d_in[8];
    const float* ln2g = (const float*)d_in[9];
    const float* ln2b = (const float*)d_in[10];
    const float* W1   = (const float*)d_in[11];
    const float* b1   = (const float*)d_in[12];
    const float* W2   = (const float*)d_in[13];
    const float* b2   = (const float*)d_in[14];
    const float* pW1  = (const float*)d_in[15];
    const float* pb1  = (const float*)d_in[16];
    const float* pW2  = (const float*)d_in[17];
    const float* pb2  = (const float*)d_in[18];

    cudaFuncSetAttribute(mma_gemm, cudaFuncAttributeMaxDynamicSharedMemorySize, GSM);
    cudaFuncSetAttribute(flash_kernel, cudaFuncAttributeMaxDynamicSharedMemorySize, FSM);

    float *qkv, *rep;
    bf16 *hh,*hl,*ah,*al,*fh,*fl,*th,*tl,*gh,*gl;
    bf16 *Wqkvh,*Wqkvl,*Woh,*Wol,*W1h,*W1l,*W2h,*W2l,*pW1h,*pW1l,*pW2h,*pW2l;
    SYM(qkv,g_qkv); SYM(rep,g_rep);
    SYM(hh,g_hh); SYM(hl,g_hl); SYM(ah,g_ah); SYM(al,g_al);
    SYM(fh,g_fh); SYM(fl,g_fl);
    SYM(th,g_th); SYM(tl,g_tl);
    SYM(gh,g_gh); SYM(gl,g_gl);
    SYM(Wqkvh,g_Wqkvh); SYM(Wqkvl,g_Wqkvl); SYM(Woh,g_Woh); SYM(Wol,g_Wol);
    SYM(W1h,g_W1h); SYM(W1l,g_W1l); SYM(W2h,g_W2h); SYM(W2l,g_W2l);
    SYM(pW1h,g_pW1h); SYM(pW1l,g_pW1l); SYM(pW2h,g_pW2h); SYM(pW2l,g_pW2l);

    dim3 wb(32, 8);
    wsplit_kernel<<<dim3(48,16,12), wb>>>(Wqkv, Wqkvh, Wqkvl, 512, 1536, 1536);
    rope_table_kernel<<<Tt, 32>>>();
    embed_kernel<<<BT, 128>>>(R, y, emb);
    wsplit_kernel<<<dim3(16,16,12), wb>>>(Wo, Woh, Wol, 512, 512, 512);

    for (int l = 0; l < Ll; l++){
        ln_kernel<<<BT, 128>>>(ln1g + l*Dd, ln1b + l*Dd);
        mma_gemm<<<dim3(12,64,1),256,GSM>>>(hh, hl, Wqkvh + (size_t)l*1536*512, Wqkvl + (size_t)l*1536*512,
            bqkv + l*1536, nullptr, nullptr, nullptr, nullptr, 512, 512, 1536, 1536, 0,0,0, 2);
        if (l == 0){
            wsplit_kernel<<<dim3(64,16,12), wb>>>(W1, W1h, W1l, 512, 2048, 2048);
            wsplit_kernel<<<dim3(16,64,12), wb>>>(W2, W2h, W2l, 2048, 512, 512);
            wsplit_kernel<<<dim3(32,16,1),  wb>>>(pW1, pW1h, pW1l, 512, 1024, 1024);
            wsplit_kernel<<<dim3(4, 32,1),  wb>>>(pW2, pW2h, pW2l, 1024, 100, 128);
        }
        flash_kernel<<<dim3(16, NBH), 256, FSM>>>();
        mma_gemm<<<dim3(4,64,1),256,GSM>>>(ah, al, Woh + (size_t)l*512*512, Wol + (size_t)l*512*512,
            bo + l*512, rep, rep, nullptr, nullptr, 512, 512, 512, 512, 0,0,0, 0);
        ln_kernel<<<BT, 128>>>(ln2g + l*Dd, ln2b + l*Dd);
        mma_gemm<<<dim3(16,64,1),256,GSM>>>(hh, hl, W1h + (size_t)l*2048*512, W1l + (size_t)l*2048*512,
            b1 + l*2048, nullptr, nullptr, fh, fl, 512, 512, 2048, 2048, 0,0,0, 1);
        mma_gemm<<<dim3(4,64,1),256,GSM>>>(fh, fl, W2h + (size_t)l*512*2048, W2l + (size_t)l*512*2048,
            b2 + l*512, rep, rep, nullptr, nullptr, 2048, 2048, 512, 512, 0,0,0, 0);
    }

    extract_kernel<<<MTEST, 128>>>();
    mma_gemm<<<dim3(8,16,1),256,GSM>>>(th, tl, pW1h, pW1l, pb1, nullptr,
        nullptr, gh, gl, 512, 512, 1024, 1024, 0,0,0, 1);
    mma_gemm<<<dim3(1,16,1),256,GSM>>>(gh, gl, pW2h, pW2l, pb2, nullptr,
        (float*)d_out, nullptr, nullptr, 1024, 1024, 100, 100, 0,0,0, 0);
}

// round 14
// speedup vs baseline: 1.7704x; 1.0117x over previous
#include <cuda_runtime.h>
#include <cuda_bf16.h>
#include <cuda_fp16.h>
#include <math.h>
#include <stdint.h>

#define Bc    4
#define Tt    2048
#define TRAIN 1536
#define Dd    512
#define Ll    12
#define FFd   2048
#define BT    (Bc*Tt)
#define NBH   32
#define MTEST 2048

typedef __nv_bfloat16 bf16;

// ---------------- static buffers ----------------
__device__ float g_rep [BT*Dd];
__device__ float g_qkv [BT*3*Dd];          // fp32 qkv, written only for t>=TRAIN (fixup)
__device__ bf16  g_hh[BT*Dd], g_hl[BT*Dd];
__device__ bf16  g_ah[BT*Dd], g_al[BT*Dd];
__device__ bf16  g_fh[BT*FFd], g_fl[BT*FFd];
__device__ bf16  g_qh[NBH*Tt*64];
__device__ bf16  g_kh[NBH*Tt*64];
__device__ __half g_Vh[NBH*Tt*64];         // V stored fp16 (single term)
__device__ bf16  g_th[MTEST*Dd], g_tl[MTEST*Dd];
__device__ bf16  g_gh[MTEST*2*Dd], g_gl[MTEST*2*Dd];
__device__ bf16  g_Wqkvh[Ll*3*Dd*Dd], g_Wqkvl[Ll*3*Dd*Dd];
__device__ bf16  g_Woh[Ll*Dd*Dd],  g_Wol[Ll*Dd*Dd];
__device__ bf16  g_W1h[Ll*FFd*Dd], g_W1l[Ll*FFd*Dd];
__device__ bf16  g_W2h[Ll*Dd*FFd], g_W2l[Ll*Dd*FFd];
__device__ bf16  g_pW1h[2*Dd*Dd],  g_pW1l[2*Dd*Dd];
__device__ bf16  g_pW2h[128*2*Dd], g_pW2l[128*2*Dd];
__device__ float g_cos[Tt*32], g_sin[Tt*32];

// ---------------- helpers ----------------
__device__ __forceinline__ float gelu_f(float x){
    float y = 0.7978845608028654f*(x + 0.044715f*x*x*x);
    float yc = fminf(fmaxf(y, -15.f), 15.f);
    float t = __expf(2.f*yc);
    float th = (t - 1.f)/(t + 1.f);
    return 0.5f*x*(1.f + th);
}
__device__ __forceinline__ void split2(float x, bf16& h, bf16& l){
    h = __float2bfloat16(x);
    l = __float2bfloat16(x - __bfloat162float(h));
}
__device__ __forceinline__ uint32_t smem_u32(const void* p){
    uint32_t a;
    asm("{ .reg .u64 t; cvta.to.shared.u64 t, %1; cvt.u32.u64 %0, t; }" : "=r"(a) : "l"(p));
    return a;
}
__device__ __forceinline__ void cpasync16(uint32_t dst, const void* src){
    asm volatile("cp.async.cg.shared.global [%0], [%1], 16;" :: "r"(dst), "l"(src) : "memory");
}
__device__ __forceinline__ void ldsm4(uint32_t* r, uint32_t a){
    asm volatile("ldmatrix.sync.aligned.m8n8.x4.shared.b16 {%0,%1,%2,%3}, [%4];"
        : "=r"(r[0]),"=r"(r[1]),"=r"(r[2]),"=r"(r[3]) : "r"(a));
}
__device__ __forceinline__ void ldsm4t(uint32_t* r, uint32_t a){
    asm volatile("ldmatrix.sync.aligned.m8n8.x4.trans.shared.b16 {%0,%1,%2,%3}, [%4];"
        : "=r"(r[0]),"=r"(r[1]),"=r"(r[2]),"=r"(r[3]) : "r"(a));
}
__device__ __forceinline__ void mma16816(float* c, const uint32_t* a, const uint32_t* b){
    asm volatile("mma.sync.aligned.m16n8k16.row.col.f32.bf16.bf16.f32 "
        "{%0,%1,%2,%3}, {%4,%5,%6,%7}, {%8,%9}, {%0,%1,%2,%3};"
        : "+f"(c[0]),"+f"(c[1]),"+f"(c[2]),"+f"(c[3])
        : "r"(a[0]),"r"(a[1]),"r"(a[2]),"r"(a[3]), "r"(b[0]),"r"(b[1]));
}
__device__ __forceinline__ void mma16816h(float* c, const uint32_t* a, const uint32_t* b){
    asm volatile("mma.sync.aligned.m16n8k16.row.col.f32.f16.f16.f32 "
        "{%0,%1,%2,%3}, {%4,%5,%6,%7}, {%8,%9}, {%0,%1,%2,%3};"
        : "+f"(c[0]),"+f"(c[1]),"+f"(c[2]),"+f"(c[3])
        : "r"(a[0]),"r"(a[1]),"r"(a[2]),"r"(a[3]), "r"(b[0]),"r"(b[1]));
}
__device__ __forceinline__ uint32_t packbf(float lo, float hi){
    uint32_t r;
    asm("cvt.rn.bf16x2.f32 %0, %1, %2;" : "=r"(r) : "f"(hi), "f"(lo));
    return r;
}
__device__ __forceinline__ uint32_t packh(float lo, float hi){
    uint32_t r;
    asm("cvt.rn.f16x2.f32 %0, %1, %2;" : "=r"(r) : "f"(hi), "f"(lo));
    return r;
}
__device__ __forceinline__ void split_store2(float v0, float v1, bf16* ph, bf16* pl){
    float h0 = __bfloat162float(__float2bfloat16(v0));
    float h1 = __bfloat162float(__float2bfloat16(v1));
    *(uint32_t*)ph = packbf(v0, v1);
    *(uint32_t*)pl = packbf(v0 - h0, v1 - h1);
}

// ================= fused flash attention (unchanged from R13) =================
#define FLDS 72
#define FTILE (64*FLDS*2)          // 9216
#define FQT   (128*FLDS*2)         // 18432
#define FSTG  (2*FTILE)            // 18432
#define FSM   (FQT + 3*FSTG)       // 73728

__global__ __launch_bounds__(256, 2) void flash_kernel(){
    extern __shared__ __align__(128) char smem[];
    const uint32_t sb = smem_u32(smem);
    const int tid = threadIdx.x, lane = tid & 31, warp = tid >> 5;
    const int bh = blockIdx.y, b = bh >> 3, h = bh & 7;
    const int t0 = blockIdx.x * 128;
    const int r0 = lane >> 2, cq = lane & 3;
    const int aRow = lane & 15, aCol = (lane >> 4)*8;
    const int bQuad = lane >> 3, bRowQ = lane & 7;
    const int ntOff = bQuad >> 1, colQ = (bQuad & 1)*8;
    const int tKey = (bQuad & 1)*8 + bRowQ, tDim = (bQuad >> 1)*8;
    const uint32_t ST0 = sb + FQT;

    auto issueKV = [&](int kt, int st){
        int s0n = kt*64;
        uint32_t base = ST0 + st*FSTG;
        #pragma unroll
        for (int i = 0; i < 4; i++){
            int idx = tid + i*256;
            int tile = idx >> 9, rem = idx & 511;
            int row = rem >> 3, ch = rem & 7;
            const void* src = tile
                ? (const void*)(g_Vh + ((size_t)bh*Tt + s0n + row)*64 + ch*8)
                : (const void*)(g_kh + ((size_t)bh*Tt + s0n + row)*64 + ch*8);
            cpasync16(base + tile*FTILE + (uint32_t)(row*FLDS + ch*8)*2, src);
        }
        asm volatile("cp.async.commit_group;" ::: "memory");
    };

    {
        #pragma unroll
        for (int i = 0; i < 4; i++){
            int idx = tid + i*256;
            int row = idx >> 3, ch = idx & 7;
            cpasync16(sb + (uint32_t)(row*FLDS + ch*8)*2,
                      g_qh + ((size_t)bh*Tt + t0 + row)*64 + ch*8);
        }
        issueKV(0, 0);
        issueKV(1, 1);
    }

    float o[8][4] = {};
    float m0 = -INFINITY, m1 = -INFINITY, l0 = 0.f, l1 = 0.f;
    uint32_t qfh[4][4];

    int st = 0;
    for (int kt = 0; kt < 24; kt++){
        if (kt + 1 < 24) asm volatile("cp.async.wait_group 1;" ::: "memory");
        else             asm volatile("cp.async.wait_group 0;" ::: "memory");
        __syncthreads();
        if (kt + 2 < 24){
            int s2 = st + 2; if (s2 >= 3) s2 -= 3;
            issueKV(kt + 2, s2);
        }

        if (kt == 0){
            #pragma unroll
            for (int ks = 0; ks < 4; ks++){
                uint32_t ad = sb + (uint32_t)((warp*16 + aRow)*FLDS + ks*16 + aCol)*2;
                ldsm4(qfh[ks], ad);
            }
        }

        uint32_t KB = ST0 + st*FSTG;
        float acc[8][4] = {};
        #pragma unroll
        for (int ks = 0; ks < 4; ks++){
            #pragma unroll
            for (int g = 0; g < 2; g++){
                uint32_t bfh[4][2];
                #pragma unroll
                for (int p = 0; p < 2; p++){
                    int ntb = g*4 + p*2;
                    uint32_t bd = KB + (uint32_t)(((ntb + ntOff)*8 + bRowQ)*FLDS + ks*16 + colQ)*2;
                    uint32_t r4[4];
                    ldsm4(r4, bd);
                    bfh[p*2][0]=r4[0]; bfh[p*2][1]=r4[1]; bfh[p*2+1][0]=r4[2]; bfh[p*2+1][1]=r4[3];
                }
                #pragma unroll
                for (int j = 0; j < 4; j++) mma16816(acc[g*4+j], qfh[ks], bfh[j]);
            }
        }

        float tm0 = -INFINITY, tm1 = -INFINITY;
        #pragma unroll
        for (int nt = 0; nt < 8; nt++){
            tm0 = fmaxf(tm0, fmaxf(acc[nt][0], acc[nt][1]));
            tm1 = fmaxf(tm1, fmaxf(acc[nt][2], acc[nt][3]));
        }
        tm0 = fmaxf(tm0, __shfl_xor_sync(~0u, tm0, 1));
        tm0 = fmaxf(tm0, __shfl_xor_sync(~0u, tm0, 2));
        tm1 = fmaxf(tm1, __shfl_xor_sync(~0u, tm1, 1));
        tm1 = fmaxf(tm1, __shfl_xor_sync(~0u, tm1, 2));
        float mn0 = fmaxf(m0, tm0), mn1 = fmaxf(m1, tm1);
        float al0 = __expf(m0 - mn0), al1 = __expf(m1 - mn1);
        float ps0 = 0.f, ps1 = 0.f;
        #pragma unroll
        for (int nt = 0; nt < 8; nt++){
            acc[nt][0] = __expf(acc[nt][0] - mn0);
            acc[nt][1] = __expf(acc[nt][1] - mn0);
            acc[nt][2] = __expf(acc[nt][2] - mn1);
            acc[nt][3] = __expf(acc[nt][3] - mn1);
            ps0 += acc[nt][0] + acc[nt][1];
            ps1 += acc[nt][2] + acc[nt][3];
        }
        ps0 += __shfl_xor_sync(~0u, ps0, 1); ps0 += __shfl_xor_sync(~0u, ps0, 2);
        ps1 += __shfl_xor_sync(~0u, ps1, 1); ps1 += __shfl_xor_sync(~0u, ps1, 2);
        l0 = l0*al0 + ps0; l1 = l1*al1 + ps1;
        m0 = mn0; m1 = mn1;
        if (__any_sync(~0u, (al0 != 1.f) || (al1 != 1.f))){
            #pragma unroll
            for (int nt = 0; nt < 8; nt++){
                o[nt][0] *= al0; o[nt][1] *= al0; o[nt][2] *= al1; o[nt][3] *= al1;
            }
        }

        uint32_t VB = KB + FTILE;
        #pragma unroll
        for (int kc = 0; kc < 4; kc++){
            uint32_t ap[4];
            ap[0] = packh(acc[2*kc][0],   acc[2*kc][1]);
            ap[1] = packh(acc[2*kc][2],   acc[2*kc][3]);
            ap[2] = packh(acc[2*kc+1][0], acc[2*kc+1][1]);
            ap[3] = packh(acc[2*kc+1][2], acc[2*kc+1][3]);
            #pragma unroll
            for (int g = 0; g < 2; g++){
                uint32_t bfh[4][2];
                #pragma unroll
                for (int p = 0; p < 2; p++){
                    int ntb = g*4 + p*2;
                    uint32_t bd = VB + (uint32_t)((kc*16 + tKey)*FLDS + ntb*8 + tDim)*2;
                    uint32_t r4[4];
                    ldsm4t(r4, bd);
                    bfh[p*2][0]=r4[0]; bfh[p*2][1]=r4[1]; bfh[p*2+1][0]=r4[2]; bfh[p*2+1][1]=r4[3];
                }
                #pragma unroll
                for (int j = 0; j < 4; j++) mma16816h(o[g*4+j], ap, bfh[j]);
            }
        }
        st++; if (st >= 3) st -= 3;
    }

    if (t0 >= TRAIN){
        float mm[2] = {m0, m1}, ll[2] = {l0, l1};
        #pragma unroll
        for (int r = 0; r < 2; r++){
            int trow = t0 + warp*16 + r0 + 8*r;
            size_t qb = ((size_t)(b*Tt + trow))*1536 + h*64;
            float part = 0.f;
            #pragma unroll
            for (int d = 0; d < 16; d++)
                part += g_qkv[qb + cq*16 + d] * g_qkv[qb + 512 + cq*16 + d];
            part += __shfl_xor_sync(~0u, part, 1);
            part += __shfl_xor_sync(~0u, part, 2);
            float mn = fmaxf(mm[r], part);
            float al = __expf(mm[r] - mn);
            float p  = __expf(part - mn);
            ll[r] = ll[r]*al + p;
            const float* vs = g_qkv + qb + 1024;
            #pragma unroll
            for (int nt = 0; nt < 8; nt++){
                o[nt][2*r+0] = o[nt][2*r+0]*al + p*vs[nt*8 + 2*cq + 0];
                o[nt][2*r+1] = o[nt][2*r+1]*al + p*vs[nt*8 + 2*cq + 1];
            }
        }
        l0 = ll[0]; l1 = ll[1];
    }

    float inv[2] = {1.f/l0, 1.f/l1};
    #pragma unroll
    for (int r = 0; r < 2; r++){
        int trow = t0 + warp*16 + r0 + 8*r;
        size_t ob = ((size_t)(b*Tt + trow))*Dd + h*64;
        #pragma unroll
        for (int nt = 0; nt < 8; nt++){
            size_t off = ob + nt*8 + 2*cq;
            split_store2(o[nt][2*r]*inv[r], o[nt][2*r+1]*inv[r], g_ah + off, g_al + off);
        }
    }
}

// ---------------- split-bf16 HMMA GEMM (3-stage, XOR-swizzled, variable TERMS) ----------------
// EPI: 0 = fp32 C (+bias,+res), 1 = gelu -> split bf16, 2 = QKV rope scatter
#define BK 32
#define TILE_B (128*64)             // 8192 B
#define STAGE_B (4*TILE_B)          // 32768 B
#define GSM (3*STAGE_B)             // 98304 B

__global__ __launch_bounds__(256, 2) void mma_gemm(
    const bf16* __restrict__ Ah, const bf16* __restrict__ Al,
    const bf16* __restrict__ Bh, const bf16* __restrict__ Bl,
    const float* __restrict__ bias, const float* __restrict__ res,
    float* C, bf16* Chi, bf16* Clo,
    int K, int ldb, int Nreal, int ldC, size_t sA, size_t sB, size_t sC, int EPI, int TERMS)
{
    extern __shared__ __align__(128) char smem[];
    const uint32_t sb = smem_u32(smem);
    const int tid = threadIdx.x, lane = tid & 31, wid = tid >> 5;
    const int m0 = blockIdx.y*128, n0 = blockIdx.x*128;
    const size_t zb = blockIdx.z;
    const bf16* pAh = Ah + zb*sA + (size_t)m0*K;
    const bf16* pAl = Al + zb*sA + (size_t)m0*K;
    const bf16* pBh = Bh + zb*sB + (size_t)n0*ldb;
    const bf16* pBl = Bl + zb*sB + (size_t)n0*ldb;

    float acc[4][4][4] = {};
    const int nk = K/BK;

    auto issue = [&](int c, int s){
        uint32_t base = sb + s*STAGE_B;
        #pragma unroll
        for (int i = 0; i < 2; i++){
            int seg = tid + i*256;
            int row = seg >> 2, s4 = seg & 3;
            int phys = s4 ^ ((row >> 1) & 3);
            uint32_t doff = (uint32_t)(row*64 + phys*16);
            const size_t go = (size_t)row*K + c*BK + s4*8;
            const size_t gob = (size_t)row*ldb + c*BK + s4*8;
            cpasync16(base + 0*TILE_B + doff, pAh + go);
            cpasync16(base + 1*TILE_B + doff, pAl + go);
            cpasync16(base + 2*TILE_B + doff, pBh + gob);
            cpasync16(base + 3*TILE_B + doff, pBl + gob);
        }
        asm volatile("cp.async.commit_group;" ::: "memory");
    };

    issue(0, 0);
    if (nk > 1) issue(1, 1);
    const int wm = (wid>>2)*64, wn = (wid&3)*32;
    const int aRow = lane & 15, aChu = lane >> 4;
    const int bQuad = lane >> 3, bRowQ = lane & 7;
    const int ntOff = bQuad >> 1, bChu = bQuad & 1;

    int st = 0;
    for (int c = 0; c < nk; c++){
        if (c+1 < nk) asm volatile("cp.async.wait_group 1;" ::: "memory");
        else          asm volatile("cp.async.wait_group 0;" ::: "memory");
        __syncthreads();
        if (c+2 < nk){
            int s2 = st + 2; if (s2 >= 3) s2 -= 3;
            issue(c+2, s2);
        }
        uint32_t base = sb + st*STAGE_B;
        #pragma unroll
        for (int ks = 0; ks < 2; ks++){
            uint32_t a_h[4][4], a_l[4][4], b_h[4][2], b_l[4][2];
            #pragma unroll
            for (int mt = 0; mt < 4; mt++){
                int row = wm + mt*16 + aRow;
                int phys = (2*ks + aChu) ^ ((row >> 1) & 3);
                uint32_t ad = base + (uint32_t)(row*64 + phys*16);
                ldsm4(a_h[mt], ad);
                if (TERMS == 3) ldsm4(a_l[mt], ad + TILE_B);
            }
            #pragma unroll
            for (int p = 0; p < 2; p++){
                int row = wn + (p*2 + ntOff)*8 + bRowQ;
                int phys = (2*ks + bChu) ^ ((row >> 1) & 3);
                uint32_t bd = base + 2*TILE_B + (uint32_t)(row*64 + phys*16);
                uint32_t r4[4];
                ldsm4(r4, bd);
                b_h[p*2][0]=r4[0]; b_h[p*2][1]=r4[1]; b_h[p*2+1][0]=r4[2]; b_h[p*2+1][1]=r4[3];
                ldsm4(r4, bd + TILE_B);
                b_l[p*2][0]=r4[0]; b_l[p*2][1]=r4[1]; b_l[p*2+1][0]=r4[2]; b_l[p*2+1][1]=r4[3];
            }
            #pragma unroll
            for (int mt = 0; mt < 4; mt++)
                #pragma unroll
                for (int nt = 0; nt < 4; nt++){
                    mma16816(acc[mt][nt], a_h[mt], b_h[nt]);
                    mma16816(acc[mt][nt], a_h[mt], b_l[nt]);
                    if (TERMS == 3) mma16816(acc[mt][nt], a_l[mt], b_h[nt]);
                }
        }
        st++; if (st >= 3) st -= 3;
    }

    const int r0 = lane >> 2, cW = (lane & 3)*2;
    #pragma unroll
    for (int mt = 0; mt < 4; mt++)
    #pragma unroll
    for (int hh2 = 0; hh2 < 2; hh2++){
        int gm = m0 + wm + mt*16 + r0 + hh2*8;
        #pragma unroll
        for (int nt = 0; nt < 4; nt++){
            float v0 = acc[mt][nt][hh2*2+0], v1 = acc[mt][nt][hh2*2+1];
            int gn = n0 + wn + nt*8 + cW;
            if (bias){ v0 += __ldg(bias+gn); v1 += __ldg(bias+gn+1); }
            if (EPI == 2){
                int b = gm >> 11, t = gm & (Tt-1);
                if (gn < 1024){
                    int hq = (gn & 511) >> 6;
                    int i = (gn & 63) >> 1;
                    float cc = g_cos[t*32+i], ss = g_sin[t*32+i];
                    float r1 = v0*cc - v1*ss, r2 = v0*ss + v1*cc;
                    if (gn < 512){ r1 *= 0.125f; r2 *= 0.125f; }
                    size_t qo = ((size_t)(b*8+hq)*Tt + t)*64 + (gn & 63);
                    if (gn < 512) *(uint32_t*)(g_qh + qo) = packbf(r1, r2);
                    else          *(uint32_t*)(g_kh + qo) = packbf(r1, r2);
                    if (t >= TRAIN){
                        size_t fo = (size_t)gm*1536 + gn;
                        g_qkv[fo] = r1; g_qkv[fo+1] = r2;
                    }
                } else {
                    int h2 = (gn - 1024) >> 6, dd = (gn - 1024) & 63;
                    size_t vo = ((size_t)(b*8+h2)*Tt + t)*64 + dd;
                    *(uint32_t*)(g_Vh + vo) = packh(v0, v1);
                    if (t >= TRAIN){
                        size_t fo = (size_t)gm*1536 + gn;
                        g_qkv[fo] = v0; g_qkv[fo+1] = v1;
                    }
                }
            } else if (EPI == 1){
                size_t off = zb*sC + (size_t)gm*ldC + gn;
                split_store2(gelu_f(v0), gelu_f(v1), Chi + off, Clo + off);
            } else {
                size_t off = zb*sC + (size_t)gm*ldC + gn;
                if (res){ v0 += res[off]; v1 += res[off+1]; }
                if (gn+1 < Nreal){
                    *(float2*)(C + off) = make_float2(v0, v1);
                } else {
                    if (gn < Nreal) C[off] = v0;
                }
            }
        }
    }
}

// ---------------- weight transpose + split ----------------
__global__ void wsplit_kernel(const float* __restrict__ W, bf16* oh, bf16* ol,
                              int K, int N, int Npad){
    __shared__ float sm[32][33];
    int n0 = blockIdx.x*32, k0 = blockIdx.y*32, z = blockIdx.z;
    const float* Wb = W + (size_t)z*K*N;
    size_t ob = (size_t)z*Npad*K;
    int tx = threadIdx.x, ty = threadIdx.y;
    #pragma unroll
    for (int j = 0; j < 4; j++){
        int n = n0 + tx;
        sm[ty+8*j][tx] = (n < N) ? Wb[(size_t)(k0+ty+8*j)*N + n] : 0.f;
    }
    __syncthreads();
    #pragma unroll
    for (int j = 0; j < 4; j++){
        size_t o = ob + (size_t)(n0+ty+8*j)*K + k0 + tx;
        split2(sm[tx][ty+8*j], oh[o], ol[o]);
    }
}

// ---------------- misc kernels ----------------
__global__ void embed_kernel(const float* __restrict__ R, const int* __restrict__ y,
                             const float* __restrict__ emb){
    int row = blockIdx.x, t = row & (Tt-1), b = row >> 11;
    const float4* Rr = (const float4*)(R + (size_t)row*Dd);
    float4* Or = (float4*)(g_rep + (size_t)row*Dd);
    if (t < TRAIN){
        int yv = y[b*TRAIN + t];
        const float4* E = (const float4*)(emb + (size_t)yv*Dd);
        for (int i = threadIdx.x; i < Dd/4; i += blockDim.x){
            float4 a = Rr[i]; float4 e = E[i];
            a.x += e.x; a.y += e.y; a.z += e.z; a.w += e.w;
            Or[i] = a;
        }
    } else {
        for (int i = threadIdx.x; i < Dd/4; i += blockDim.x) Or[i] = Rr[i];
    }
}

// warp-per-row LN: 8 rows/block, pure shfl reductions, coalesced float4 loads
__global__ __launch_bounds__(256) void ln_kernel(const float* __restrict__ g,
                                                 const float* __restrict__ be){
    int row = blockIdx.x*8 + (threadIdx.x >> 5);
    int lane = threadIdx.x & 31;
    const float4* xr = (const float4*)(g_rep + (size_t)row*Dd);
    float4 v[4];
    float s = 0.f;
    #pragma unroll
    for (int j = 0; j < 4; j++){
        v[j] = xr[lane + 32*j];
        s += v[j].x + v[j].y + v[j].z + v[j].w;
    }
    #pragma unroll
    for (int o = 16; o; o >>= 1) s += __shfl_xor_sync(~0u, s, o);
    float mu = s * (1.f/Dd);
    float vs = 0.f;
    #pragma unroll
    for (int j = 0; j < 4; j++){
        float a = v[j].x-mu, b2 = v[j].y-mu, c = v[j].z-mu, d = v[j].w-mu;
        vs += a*a + b2*b2 + c*c + d*d;
    }
    #pragma unroll
    for (int o = 16; o; o >>= 1) vs += __shfl_xor_sync(~0u, vs, o);
    float rs = rsqrtf(vs*(1.f/Dd) + 1e-5f);
    #pragma unroll
    for (int j = 0; j < 4; j++){
        int i = lane*4 + 128*j;
        float4 gv = *(const float4*)(g + i);
        float4 bv = *(const float4*)(be + i);
        size_t o = (size_t)row*Dd + i;
        split_store2((v[j].x-mu)*rs*gv.x + bv.x, (v[j].y-mu)*rs*gv.y + bv.y,
                     g_hh + o, g_hl + o);
        split_store2((v[j].z-mu)*rs*gv.z + bv.z, (v[j].w-mu)*rs*gv.w + bv.w,
                     g_hh + o + 2, g_hl + o + 2);
    }
}

__global__ void rope_table_kernel(){
    int t = blockIdx.x, i = threadIdx.x;
    float inv = (float)pow(100000.0, -((double)(2*i))/64.0);
    float ang = (float)t * inv;
    g_cos[t*32+i] = cosf(ang);
    g_sin[t*32+i] = sinf(ang);
}

__global__ void extract_kernel(){
    int r = blockIdx.x, b = r >> 9, i = r & 511;
    const float* src = g_rep + (size_t)(b*Tt + TRAIN + i)*Dd;
    for (int j = threadIdx.x*2; j < Dd; j += 256){
        split_store2(src[j], src[j+1], g_th + (size_t)r*Dd + j, g_tl + (size_t)r*Dd + j);
    }
}

// ---------------- launcher ----------------
#define SYM(p, s) cudaGetSymbolAddress((void**)&p, s)

extern "C" void kernel_launch(void* const* d_in, const int* in_sizes, int n_in,
                              void* d_out, int out_size){
    const float* R    = (const float*)d_in[0];
    const int*   y    = (const int*)  d_in[1];
    const float* emb  = (const float*)d_in[2];
    const float* Wqkv = (const float*)d_in[3];
    const float* bqkv = (const float*)d_in[4];
    const float* Wo   = (const float*)d_in[5];
    const float* bo   = (const float*)d_in[6];
    const float* ln1g = (const float*)d_in[7];
    const float* ln1b = (const float*)d_in[8];
    const float* ln2g = (const float*)d_in[9];
    const float* ln2b = (const float*)d_in[10];
    const float* W1   = (const float*)d_in[11];
    const float* b1   = (const float*)d_in[12];
    const float* W2   = (const float*)d_in[13];
    const float* b2   = (const float*)d_in[14];
    const float* pW1  = (const float*)d_in[15];
    const float* pb1  = (const float*)d_in[16];
    const float* pW2  = (const float*)d_in[17];
    const float* pb2  = (const float*)d_in[18];

    cudaFuncSetAttribute(mma_gemm, cudaFuncAttributeMaxDynamicSharedMemorySize, GSM);
    cudaFuncSetAttribute(flash_kernel, cudaFuncAttributeMaxDynamicSharedMemorySize, FSM);

    float *qkv, *rep;
    bf16 *hh,*hl,*ah,*al,*fh,*fl,*th,*tl,*gh,*gl;
    bf16 *Wqkvh,*Wqkvl,*Woh,*Wol,*W1h,*W1l,*W2h,*W2l,*pW1h,*pW1l,*pW2h,*pW2l;
    SYM(qkv,g_qkv); SYM(rep,g_rep);
    SYM(hh,g_hh); SYM(hl,g_hl); SYM(ah,g_ah); SYM(al,g_al);
    SYM(fh,g_fh); SYM(fl,g_fl);
    SYM(th,g_th); SYM(tl,g_tl);
    SYM(gh,g_gh); SYM(gl,g_gl);
    SYM(Wqkvh,g_Wqkvh); SYM(Wqkvl,g_Wqkvl); SYM(Woh,g_Woh); SYM(Wol,g_Wol);
    SYM(W1h,g_W1h); SYM(W1l,g_W1l); SYM(W2h,g_W2h); SYM(W2l,g_W2l);
    SYM(pW1h,g_pW1h); SYM(pW1l,g_pW1l); SYM(pW2h,g_pW2h); SYM(pW2l,g_pW2l);

    dim3 wb(32, 8);
    wsplit_kernel<<<dim3(48,16,12), wb>>>(Wqkv, Wqkvh, Wqkvl, 512, 1536, 1536);
    rope_table_kernel<<<Tt, 32>>>();
    embed_kernel<<<BT, 128>>>(R, y, emb);
    wsplit_kernel<<<dim3(16,16,12), wb>>>(Wo, Woh, Wol, 512, 512, 512);

    for (int l = 0; l < Ll; l++){
        ln_kernel<<<BT/8, 256>>>(ln1g + l*Dd, ln1b + l*Dd);
        mma_gemm<<<dim3(12,64,1),256,GSM>>>(hh, hl, Wqkvh + (size_t)l*1536*512, Wqkvl + (size_t)l*1536*512,
            bqkv + l*1536, nullptr, nullptr, nullptr, nullptr, 512, 512, 1536, 1536, 0,0,0, 2, 2);
        if (l == 0){
            wsplit_kernel<<<dim3(64,16,12), wb>>>(W1, W1h, W1l, 512, 2048, 2048);
            wsplit_kernel<<<dim3(16,64,12), wb>>>(W2, W2h, W2l, 2048, 512, 512);
            wsplit_kernel<<<dim3(32,16,1),  wb>>>(pW1, pW1h, pW1l, 512, 1024, 1024);
            wsplit_kernel<<<dim3(4, 32,1),  wb>>>(pW2, pW2h, pW2l, 1024, 100, 128);
        }
        flash_kernel<<<dim3(16, NBH), 256, FSM>>>();
        mma_gemm<<<dim3(4,64,1),256,GSM>>>(ah, al, Woh + (size_t)l*512*512, Wol + (size_t)l*512*512,
            bo + l*512, rep, rep, nullptr, nullptr, 512, 512, 512, 512, 0,0,0, 0, 3);
        ln_kernel<<<BT/8, 256>>>(ln2g + l*Dd, ln2b + l*Dd);
        mma_gemm<<<dim3(16,64,1),256,GSM>>>(hh, hl, W1h + (size_t)l*2048*512, W1l + (size_t)l*2048*512,
            b1 + l*2048, nullptr, nullptr, fh, fl, 512, 512, 2048, 2048, 0,0,0, 1, 3);
        mma_gemm<<<dim3(4,64,1),256,GSM>>>(fh, fl, W2h + (size_t)l*512*2048, W2l + (size_t)l*512*2048,
            b2 + l*512, rep, rep, nullptr, nullptr, 2048, 2048, 512, 512, 0,0,0, 0, 3);
    }

    extract_kernel<<<MTEST, 128>>>();
    mma_gemm<<<dim3(8,16,1),256,GSM>>>(th, tl, pW1h, pW1l, pb1, nullptr,
        nullptr, gh, gl, 512, 512, 1024, 1024, 0,0,0, 1, 3);
    mma_gemm<<<dim3(1,16,1),256,GSM>>>(gh, gl, pW2h, pW2l, pb2, nullptr,
        (float*)d_out, nullptr, nullptr, 1024, 1024, 100, 100, 0,0,0, 0, 3);
}

// round 15
// speedup vs baseline: 1.8287x; 1.0329x over previous
#include <cuda_runtime.h>
#include <cuda_bf16.h>
#include <cuda_fp16.h>
#include <math.h>
#include <stdint.h>

#define Bc    4
#define Tt    2048
#define TRAIN 1536
#define Dd    512
#define Ll    12
#define FFd   2048
#define BT    (Bc*Tt)
#define NBH   32
#define MTEST 2048

typedef __nv_bfloat16 bf16;

// ---------------- static buffers ----------------
__device__ float g_rep [BT*Dd];
__device__ float g_qkv [BT*3*Dd];          // fp32 qkv, written only for t>=TRAIN (fixup)
__device__ bf16  g_hh[BT*Dd], g_hl[BT*Dd];
__device__ bf16  g_ah[BT*Dd], g_al[BT*Dd];
__device__ bf16  g_fh[BT*FFd], g_fl[BT*FFd];
__device__ bf16  g_qh[NBH*Tt*64];
__device__ bf16  g_kh[NBH*Tt*64];
__device__ __half g_Vh[NBH*Tt*64];         // V stored fp16 (single term)
__device__ bf16  g_th[MTEST*Dd], g_tl[MTEST*Dd];
__device__ bf16  g_gh[MTEST*2*Dd], g_gl[MTEST*2*Dd];
__device__ bf16  g_Wqkvh[Ll*3*Dd*Dd], g_Wqkvl[Ll*3*Dd*Dd];
__device__ bf16  g_Woh[Ll*Dd*Dd],  g_Wol[Ll*Dd*Dd];
__device__ bf16  g_W1h[Ll*FFd*Dd], g_W1l[Ll*FFd*Dd];
__device__ bf16  g_W2h[Ll*Dd*FFd], g_W2l[Ll*Dd*FFd];
__device__ bf16  g_pW1h[2*Dd*Dd],  g_pW1l[2*Dd*Dd];
__device__ bf16  g_pW2h[128*2*Dd], g_pW2l[128*2*Dd];
__device__ float g_cos[Tt*32], g_sin[Tt*32];

// ---------------- helpers ----------------
__device__ __forceinline__ float gelu_f(float x){
    float y = 0.7978845608028654f*(x + 0.044715f*x*x*x);
    float yc = fminf(fmaxf(y, -15.f), 15.f);
    float t = __expf(2.f*yc);
    float th = (t - 1.f)/(t + 1.f);
    return 0.5f*x*(1.f + th);
}
__device__ __forceinline__ void split2(float x, bf16& h, bf16& l){
    h = __float2bfloat16(x);
    l = __float2bfloat16(x - __bfloat162float(h));
}
__device__ __forceinline__ uint32_t smem_u32(const void* p){
    uint32_t a;
    asm("{ .reg .u64 t; cvta.to.shared.u64 t, %1; cvt.u32.u64 %0, t; }" : "=r"(a) : "l"(p));
    return a;
}
__device__ __forceinline__ void cpasync16(uint32_t dst, const void* src){
    asm volatile("cp.async.cg.shared.global [%0], [%1], 16;" :: "r"(dst), "l"(src) : "memory");
}
__device__ __forceinline__ void ldsm4(uint32_t* r, uint32_t a){
    asm volatile("ldmatrix.sync.aligned.m8n8.x4.shared.b16 {%0,%1,%2,%3}, [%4];"
        : "=r"(r[0]),"=r"(r[1]),"=r"(r[2]),"=r"(r[3]) : "r"(a));
}
__device__ __forceinline__ void ldsm4t(uint32_t* r, uint32_t a){
    asm volatile("ldmatrix.sync.aligned.m8n8.x4.trans.shared.b16 {%0,%1,%2,%3}, [%4];"
        : "=r"(r[0]),"=r"(r[1]),"=r"(r[2]),"=r"(r[3]) : "r"(a));
}
__device__ __forceinline__ void mma16816(float* c, const uint32_t* a, const uint32_t* b){
    asm volatile("mma.sync.aligned.m16n8k16.row.col.f32.bf16.bf16.f32 "
        "{%0,%1,%2,%3}, {%4,%5,%6,%7}, {%8,%9}, {%0,%1,%2,%3};"
        : "+f"(c[0]),"+f"(c[1]),"+f"(c[2]),"+f"(c[3])
        : "r"(a[0]),"r"(a[1]),"r"(a[2]),"r"(a[3]), "r"(b[0]),"r"(b[1]));
}
__device__ __forceinline__ void mma16816h(float* c, const uint32_t* a, const uint32_t* b){
    asm volatile("mma.sync.aligned.m16n8k16.row.col.f32.f16.f16.f32 "
        "{%0,%1,%2,%3}, {%4,%5,%6,%7}, {%8,%9}, {%0,%1,%2,%3};"
        : "+f"(c[0]),"+f"(c[1]),"+f"(c[2]),"+f"(c[3])
        : "r"(a[0]),"r"(a[1]),"r"(a[2]),"r"(a[3]), "r"(b[0]),"r"(b[1]));
}
__device__ __forceinline__ uint32_t packbf(float lo, float hi){
    uint32_t r;
    asm("cvt.rn.bf16x2.f32 %0, %1, %2;" : "=r"(r) : "f"(hi), "f"(lo));
    return r;
}
__device__ __forceinline__ uint32_t packh(float lo, float hi){
    uint32_t r;
    asm("cvt.rn.f16x2.f32 %0, %1, %2;" : "=r"(r) : "f"(hi), "f"(lo));
    return r;
}
__device__ __forceinline__ void split_store2(float v0, float v1, bf16* ph, bf16* pl){
    float h0 = __bfloat162float(__float2bfloat16(v0));
    float h1 = __bfloat162float(__float2bfloat16(v1));
    *(uint32_t*)ph = packbf(v0, v1);
    *(uint32_t*)pl = packbf(v0 - h0, v1 - h1);
}

// ================= fused flash attention =================
// No-max softmax: scores bounded (|s| << 80), so exp(s) accumulates safely in fp32.
// Mathematically identical to max-subtracted softmax. 3-stage pipe, 1 sync/tile.
#define FLDS 72
#define FTILE (64*FLDS*2)          // 9216
#define FQT   (128*FLDS*2)         // 18432
#define FSTG  (2*FTILE)            // 18432
#define FSM   (FQT + 3*FSTG)       // 73728

__global__ __launch_bounds__(256, 2) void flash_kernel(){
    extern __shared__ __align__(128) char smem[];
    const uint32_t sb = smem_u32(smem);
    const int tid = threadIdx.x, lane = tid & 31, warp = tid >> 5;
    const int bh = blockIdx.y, b = bh >> 3, h = bh & 7;
    const int t0 = blockIdx.x * 128;
    const int r0 = lane >> 2, cq = lane & 3;
    const int aRow = lane & 15, aCol = (lane >> 4)*8;
    const int bQuad = lane >> 3, bRowQ = lane & 7;
    const int ntOff = bQuad >> 1, colQ = (bQuad & 1)*8;
    const int tKey = (bQuad & 1)*8 + bRowQ, tDim = (bQuad >> 1)*8;
    const uint32_t ST0 = sb + FQT;

    auto issueKV = [&](int kt, int st){
        int s0n = kt*64;
        uint32_t base = ST0 + st*FSTG;
        #pragma unroll
        for (int i = 0; i < 4; i++){
            int idx = tid + i*256;
            int tile = idx >> 9, rem = idx & 511;
            int row = rem >> 3, ch = rem & 7;
            const void* src = tile
                ? (const void*)(g_Vh + ((size_t)bh*Tt + s0n + row)*64 + ch*8)
                : (const void*)(g_kh + ((size_t)bh*Tt + s0n + row)*64 + ch*8);
            cpasync16(base + tile*FTILE + (uint32_t)(row*FLDS + ch*8)*2, src);
        }
        asm volatile("cp.async.commit_group;" ::: "memory");
    };

    {
        #pragma unroll
        for (int i = 0; i < 4; i++){
            int idx = tid + i*256;
            int row = idx >> 3, ch = idx & 7;
            cpasync16(sb + (uint32_t)(row*FLDS + ch*8)*2,
                      g_qh + ((size_t)bh*Tt + t0 + row)*64 + ch*8);
        }
        issueKV(0, 0);
        issueKV(1, 1);
    }

    float o[8][4] = {};
    float l0 = 0.f, l1 = 0.f;
    uint32_t qfh[4][4];

    int st = 0;
    for (int kt = 0; kt < 24; kt++){
        if (kt + 1 < 24) asm volatile("cp.async.wait_group 1;" ::: "memory");
        else             asm volatile("cp.async.wait_group 0;" ::: "memory");
        __syncthreads();
        if (kt + 2 < 24){
            int s2 = st + 2; if (s2 >= 3) s2 -= 3;
            issueKV(kt + 2, s2);
        }

        if (kt == 0){
            #pragma unroll
            for (int ks = 0; ks < 4; ks++){
                uint32_t ad = sb + (uint32_t)((warp*16 + aRow)*FLDS + ks*16 + aCol)*2;
                ldsm4(qfh[ks], ad);
            }
        }

        uint32_t KB = ST0 + st*FSTG;
        // ---- S = Qh Kh^T ----
        float acc[8][4] = {};
        #pragma unroll
        for (int ks = 0; ks < 4; ks++){
            #pragma unroll
            for (int g = 0; g < 2; g++){
                uint32_t bfh[4][2];
                #pragma unroll
                for (int p = 0; p < 2; p++){
                    int ntb = g*4 + p*2;
                    uint32_t bd = KB + (uint32_t)(((ntb + ntOff)*8 + bRowQ)*FLDS + ks*16 + colQ)*2;
                    uint32_t r4[4];
                    ldsm4(r4, bd);
                    bfh[p*2][0]=r4[0]; bfh[p*2][1]=r4[1]; bfh[p*2+1][0]=r4[2]; bfh[p*2+1][1]=r4[3];
                }
                #pragma unroll
                for (int j = 0; j < 4; j++) mma16816(acc[g*4+j], qfh[ks], bfh[j]);
            }
        }

        // ---- exp (no max subtraction; scores bounded) + row-sum ----
        float ps0 = 0.f, ps1 = 0.f;
        #pragma unroll
        for (int nt = 0; nt < 8; nt++){
            acc[nt][0] = __expf(acc[nt][0]);
            acc[nt][1] = __expf(acc[nt][1]);
            acc[nt][2] = __expf(acc[nt][2]);
            acc[nt][3] = __expf(acc[nt][3]);
            ps0 += acc[nt][0] + acc[nt][1];
            ps1 += acc[nt][2] + acc[nt][3];
        }
        ps0 += __shfl_xor_sync(~0u, ps0, 1); ps0 += __shfl_xor_sync(~0u, ps0, 2);
        ps1 += __shfl_xor_sync(~0u, ps1, 1); ps1 += __shfl_xor_sync(~0u, ps1, 2);
        l0 += ps0; l1 += ps1;

        // ---- O += P V (fp16) ----
        uint32_t VB = KB + FTILE;
        #pragma unroll
        for (int kc = 0; kc < 4; kc++){
            uint32_t ap[4];
            ap[0] = packh(acc[2*kc][0],   acc[2*kc][1]);
            ap[1] = packh(acc[2*kc][2],   acc[2*kc][3]);
            ap[2] = packh(acc[2*kc+1][0], acc[2*kc+1][1]);
            ap[3] = packh(acc[2*kc+1][2], acc[2*kc+1][3]);
            #pragma unroll
            for (int g = 0; g < 2; g++){
                uint32_t bfh[4][2];
                #pragma unroll
                for (int p = 0; p < 2; p++){
                    int ntb = g*4 + p*2;
                    uint32_t bd = VB + (uint32_t)((kc*16 + tKey)*FLDS + ntb*8 + tDim)*2;
                    uint32_t r4[4];
                    ldsm4t(r4, bd);
                    bfh[p*2][0]=r4[0]; bfh[p*2][1]=r4[1]; bfh[p*2+1][0]=r4[2]; bfh[p*2+1][1]=r4[3];
                }
                #pragma unroll
                for (int j = 0; j < 4; j++) mma16816h(o[g*4+j], ap, bfh[j]);
            }
        }
        st++; if (st >= 3) st -= 3;
    }

    // ---- self-key fixup (fp32 exact; rows t >= TRAIN) ----
    if (t0 >= TRAIN){
        float ll[2] = {l0, l1};
        #pragma unroll
        for (int r = 0; r < 2; r++){
            int trow = t0 + warp*16 + r0 + 8*r;
            size_t qb = ((size_t)(b*Tt + trow))*1536 + h*64;
            float part = 0.f;
            #pragma unroll
            for (int d = 0; d < 16; d++)
                part += g_qkv[qb + cq*16 + d] * g_qkv[qb + 512 + cq*16 + d];
            part += __shfl_xor_sync(~0u, part, 1);
            part += __shfl_xor_sync(~0u, part, 2);
            float p = __expf(part);
            ll[r] += p;
            const float* vs = g_qkv + qb + 1024;
            #pragma unroll
            for (int nt = 0; nt < 8; nt++){
                o[nt][2*r+0] += p*vs[nt*8 + 2*cq + 0];
                o[nt][2*r+1] += p*vs[nt*8 + 2*cq + 1];
            }
        }
        l0 = ll[0]; l1 = ll[1];
    }

    // ---- normalize + packed split write ----
    float inv[2] = {1.f/l0, 1.f/l1};
    #pragma unroll
    for (int r = 0; r < 2; r++){
        int trow = t0 + warp*16 + r0 + 8*r;
        size_t ob = ((size_t)(b*Tt + trow))*Dd + h*64;
        #pragma unroll
        for (int nt = 0; nt < 8; nt++){
            size_t off = ob + nt*8 + 2*cq;
            split_store2(o[nt][2*r]*inv[r], o[nt][2*r+1]*inv[r], g_ah + off, g_al + off);
        }
    }
}

// ---------------- split-bf16 HMMA GEMM (3-stage, XOR-swizzled, variable TERMS) ----------------
// EPI: 0 = fp32 C (+bias,+res), 1 = gelu -> split bf16, 2 = QKV rope scatter
#define BK 32
#define TILE_B (128*64)             // 8192 B
#define STAGE_B (4*TILE_B)          // 32768 B
#define GSM (3*STAGE_B)             // 98304 B

__global__ __launch_bounds__(256, 2) void mma_gemm(
    const bf16* __restrict__ Ah, const bf16* __restrict__ Al,
    const bf16* __restrict__ Bh, const bf16* __restrict__ Bl,
    const float* __restrict__ bias, const float* __restrict__ res,
    float* C, bf16* Chi, bf16* Clo,
    int K, int ldb, int Nreal, int ldC, size_t sA, size_t sB, size_t sC, int EPI, int TERMS)
{
    extern __shared__ __align__(128) char smem[];
    const uint32_t sb = smem_u32(smem);
    const int tid = threadIdx.x, lane = tid & 31, wid = tid >> 5;
    const int m0 = blockIdx.y*128, n0 = blockIdx.x*128;
    const size_t zb = blockIdx.z;
    const bf16* pAh = Ah + zb*sA + (size_t)m0*K;
    const bf16* pAl = Al + zb*sA + (size_t)m0*K;
    const bf16* pBh = Bh + zb*sB + (size_t)n0*ldb;
    const bf16* pBl = Bl + zb*sB + (size_t)n0*ldb;

    float acc[4][4][4] = {};
    const int nk = K/BK;

    auto issue = [&](int c, int s){
        uint32_t base = sb + s*STAGE_B;
        #pragma unroll
        for (int i = 0; i < 2; i++){
            int seg = tid + i*256;
            int row = seg >> 2, s4 = seg & 3;
            int phys = s4 ^ ((row >> 1) & 3);
            uint32_t doff = (uint32_t)(row*64 + phys*16);
            const size_t go = (size_t)row*K + c*BK + s4*8;
            const size_t gob = (size_t)row*ldb + c*BK + s4*8;
            cpasync16(base + 0*TILE_B + doff, pAh + go);
            cpasync16(base + 1*TILE_B + doff, pAl + go);
            cpasync16(base + 2*TILE_B + doff, pBh + gob);
            cpasync16(base + 3*TILE_B + doff, pBl + gob);
        }
        asm volatile("cp.async.commit_group;" ::: "memory");
    };

    issue(0, 0);
    if (nk > 1) issue(1, 1);
    const int wm = (wid>>2)*64, wn = (wid&3)*32;
    const int aRow = lane & 15, aChu = lane >> 4;
    const int bQuad = lane >> 3, bRowQ = lane & 7;
    const int ntOff = bQuad >> 1, bChu = bQuad & 1;

    int st = 0;
    for (int c = 0; c < nk; c++){
        if (c+1 < nk) asm volatile("cp.async.wait_group 1;" ::: "memory");
        else          asm volatile("cp.async.wait_group 0;" ::: "memory");
        __syncthreads();
        if (c+2 < nk){
            int s2 = st + 2; if (s2 >= 3) s2 -= 3;
            issue(c+2, s2);
        }
        uint32_t base = sb + st*STAGE_B;
        #pragma unroll
        for (int ks = 0; ks < 2; ks++){
            uint32_t a_h[4][4], a_l[4][4], b_h[4][2], b_l[4][2];
            #pragma unroll
            for (int mt = 0; mt < 4; mt++){
                int row = wm + mt*16 + aRow;
                int phys = (2*ks + aChu) ^ ((row >> 1) & 3);
                uint32_t ad = base + (uint32_t)(row*64 + phys*16);
                ldsm4(a_h[mt], ad);
                if (TERMS == 3) ldsm4(a_l[mt], ad + TILE_B);
            }
            #pragma unroll
            for (int p = 0; p < 2; p++){
                int row = wn + (p*2 + ntOff)*8 + bRowQ;
                int phys = (2*ks + bChu) ^ ((row >> 1) & 3);
                uint32_t bd = base + 2*TILE_B + (uint32_t)(row*64 + phys*16);
                uint32_t r4[4];
                ldsm4(r4, bd);
                b_h[p*2][0]=r4[0]; b_h[p*2][1]=r4[1]; b_h[p*2+1][0]=r4[2]; b_h[p*2+1][1]=r4[3];
                ldsm4(r4, bd + TILE_B);
                b_l[p*2][0]=r4[0]; b_l[p*2][1]=r4[1]; b_l[p*2+1][0]=r4[2]; b_l[p*2+1][1]=r4[3];
            }
            #pragma unroll
            for (int mt = 0; mt < 4; mt++)
                #pragma unroll
                for (int nt = 0; nt < 4; nt++){
                    mma16816(acc[mt][nt], a_h[mt], b_h[nt]);
                    mma16816(acc[mt][nt], a_h[mt], b_l[nt]);
                    if (TERMS == 3) mma16816(acc[mt][nt], a_l[mt], b_h[nt]);
                }
        }
        st++; if (st >= 3) st -= 3;
    }

    const int r0 = lane >> 2, cW = (lane & 3)*2;
    #pragma unroll
    for (int mt = 0; mt < 4; mt++)
    #pragma unroll
    for (int hh2 = 0; hh2 < 2; hh2++){
        int gm = m0 + wm + mt*16 + r0 + hh2*8;
        #pragma unroll
        for (int nt = 0; nt < 4; nt++){
            float v0 = acc[mt][nt][hh2*2+0], v1 = acc[mt][nt][hh2*2+1];
            int gn = n0 + wn + nt*8 + cW;
            if (bias){ v0 += __ldg(bias+gn); v1 += __ldg(bias+gn+1); }
            if (EPI == 2){
                int b = gm >> 11, t = gm & (Tt-1);
                if (gn < 1024){
                    int hq = (gn & 511) >> 6;
                    int i = (gn & 63) >> 1;
                    float cc = g_cos[t*32+i], ss = g_sin[t*32+i];
                    float r1 = v0*cc - v1*ss, r2 = v0*ss + v1*cc;
                    if (gn < 512){ r1 *= 0.125f; r2 *= 0.125f; }
                    size_t qo = ((size_t)(b*8+hq)*Tt + t)*64 + (gn & 63);
                    if (gn < 512) *(uint32_t*)(g_qh + qo) = packbf(r1, r2);
                    else          *(uint32_t*)(g_kh + qo) = packbf(r1, r2);
                    if (t >= TRAIN){
                        size_t fo = (size_t)gm*1536 + gn;
                        g_qkv[fo] = r1; g_qkv[fo+1] = r2;
                    }
                } else {
                    int h2 = (gn - 1024) >> 6, dd = (gn - 1024) & 63;
                    size_t vo = ((size_t)(b*8+h2)*Tt + t)*64 + dd;
                    *(uint32_t*)(g_Vh + vo) = packh(v0, v1);
                    if (t >= TRAIN){
                        size_t fo = (size_t)gm*1536 + gn;
                        g_qkv[fo] = v0; g_qkv[fo+1] = v1;
                    }
                }
            } else if (EPI == 1){
                size_t off = zb*sC + (size_t)gm*ldC + gn;
                split_store2(gelu_f(v0), gelu_f(v1), Chi + off, Clo + off);
            } else {
                size_t off = zb*sC + (size_t)gm*ldC + gn;
                if (res){ v0 += res[off]; v1 += res[off+1]; }
                if (gn+1 < Nreal){
                    *(float2*)(C + off) = make_float2(v0, v1);
                } else {
                    if (gn < Nreal) C[off] = v0;
                }
            }
        }
    }
}

// ---------------- weight transpose + split ----------------
__global__ void wsplit_kernel(const float* __restrict__ W, bf16* oh, bf16* ol,
                              int K, int N, int Npad){
    __shared__ float sm[32][33];
    int n0 = blockIdx.x*32, k0 = blockIdx.y*32, z = blockIdx.z;
    const float* Wb = W + (size_t)z*K*N;
    size_t ob = (size_t)z*Npad*K;
    int tx = threadIdx.x, ty = threadIdx.y;
    #pragma unroll
    for (int j = 0; j < 4; j++){
        int n = n0 + tx;
        sm[ty+8*j][tx] = (n < N) ? Wb[(size_t)(k0+ty+8*j)*N + n] : 0.f;
    }
    __syncthreads();
    #pragma unroll
    for (int j = 0; j < 4; j++){
        size_t o = ob + (size_t)(n0+ty+8*j)*K + k0 + tx;
        split2(sm[tx][ty+8*j], oh[o], ol[o]);
    }
}

// ---------------- misc kernels ----------------
__global__ void embed_kernel(const float* __restrict__ R, const int* __restrict__ y,
                             const float* __restrict__ emb){
    int row = blockIdx.x, t = row & (Tt-1), b = row >> 11;
    const float4* Rr = (const float4*)(R + (size_t)row*Dd);
    float4* Or = (float4*)(g_rep + (size_t)row*Dd);
    if (t < TRAIN){
        int yv = y[b*TRAIN + t];
        const float4* E = (const float4*)(emb + (size_t)yv*Dd);
        for (int i = threadIdx.x; i < Dd/4; i += blockDim.x){
            float4 a = Rr[i]; float4 e = E[i];
            a.x += e.x; a.y += e.y; a.z += e.z; a.w += e.w;
            Or[i] = a;
        }
    } else {
        for (int i = threadIdx.x; i < Dd/4; i += blockDim.x) Or[i] = Rr[i];
    }
}

__global__ __launch_bounds__(256) void ln_kernel(const float* __restrict__ g,
                                                 const float* __restrict__ be){
    int row = blockIdx.x*8 + (threadIdx.x >> 5);
    int lane = threadIdx.x & 31;
    const float4* xr = (const float4*)(g_rep + (size_t)row*Dd);
    float4 v[4];
    float s = 0.f;
    #pragma unroll
    for (int j = 0; j < 4; j++){
        v[j] = xr[lane + 32*j];
        s += v[j].x + v[j].y + v[j].z + v[j].w;
    }
    #pragma unroll
    for (int o = 16; o; o >>= 1) s += __shfl_xor_sync(~0u, s, o);
    float mu = s * (1.f/Dd);
    float vs = 0.f;
    #pragma unroll
    for (int j = 0; j < 4; j++){
        float a = v[j].x-mu, b2 = v[j].y-mu, c = v[j].z-mu, d = v[j].w-mu;
        vs += a*a + b2*b2 + c*c + d*d;
    }
    #pragma unroll
    for (int o = 16; o; o >>= 1) vs += __shfl_xor_sync(~0u, vs, o);
    float rs = rsqrtf(vs*(1.f/Dd) + 1e-5f);
    #pragma unroll
    for (int j = 0; j < 4; j++){
        int i = lane*4 + 128*j;
        float4 gv = *(const float4*)(g + i);
        float4 bv = *(const float4*)(be + i);
        size_t o = (size_t)row*Dd + i;
        split_store2((v[j].x-mu)*rs*gv.x + bv.x, (v[j].y-mu)*rs*gv.y + bv.y,
                     g_hh + o, g_hl + o);
        split_store2((v[j].z-mu)*rs*gv.z + bv.z, (v[j].w-mu)*rs*gv.w + bv.w,
                     g_hh + o + 2, g_hl + o + 2);
    }
}

__global__ void rope_table_kernel(){
    int t = blockIdx.x, i = threadIdx.x;
    float inv = (float)pow(100000.0, -((double)(2*i))/64.0);
    float ang = (float)t * inv;
    g_cos[t*32+i] = cosf(ang);
    g_sin[t*32+i] = sinf(ang);
}

__global__ void extract_kernel(){
    int r = blockIdx.x, b = r >> 9, i = r & 511;
    const float* src = g_rep + (size_t)(b*Tt + TRAIN + i)*Dd;
    for (int j = threadIdx.x*2; j < Dd; j += 256){
        split_store2(src[j], src[j+1], g_th + (size_t)r*Dd + j, g_tl + (size_t)r*Dd + j);
    }
}

// ---------------- launcher ----------------
#define SYM(p, s) cudaGetSymbolAddress((void**)&p, s)

extern "C" void kernel_launch(void* const* d_in, const int* in_sizes, int n_in,
                              void* d_out, int out_size){
    const float* R    = (const float*)d_in[0];
    const int*   y    = (const int*)  d_in[1];
    const float* emb  = (const float*)d_in[2];
    const float* Wqkv = (const float*)d_in[3];
    const float* bqkv = (const float*)d_in[4];
    const float* Wo   = (const float*)d_in[5];
    const float* bo   = (const float*)d_in[6];
    const float* ln1g = (const float*)d_in[7];
    const float* ln1b = (const float*)d_in[8];
    const float* ln2g = (const float*)d_in[9];
    const float* ln2b = (const float*)d_in[10];
    const float* W1   = (const float*)d_in[11];
    const float* b1   = (const float*)d_in[12];
    const float* W2   = (const float*)d_in[13];
    const float* b2   = (const float*)d_in[14];
    const float* pW1  = (const float*)d_in[15];
    const float* pb1  = (const float*)d_in[16];
    const float* pW2  = (const float*)d_in[17];
    const float* pb2  = (const float*)d_in[18];

    cudaFuncSetAttribute(mma_gemm, cudaFuncAttributeMaxDynamicSharedMemorySize, GSM);
    cudaFuncSetAttribute(flash_kernel, cudaFuncAttributeMaxDynamicSharedMemorySize, FSM);

    float *qkv, *rep;
    bf16 *hh,*hl,*ah,*al,*fh,*fl,*th,*tl,*gh,*gl;
    bf16 *Wqkvh,*Wqkvl,*Woh,*Wol,*W1h,*W1l,*W2h,*W2l,*pW1h,*pW1l,*pW2h,*pW2l;
    SYM(qkv,g_qkv); SYM(rep,g_rep);
    SYM(hh,g_hh); SYM(hl,g_hl); SYM(ah,g_ah); SYM(al,g_al);
    SYM(fh,g_fh); SYM(fl,g_fl);
    SYM(th,g_th); SYM(tl,g_tl);
    SYM(gh,g_gh); SYM(gl,g_gl);
    SYM(Wqkvh,g_Wqkvh); SYM(Wqkvl,g_Wqkvl); SYM(Woh,g_Woh); SYM(Wol,g_Wol);
    SYM(W1h,g_W1h); SYM(W1l,g_W1l); SYM(W2h,g_W2h); SYM(W2l,g_W2l);
    SYM(pW1h,g_pW1h); SYM(pW1l,g_pW1l); SYM(pW2h,g_pW2h); SYM(pW2l,g_pW2l);

    dim3 wb(32, 8);
    wsplit_kernel<<<dim3(48,16,12), wb>>>(Wqkv, Wqkvh, Wqkvl, 512, 1536, 1536);
    rope_table_kernel<<<Tt, 32>>>();
    embed_kernel<<<BT, 128>>>(R, y, emb);
    wsplit_kernel<<<dim3(16,16,12), wb>>>(Wo, Woh, Wol, 512, 512, 512);

    for (int l = 0; l < Ll; l++){
        ln_kernel<<<BT/8, 256>>>(ln1g + l*Dd, ln1b + l*Dd);
        mma_gemm<<<dim3(12,64,1),256,GSM>>>(hh, hl, Wqkvh + (size_t)l*1536*512, Wqkvl + (size_t)l*1536*512,
            bqkv + l*1536, nullptr, nullptr, nullptr, nullptr, 512, 512, 1536, 1536, 0,0,0, 2, 2);
        if (l == 0){
            wsplit_kernel<<<dim3(64,16,12), wb>>>(W1, W1h, W1l, 512, 2048, 2048);
            wsplit_kernel<<<dim3(16,64,12), wb>>>(W2, W2h, W2l, 2048, 512, 512);
            wsplit_kernel<<<dim3(32,16,1),  wb>>>(pW1, pW1h, pW1l, 512, 1024, 1024);
            wsplit_kernel<<<dim3(4, 32,1),  wb>>>(pW2, pW2h, pW2l, 1024, 100, 128);
        }
        flash_kernel<<<dim3(16, NBH), 256, FSM>>>();
        mma_gemm<<<dim3(4,64,1),256,GSM>>>(ah, al, Woh + (size_t)l*512*512, Wol + (size_t)l*512*512,
            bo + l*512, rep, rep, nullptr, nullptr, 512, 512, 512, 512, 0,0,0, 0, 3);
        ln_kernel<<<BT/8, 256>>>(ln2g + l*Dd, ln2b + l*Dd);
        mma_gemm<<<dim3(16,64,1),256,GSM>>>(hh, hl, W1h + (size_t)l*2048*512, W1l + (size_t)l*2048*512,
            b1 + l*2048, nullptr, nullptr, fh, fl, 512, 512, 2048, 2048, 0,0,0, 1, 3);
        mma_gemm<<<dim3(4,64,1),256,GSM>>>(fh, fl, W2h + (size_t)l*512*2048, W2l + (size_t)l*512*2048,
            b2 + l*512, rep, rep, nullptr, nullptr, 2048, 2048, 512, 512, 0,0,0, 0, 3);
    }

    extract_kernel<<<MTEST, 128>>>();
    mma_gemm<<<dim3(8,16,1),256,GSM>>>(th, tl, pW1h, pW1l, pb1, nullptr,
        nullptr, gh, gl, 512, 512, 1024, 1024, 0,0,0, 1, 3);
    mma_gemm<<<dim3(1,16,1),256,GSM>>>(gh, gl, pW2h, pW2l, pb2, nullptr,
        (float*)d_out, nullptr, nullptr, 1024, 1024, 100, 100, 0,0,0, 0, 3);
}

// round 16
// speedup vs baseline: 1.8388x; 1.0055x over previous
#include <cuda_runtime.h>
#include <cuda_bf16.h>
#include <cuda_fp16.h>
#include <math.h>
#include <stdint.h>

#define Bc    4
#define Tt    2048
#define TRAIN 1536
#define Dd    512
#define Ll    12
#define FFd   2048
#define BT    (Bc*Tt)
#define NBH   32
#define MTEST 2048

typedef __half hf;

// ---------------- static buffers (all splits fp16) ----------------
__device__ float g_rep [BT*Dd];
__device__ float g_qkv [BT*3*Dd];          // fp32 qkv, written only for t>=TRAIN (fixup)
__device__ hf    g_hh[BT*Dd], g_hl[BT*Dd];
__device__ hf    g_ah[BT*Dd], g_al[BT*Dd];
__device__ hf    g_fh[BT*FFd], g_fl[BT*FFd];
__device__ hf    g_qh[NBH*Tt*64];
__device__ hf    g_kh[NBH*Tt*64];
__device__ hf    g_Vh[NBH*Tt*64];
__device__ hf    g_th[MTEST*Dd], g_tl[MTEST*Dd];
__device__ hf    g_gh[MTEST*2*Dd], g_gl[MTEST*2*Dd];
__device__ hf    g_Wqkvh[Ll*3*Dd*Dd], g_Wqkvl[Ll*3*Dd*Dd];
__device__ hf    g_Woh[Ll*Dd*Dd],  g_Wol[Ll*Dd*Dd];
__device__ hf    g_W1h[Ll*FFd*Dd], g_W1l[Ll*FFd*Dd];
__device__ hf    g_W2h[Ll*Dd*FFd], g_W2l[Ll*Dd*FFd];
__device__ hf    g_pW1h[2*Dd*Dd],  g_pW1l[2*Dd*Dd];
__device__ hf    g_pW2h[128*2*Dd], g_pW2l[128*2*Dd];
__device__ float g_cos[Tt*32], g_sin[Tt*32];

// ---------------- helpers ----------------
__device__ __forceinline__ float gelu_f(float x){
    float y = 0.7978845608028654f*(x + 0.044715f*x*x*x);
    float yc = fminf(fmaxf(y, -15.f), 15.f);
    float t = __expf(2.f*yc);
    float th = (t - 1.f)/(t + 1.f);
    return 0.5f*x*(1.f + th);
}
__device__ __forceinline__ uint32_t smem_u32(const void* p){
    uint32_t a;
    asm("{ .reg .u64 t; cvta.to.shared.u64 t, %1; cvt.u32.u64 %0, t; }" : "=r"(a) : "l"(p));
    return a;
}
__device__ __forceinline__ void cpasync16(uint32_t dst, const void* src){
    asm volatile("cp.async.cg.shared.global [%0], [%1], 16;" :: "r"(dst), "l"(src) : "memory");
}
__device__ __forceinline__ void ldsm4(uint32_t* r, uint32_t a){
    asm volatile("ldmatrix.sync.aligned.m8n8.x4.shared.b16 {%0,%1,%2,%3}, [%4];"
        : "=r"(r[0]),"=r"(r[1]),"=r"(r[2]),"=r"(r[3]) : "r"(a));
}
__device__ __forceinline__ void ldsm4t(uint32_t* r, uint32_t a){
    asm volatile("ldmatrix.sync.aligned.m8n8.x4.trans.shared.b16 {%0,%1,%2,%3}, [%4];"
        : "=r"(r[0]),"=r"(r[1]),"=r"(r[2]),"=r"(r[3]) : "r"(a));
}
__device__ __forceinline__ void mma16816h(float* c, const uint32_t* a, const uint32_t* b){
    asm volatile("mma.sync.aligned.m16n8k16.row.col.f32.f16.f16.f32 "
        "{%0,%1,%2,%3}, {%4,%5,%6,%7}, {%8,%9}, {%0,%1,%2,%3};"
        : "+f"(c[0]),"+f"(c[1]),"+f"(c[2]),"+f"(c[3])
        : "r"(a[0]),"r"(a[1]),"r"(a[2]),"r"(a[3]), "r"(b[0]),"r"(b[1]));
}
__device__ __forceinline__ uint32_t packh(float lo, float hi){
    uint32_t r;
    asm("cvt.rn.f16x2.f32 %0, %1, %2;" : "=r"(r) : "f"(hi), "f"(lo));
    return r;
}
__device__ __forceinline__ void split2h(float x, hf& h, hf& l){
    h = __float2half_rn(x);
    l = __float2half_rn(x - __half2float(h));
}
__device__ __forceinline__ void split_store2h(float v0, float v1, hf* ph, hf* pl){
    float h0 = __half2float(__float2half_rn(v0));
    float h1 = __half2float(__float2half_rn(v1));
    *(uint32_t*)ph = packh(v0, v1);
    *(uint32_t*)pl = packh(v0 - h0, v1 - h1);
}

// ================= fused flash attention (fp16 S and PV) =================
#define FLDS 72
#define FTILE (64*FLDS*2)          // 9216
#define FQT   (128*FLDS*2)         // 18432
#define FSTG  (2*FTILE)            // 18432
#define FSM   (FQT + 3*FSTG)       // 73728

__global__ __launch_bounds__(256, 2) void flash_kernel(){
    extern __shared__ __align__(128) char smem[];
    const uint32_t sb = smem_u32(smem);
    const int tid = threadIdx.x, lane = tid & 31, warp = tid >> 5;
    const int bh = blockIdx.y, b = bh >> 3, h = bh & 7;
    const int t0 = blockIdx.x * 128;
    const int r0 = lane >> 2, cq = lane & 3;
    const int aRow = lane & 15, aCol = (lane >> 4)*8;
    const int bQuad = lane >> 3, bRowQ = lane & 7;
    const int ntOff = bQuad >> 1, colQ = (bQuad & 1)*8;
    const int tKey = (bQuad & 1)*8 + bRowQ, tDim = (bQuad >> 1)*8;
    const uint32_t ST0 = sb + FQT;

    auto issueKV = [&](int kt, int st){
        int s0n = kt*64;
        uint32_t base = ST0 + st*FSTG;
        #pragma unroll
        for (int i = 0; i < 4; i++){
            int idx = tid + i*256;
            int tile = idx >> 9, rem = idx & 511;
            int row = rem >> 3, ch = rem & 7;
            const void* src = tile
                ? (const void*)(g_Vh + ((size_t)bh*Tt + s0n + row)*64 + ch*8)
                : (const void*)(g_kh + ((size_t)bh*Tt + s0n + row)*64 + ch*8);
            cpasync16(base + tile*FTILE + (uint32_t)(row*FLDS + ch*8)*2, src);
        }
        asm volatile("cp.async.commit_group;" ::: "memory");
    };

    {
        #pragma unroll
        for (int i = 0; i < 4; i++){
            int idx = tid + i*256;
            int row = idx >> 3, ch = idx & 7;
            cpasync16(sb + (uint32_t)(row*FLDS + ch*8)*2,
                      g_qh + ((size_t)bh*Tt + t0 + row)*64 + ch*8);
        }
        issueKV(0, 0);
        issueKV(1, 1);
    }

    float o[8][4] = {};
    float l0 = 0.f, l1 = 0.f;
    uint32_t qfh[4][4];

    int st = 0;
    for (int kt = 0; kt < 24; kt++){
        if (kt + 1 < 24) asm volatile("cp.async.wait_group 1;" ::: "memory");
        else             asm volatile("cp.async.wait_group 0;" ::: "memory");
        __syncthreads();
        if (kt + 2 < 24){
            int s2 = st + 2; if (s2 >= 3) s2 -= 3;
            issueKV(kt + 2, s2);
        }

        if (kt == 0){
            #pragma unroll
            for (int ks = 0; ks < 4; ks++){
                uint32_t ad = sb + (uint32_t)((warp*16 + aRow)*FLDS + ks*16 + aCol)*2;
                ldsm4(qfh[ks], ad);
            }
        }

        uint32_t KB = ST0 + st*FSTG;
        // ---- S = Q K^T (fp16) ----
        float acc[8][4] = {};
        #pragma unroll
        for (int ks = 0; ks < 4; ks++){
            #pragma unroll
            for (int g = 0; g < 2; g++){
                uint32_t bfh[4][2];
                #pragma unroll
                for (int p = 0; p < 2; p++){
                    int ntb = g*4 + p*2;
                    uint32_t bd = KB + (uint32_t)(((ntb + ntOff)*8 + bRowQ)*FLDS + ks*16 + colQ)*2;
                    uint32_t r4[4];
                    ldsm4(r4, bd);
                    bfh[p*2][0]=r4[0]; bfh[p*2][1]=r4[1]; bfh[p*2+1][0]=r4[2]; bfh[p*2+1][1]=r4[3];
                }
                #pragma unroll
                for (int j = 0; j < 4; j++) mma16816h(acc[g*4+j], qfh[ks], bfh[j]);
            }
        }

        // ---- exp (no max; scores bounded) + row-sum ----
        float ps0 = 0.f, ps1 = 0.f;
        #pragma unroll
        for (int nt = 0; nt < 8; nt++){
            acc[nt][0] = __expf(acc[nt][0]);
            acc[nt][1] = __expf(acc[nt][1]);
            acc[nt][2] = __expf(acc[nt][2]);
            acc[nt][3] = __expf(acc[nt][3]);
            ps0 += acc[nt][0] + acc[nt][1];
            ps1 += acc[nt][2] + acc[nt][3];
        }
        ps0 += __shfl_xor_sync(~0u, ps0, 1); ps0 += __shfl_xor_sync(~0u, ps0, 2);
        ps1 += __shfl_xor_sync(~0u, ps1, 1); ps1 += __shfl_xor_sync(~0u, ps1, 2);
        l0 += ps0; l1 += ps1;

        // ---- O += P V (fp16) ----
        uint32_t VB = KB + FTILE;
        #pragma unroll
        for (int kc = 0; kc < 4; kc++){
            uint32_t ap[4];
            ap[0] = packh(acc[2*kc][0],   acc[2*kc][1]);
            ap[1] = packh(acc[2*kc][2],   acc[2*kc][3]);
            ap[2] = packh(acc[2*kc+1][0], acc[2*kc+1][1]);
            ap[3] = packh(acc[2*kc+1][2], acc[2*kc+1][3]);
            #pragma unroll
            for (int g = 0; g < 2; g++){
                uint32_t bfh[4][2];
                #pragma unroll
                for (int p = 0; p < 2; p++){
                    int ntb = g*4 + p*2;
                    uint32_t bd = VB + (uint32_t)((kc*16 + tKey)*FLDS + ntb*8 + tDim)*2;
                    uint32_t r4[4];
                    ldsm4t(r4, bd);
                    bfh[p*2][0]=r4[0]; bfh[p*2][1]=r4[1]; bfh[p*2+1][0]=r4[2]; bfh[p*2+1][1]=r4[3];
                }
                #pragma unroll
                for (int j = 0; j < 4; j++) mma16816h(o[g*4+j], ap, bfh[j]);
            }
        }
        st++; if (st >= 3) st -= 3;
    }

    // ---- self-key fixup (fp32 exact; rows t >= TRAIN) ----
    if (t0 >= TRAIN){
        float ll[2] = {l0, l1};
        #pragma unroll
        for (int r = 0; r < 2; r++){
            int trow = t0 + warp*16 + r0 + 8*r;
            size_t qb = ((size_t)(b*Tt + trow))*1536 + h*64;
            float part = 0.f;
            #pragma unroll
            for (int d = 0; d < 16; d++)
                part += g_qkv[qb + cq*16 + d] * g_qkv[qb + 512 + cq*16 + d];
            part += __shfl_xor_sync(~0u, part, 1);
            part += __shfl_xor_sync(~0u, part, 2);
            float p = __expf(part);
            ll[r] += p;
            const float* vs = g_qkv + qb + 1024;
            #pragma unroll
            for (int nt = 0; nt < 8; nt++){
                o[nt][2*r+0] += p*vs[nt*8 + 2*cq + 0];
                o[nt][2*r+1] += p*vs[nt*8 + 2*cq + 1];
            }
        }
        l0 = ll[0]; l1 = ll[1];
    }

    // ---- normalize + packed split write ----
    float inv[2] = {1.f/l0, 1.f/l1};
    #pragma unroll
    for (int r = 0; r < 2; r++){
        int trow = t0 + warp*16 + r0 + 8*r;
        size_t ob = ((size_t)(b*Tt + trow))*Dd + h*64;
        #pragma unroll
        for (int nt = 0; nt < 8; nt++){
            size_t off = ob + nt*8 + 2*cq;
            split_store2h(o[nt][2*r]*inv[r], o[nt][2*r+1]*inv[r], g_ah + off, g_al + off);
        }
    }
}

// ---------------- split-fp16 HMMA GEMM (3-stage, XOR-swizzled, variable TERMS) ----------------
// EPI: 0 = fp32 C (+bias,+res), 1 = gelu -> split fp16, 2 = QKV rope scatter
#define BK 32
#define TILE_B (128*64)             // 8192 B
#define STAGE_B (4*TILE_B)          // 32768 B
#define GSM (3*STAGE_B)             // 98304 B

__global__ __launch_bounds__(256, 2) void mma_gemm(
    const hf* __restrict__ Ah, const hf* __restrict__ Al,
    const hf* __restrict__ Bh, const hf* __restrict__ Bl,
    const float* __restrict__ bias, const float* __restrict__ res,
    float* C, hf* Chi, hf* Clo,
    int K, int ldb, int Nreal, int ldC, size_t sA, size_t sB, size_t sC, int EPI, int TERMS)
{
    extern __shared__ __align__(128) char smem[];
    const uint32_t sb = smem_u32(smem);
    const int tid = threadIdx.x, lane = tid & 31, wid = tid >> 5;
    const int m0 = blockIdx.y*128, n0 = blockIdx.x*128;
    const size_t zb = blockIdx.z;
    const hf* pAh = Ah + zb*sA + (size_t)m0*K;
    const hf* pAl = Al + zb*sA + (size_t)m0*K;
    const hf* pBh = Bh + zb*sB + (size_t)n0*ldb;
    const hf* pBl = Bl + zb*sB + (size_t)n0*ldb;

    float acc[4][4][4] = {};
    const int nk = K/BK;

    auto issue = [&](int c, int s){
        uint32_t base = sb + s*STAGE_B;
        #pragma unroll
        for (int i = 0; i < 2; i++){
            int seg = tid + i*256;
            int row = seg >> 2, s4 = seg & 3;
            int phys = s4 ^ ((row >> 1) & 3);
            uint32_t doff = (uint32_t)(row*64 + phys*16);
            const size_t go = (size_t)row*K + c*BK + s4*8;
            const size_t gob = (size_t)row*ldb + c*BK + s4*8;
            cpasync16(base + 0*TILE_B + doff, pAh + go);
            cpasync16(base + 1*TILE_B + doff, pAl + go);
            cpasync16(base + 2*TILE_B + doff, pBh + gob);
            cpasync16(base + 3*TILE_B + doff, pBl + gob);
        }
        asm volatile("cp.async.commit_group;" ::: "memory");
    };

    issue(0, 0);
    if (nk > 1) issue(1, 1);
    const int wm = (wid>>2)*64, wn = (wid&3)*32;
    const int aRow = lane & 15, aChu = lane >> 4;
    const int bQuad = lane >> 3, bRowQ = lane & 7;
    const int ntOff = bQuad >> 1, bChu = bQuad & 1;

    int st = 0;
    for (int c = 0; c < nk; c++){
        if (c+1 < nk) asm volatile("cp.async.wait_group 1;" ::: "memory");
        else          asm volatile("cp.async.wait_group 0;" ::: "memory");
        __syncthreads();
        if (c+2 < nk){
            int s2 = st + 2; if (s2 >= 3) s2 -= 3;
            issue(c+2, s2);
        }
        uint32_t base = sb + st*STAGE_B;
        #pragma unroll
        for (int ks = 0; ks < 2; ks++){
            uint32_t a_h[4][4], a_l[4][4], b_h[4][2], b_l[4][2];
            #pragma unroll
            for (int mt = 0; mt < 4; mt++){
                int row = wm + mt*16 + aRow;
                int phys = (2*ks + aChu) ^ ((row >> 1) & 3);
                uint32_t ad = base + (uint32_t)(row*64 + phys*16);
                ldsm4(a_h[mt], ad);
                if (TERMS == 3) ldsm4(a_l[mt], ad + TILE_B);
            }
            #pragma unroll
            for (int p = 0; p < 2; p++){
                int row = wn + (p*2 + ntOff)*8 + bRowQ;
                int phys = (2*ks + bChu) ^ ((row >> 1) & 3);
                uint32_t bd = base + 2*TILE_B + (uint32_t)(row*64 + phys*16);
                uint32_t r4[4];
                ldsm4(r4, bd);
                b_h[p*2][0]=r4[0]; b_h[p*2][1]=r4[1]; b_h[p*2+1][0]=r4[2]; b_h[p*2+1][1]=r4[3];
                ldsm4(r4, bd + TILE_B);
                b_l[p*2][0]=r4[0]; b_l[p*2][1]=r4[1]; b_l[p*2+1][0]=r4[2]; b_l[p*2+1][1]=r4[3];
            }
            #pragma unroll
            for (int mt = 0; mt < 4; mt++)
                #pragma unroll
                for (int nt = 0; nt < 4; nt++){
                    mma16816h(acc[mt][nt], a_h[mt], b_h[nt]);
                    mma16816h(acc[mt][nt], a_h[mt], b_l[nt]);
                    if (TERMS == 3) mma16816h(acc[mt][nt], a_l[mt], b_h[nt]);
                }
        }
        st++; if (st >= 3) st -= 3;
    }

    const int r0 = lane >> 2, cW = (lane & 3)*2;
    #pragma unroll
    for (int mt = 0; mt < 4; mt++)
    #pragma unroll
    for (int hh2 = 0; hh2 < 2; hh2++){
        int gm = m0 + wm + mt*16 + r0 + hh2*8;
        #pragma unroll
        for (int nt = 0; nt < 4; nt++){
            float v0 = acc[mt][nt][hh2*2+0], v1 = acc[mt][nt][hh2*2+1];
            int gn = n0 + wn + nt*8 + cW;
            if (bias){ v0 += __ldg(bias+gn); v1 += __ldg(bias+gn+1); }
            if (EPI == 2){
                int b = gm >> 11, t = gm & (Tt-1);
                if (gn < 1024){
                    int hq = (gn & 511) >> 6;
                    int i = (gn & 63) >> 1;
                    float cc = g_cos[t*32+i], ss = g_sin[t*32+i];
                    float r1 = v0*cc - v1*ss, r2 = v0*ss + v1*cc;
                    if (gn < 512){ r1 *= 0.125f; r2 *= 0.125f; }
                    size_t qo = ((size_t)(b*8+hq)*Tt + t)*64 + (gn & 63);
                    if (gn < 512) *(uint32_t*)(g_qh + qo) = packh(r1, r2);
                    else          *(uint32_t*)(g_kh + qo) = packh(r1, r2);
                    if (t >= TRAIN){
                        size_t fo = (size_t)gm*1536 + gn;
                        g_qkv[fo] = r1; g_qkv[fo+1] = r2;
                    }
                } else {
                    int h2 = (gn - 1024) >> 6, dd = (gn - 1024) & 63;
                    size_t vo = ((size_t)(b*8+h2)*Tt + t)*64 + dd;
                    *(uint32_t*)(g_Vh + vo) = packh(v0, v1);
                    if (t >= TRAIN){
                        size_t fo = (size_t)gm*1536 + gn;
                        g_qkv[fo] = v0; g_qkv[fo+1] = v1;
                    }
                }
            } else if (EPI == 1){
                size_t off = zb*sC + (size_t)gm*ldC + gn;
                split_store2h(gelu_f(v0), gelu_f(v1), Chi + off, Clo + off);
            } else {
                size_t off = zb*sC + (size_t)gm*ldC + gn;
                if (res){ v0 += res[off]; v1 += res[off+1]; }
                if (gn+1 < Nreal){
                    *(float2*)(C + off) = make_float2(v0, v1);
                } else {
                    if (gn < Nreal) C[off] = v0;
                }
            }
        }
    }
}

// ---------------- weight transpose + split (fp16) ----------------
__global__ void wsplit_kernel(const float* __restrict__ W, hf* oh, hf* ol,
                              int K, int N, int Npad){
    __shared__ float sm[32][33];
    int n0 = blockIdx.x*32, k0 = blockIdx.y*32, z = blockIdx.z;
    const float* Wb = W + (size_t)z*K*N;
    size_t ob = (size_t)z*Npad*K;
    int tx = threadIdx.x, ty = threadIdx.y;
    #pragma unroll
    for (int j = 0; j < 4; j++){
        int n = n0 + tx;
        sm[ty+8*j][tx] = (n < N) ? Wb[(size_t)(k0+ty+8*j)*N + n] : 0.f;
    }
    __syncthreads();
    #pragma unroll
    for (int j = 0; j < 4; j++){
        size_t o = ob + (size_t)(n0+ty+8*j)*K + k0 + tx;
        split2h(sm[tx][ty+8*j], oh[o], ol[o]);
    }
}

// ---------------- misc kernels ----------------
__global__ void embed_kernel(const float* __restrict__ R, const int* __restrict__ y,
                             const float* __restrict__ emb){
    int row = blockIdx.x, t = row & (Tt-1), b = row >> 11;
    const float4* Rr = (const float4*)(R + (size_t)row*Dd);
    float4* Or = (float4*)(g_rep + (size_t)row*Dd);
    if (t < TRAIN){
        int yv = y[b*TRAIN + t];
        const float4* E = (const float4*)(emb + (size_t)yv*Dd);
        for (int i = threadIdx.x; i < Dd/4; i += blockDim.x){
            float4 a = Rr[i]; float4 e = E[i];
            a.x += e.x; a.y += e.y; a.z += e.z; a.w += e.w;
            Or[i] = a;
        }
    } else {
        for (int i = threadIdx.x; i < Dd/4; i += blockDim.x) Or[i] = Rr[i];
    }
}

__global__ __launch_bounds__(256) void ln_kernel(const float* __restrict__ g,
                                                 const float* __restrict__ be){
    int row = blockIdx.x*8 + (threadIdx.x >> 5);
    int lane = threadIdx.x & 31;
    const float4* xr = (const float4*)(g_rep + (size_t)row*Dd);
    float4 v[4];
    float s = 0.f;
    #pragma unroll
    for (int j = 0; j < 4; j++){
        v[j] = xr[lane + 32*j];
        s += v[j].x + v[j].y + v[j].z + v[j].w;
    }
    #pragma unroll
    for (int o = 16; o; o >>= 1) s += __shfl_xor_sync(~0u, s, o);
    float mu = s * (1.f/Dd);
    float vs = 0.f;
    #pragma unroll
    for (int j = 0; j < 4; j++){
        float a = v[j].x-mu, b2 = v[j].y-mu, c = v[j].z-mu, d = v[j].w-mu;
        vs += a*a + b2*b2 + c*c + d*d;
    }
    #pragma unroll
    for (int o = 16; o; o >>= 1) vs += __shfl_xor_sync(~0u, vs, o);
    float rs = rsqrtf(vs*(1.f/Dd) + 1e-5f);
    #pragma unroll
    for (int j = 0; j < 4; j++){
        int i = lane*4 + 128*j;
        float4 gv = *(const float4*)(g + i);
        float4 bv = *(const float4*)(be + i);
        size_t o = (size_t)row*Dd + i;
        split_store2h((v[j].x-mu)*rs*gv.x + bv.x, (v[j].y-mu)*rs*gv.y + bv.y,
                      g_hh + o, g_hl + o);
        split_store2h((v[j].z-mu)*rs*gv.z + bv.z, (v[j].w-mu)*rs*gv.w + bv.w,
                      g_hh + o + 2, g_hl + o + 2);
    }
}

__global__ void rope_table_kernel(){
    int t = blockIdx.x, i = threadIdx.x;
    float inv = (float)pow(100000.0, -((double)(2*i))/64.0);
    float ang = (float)t * inv;
    g_cos[t*32+i] = cosf(ang);
    g_sin[t*32+i] = sinf(ang);
}

__global__ void extract_kernel(){
    int r = blockIdx.x, b = r >> 9, i = r & 511;
    const float* src = g_rep + (size_t)(b*Tt + TRAIN + i)*Dd;
    for (int j = threadIdx.x*2; j < Dd; j += 256){
        split_store2h(src[j], src[j+1], g_th + (size_t)r*Dd + j, g_tl + (size_t)r*Dd + j);
    }
}

// ---------------- launcher ----------------
#define SYM(p, s) cudaGetSymbolAddress((void**)&p, s)

extern "C" void kernel_launch(void* const* d_in, const int* in_sizes, int n_in,
                              void* d_out, int out_size){
    const float* R    = (const float*)d_in[0];
    const int*   y    = (const int*)  d_in[1];
    const float* emb  = (const float*)d_in[2];
    const float* Wqkv = (const float*)d_in[3];
    const float* bqkv = (const float*)d_in[4];
    const float* Wo   = (const float*)d_in[5];
    const float* bo   = (const float*)d_in[6];
    const float* ln1g = (const float*)d_in[7];
    const float* ln1b = (const float*)d_in[8];
    const float* ln2g = (const float*)d_in[9];
    const float* ln2b = (const float*)d_in[10];
    const float* W1   = (const float*)d_in[11];
    const float* b1   = (const float*)d_in[12];
    const float* W2   = (const float*)d_in[13];
    const float* b2   = (const float*)d_in[14];
    const float* pW1  = (const float*)d_in[15];
    const float* pb1  = (const float*)d_in[16];
    const float* pW2  = (const float*)d_in[17];
    const float* pb2  = (const float*)d_in[18];

    cudaFuncSetAttribute(mma_gemm, cudaFuncAttributeMaxDynamicSharedMemorySize, GSM);
    cudaFuncSetAttribute(flash_kernel, cudaFuncAttributeMaxDynamicSharedMemorySize, FSM);

    float *qkv, *rep;
    hf *hh,*hl,*ah,*al,*fh,*fl,*th,*tl,*gh,*gl;
    hf *Wqkvh,*Wqkvl,*Woh,*Wol,*W1h,*W1l,*W2h,*W2l,*pW1h,*pW1l,*pW2h,*pW2l;
    SYM(qkv,g_qkv); SYM(rep,g_rep);
    SYM(hh,g_hh); SYM(hl,g_hl); SYM(ah,g_ah); SYM(al,g_al);
    SYM(fh,g_fh); SYM(fl,g_fl);
    SYM(th,g_th); SYM(tl,g_tl);
    SYM(gh,g_gh); SYM(gl,g_gl);
    SYM(Wqkvh,g_Wqkvh); SYM(Wqkvl,g_Wqkvl); SYM(Woh,g_Woh); SYM(Wol,g_Wol);
    SYM(W1h,g_W1h); SYM(W1l,g_W1l); SYM(W2h,g_W2h); SYM(W2l,g_W2l);
    SYM(pW1h,g_pW1h); SYM(pW1l,g_pW1l); SYM(pW2h,g_pW2h); SYM(pW2l,g_pW2l);

    dim3 wb(32, 8);
    wsplit_kernel<<<dim3(48,16,12), wb>>>(Wqkv, Wqkvh, Wqkvl, 512, 1536, 1536);
    rope_table_kernel<<<Tt, 32>>>();
    embed_kernel<<<BT, 128>>>(R, y, emb);
    wsplit_kernel<<<dim3(16,16,12), wb>>>(Wo, Woh, Wol, 512, 512, 512);

    for (int l = 0; l < Ll; l++){
        ln_kernel<<<BT/8, 256>>>(ln1g + l*Dd, ln1b + l*Dd);
        mma_gemm<<<dim3(12,64,1),256,GSM>>>(hh, hl, Wqkvh + (size_t)l*1536*512, Wqkvl + (size_t)l*1536*512,
            bqkv + l*1536, nullptr, nullptr, nullptr, nullptr, 512, 512, 1536, 1536, 0,0,0, 2, 2);
        if (l == 0){
            wsplit_kernel<<<dim3(64,16,12), wb>>>(W1, W1h, W1l, 512, 2048, 2048);
            wsplit_kernel<<<dim3(16,64,12), wb>>>(W2, W2h, W2l, 2048, 512, 512);
            wsplit_kernel<<<dim3(32,16,1),  wb>>>(pW1, pW1h, pW1l, 512, 1024, 1024);
            wsplit_kernel<<<dim3(4, 32,1),  wb>>>(pW2, pW2h, pW2l, 1024, 100, 128);
        }
        flash_kernel<<<dim3(16, NBH), 256, FSM>>>();
        mma_gemm<<<dim3(4,64,1),256,GSM>>>(ah, al, Woh + (size_t)l*512*512, Wol + (size_t)l*512*512,
            bo + l*512, rep, rep, nullptr, nullptr, 512, 512, 512, 512, 0,0,0, 0, 2);
        ln_kernel<<<BT/8, 256>>>(ln2g + l*Dd, ln2b + l*Dd);
        mma_gemm<<<dim3(16,64,1),256,GSM>>>(hh, hl, W1h + (size_t)l*2048*512, W1l + (size_t)l*2048*512,
            b1 + l*2048, nullptr, nullptr, fh, fl, 512, 512, 2048, 2048, 0,0,0, 1, 2);
        mma_gemm<<<dim3(4,64,1),256,GSM>>>(fh, fl, W2h + (size_t)l*512*2048, W2l + (size_t)l*512*2048,
            b2 + l*512, rep, rep, nullptr, nullptr, 2048, 2048, 512, 512, 0,0,0, 0, 2);
    }

    extract_kernel<<<MTEST, 128>>>();
    mma_gemm<<<dim3(8,16,1),256,GSM>>>(th, tl, pW1h, pW1l, pb1, nullptr,
        nullptr, gh, gl, 512, 512, 1024, 1024, 0,0,0, 1, 3);
    mma_gemm<<<dim3(1,16,1),256,GSM>>>(gh, gl, pW2h, pW2l, pb2, nullptr,
        (float*)d_out, nullptr, nullptr, 1024, 1024, 100, 100, 0,0,0, 0, 3);
}

// round 17
// speedup vs baseline: 2.2754x; 1.2374x over previous
#include <cuda_runtime.h>
#include <cuda_bf16.h>
#include <cuda_fp16.h>
#include <math.h>
#include <stdint.h>

#define Bc    4
#define Tt    2048
#define TRAIN 1536
#define Dd    512
#define Ll    12
#define FFd   2048
#define BT    (Bc*Tt)
#define NBH   32
#define MTEST 2048

typedef __half hf;

// ---------------- static buffers (all splits fp16) ----------------
__device__ float g_rep [BT*Dd];
__device__ float g_qkv [BT*3*Dd];          // fp32 qkv, written only for t>=TRAIN (fixup)
__device__ hf    g_hh[BT*Dd], g_hl[BT*Dd];
__device__ hf    g_ah[BT*Dd], g_al[BT*Dd];
__device__ hf    g_fh[BT*FFd], g_fl[BT*FFd];
__device__ hf    g_qh[NBH*Tt*64];
__device__ hf    g_kh[NBH*Tt*64];
__device__ hf    g_Vh[NBH*Tt*64];
__device__ hf    g_th[MTEST*Dd], g_tl[MTEST*Dd];
__device__ hf    g_gh[MTEST*2*Dd], g_gl[MTEST*2*Dd];
__device__ hf    g_Wqkvh[Ll*3*Dd*Dd], g_Wqkvl[Ll*3*Dd*Dd];
__device__ hf    g_Woh[Ll*Dd*Dd],  g_Wol[Ll*Dd*Dd];
__device__ hf    g_W1h[Ll*FFd*Dd], g_W1l[Ll*FFd*Dd];
__device__ hf    g_W2h[Ll*Dd*FFd], g_W2l[Ll*Dd*FFd];
__device__ hf    g_pW1h[2*Dd*Dd],  g_pW1l[2*Dd*Dd];
__device__ hf    g_pW2h[128*2*Dd], g_pW2l[128*2*Dd];
__device__ float g_cos[Tt*32], g_sin[Tt*32];

// ---------------- helpers ----------------
__device__ __forceinline__ float gelu_f(float x){
    float y = 0.7978845608028654f*(x + 0.044715f*x*x*x);
    float yc = fminf(fmaxf(y, -15.f), 15.f);
    float t = __expf(2.f*yc);
    float th = (t - 1.f)/(t + 1.f);
    return 0.5f*x*(1.f + th);
}
__device__ __forceinline__ uint32_t smem_u32(const void* p){
    uint32_t a;
    asm("{ .reg .u64 t; cvta.to.shared.u64 t, %1; cvt.u32.u64 %0, t; }" : "=r"(a) : "l"(p));
    return a;
}
__device__ __forceinline__ void cpasync16(uint32_t dst, const void* src){
    asm volatile("cp.async.cg.shared.global [%0], [%1], 16;" :: "r"(dst), "l"(src) : "memory");
}
__device__ __forceinline__ void ldsm4(uint32_t* r, uint32_t a){
    asm volatile("ldmatrix.sync.aligned.m8n8.x4.shared.b16 {%0,%1,%2,%3}, [%4];"
        : "=r"(r[0]),"=r"(r[1]),"=r"(r[2]),"=r"(r[3]) : "r"(a));
}
__device__ __forceinline__ void ldsm4t(uint32_t* r, uint32_t a){
    asm volatile("ldmatrix.sync.aligned.m8n8.x4.trans.shared.b16 {%0,%1,%2,%3}, [%4];"
        : "=r"(r[0]),"=r"(r[1]),"=r"(r[2]),"=r"(r[3]) : "r"(a));
}
__device__ __forceinline__ void mma16816h(float* c, const uint32_t* a, const uint32_t* b){
    asm volatile("mma.sync.aligned.m16n8k16.row.col.f32.f16.f16.f32 "
        "{%0,%1,%2,%3}, {%4,%5,%6,%7}, {%8,%9}, {%0,%1,%2,%3};"
        : "+f"(c[0]),"+f"(c[1]),"+f"(c[2]),"+f"(c[3])
        : "r"(a[0]),"r"(a[1]),"r"(a[2]),"r"(a[3]), "r"(b[0]),"r"(b[1]));
}
__device__ __forceinline__ uint32_t packh(float lo, float hi){
    uint32_t r;
    asm("cvt.rn.f16x2.f32 %0, %1, %2;" : "=r"(r) : "f"(hi), "f"(lo));
    return r;
}
__device__ __forceinline__ void split2h(float x, hf& h, hf& l){
    h = __float2half_rn(x);
    l = __float2half_rn(x - __half2float(h));
}
__device__ __forceinline__ void split_store2h(float v0, float v1, hf* ph, hf* pl){
    float h0 = __half2float(__float2half_rn(v0));
    float h1 = __half2float(__float2half_rn(v1));
    *(uint32_t*)ph = packh(v0, v1);
    *(uint32_t*)pl = packh(v0 - h0, v1 - h1);
}

// ================= fused flash attention (fp16 S and PV) =================
#define FLDS 72
#define FTILE (64*FLDS*2)          // 9216
#define FQT   (128*FLDS*2)         // 18432
#define FSTG  (2*FTILE)            // 18432
#define FSM   (FQT + 3*FSTG)       // 73728

__global__ __launch_bounds__(256, 2) void flash_kernel(){
    extern __shared__ __align__(128) char smem[];
    const uint32_t sb = smem_u32(smem);
    const int tid = threadIdx.x, lane = tid & 31, warp = tid >> 5;
    const int bh = blockIdx.y, b = bh >> 3, h = bh & 7;
    const int t0 = blockIdx.x * 128;
    const int r0 = lane >> 2, cq = lane & 3;
    const int aRow = lane & 15, aCol = (lane >> 4)*8;
    const int bQuad = lane >> 3, bRowQ = lane & 7;
    const int ntOff = bQuad >> 1, colQ = (bQuad & 1)*8;
    const int tKey = (bQuad & 1)*8 + bRowQ, tDim = (bQuad >> 1)*8;
    const uint32_t ST0 = sb + FQT;

    auto issueKV = [&](int kt, int st){
        int s0n = kt*64;
        uint32_t base = ST0 + st*FSTG;
        #pragma unroll
        for (int i = 0; i < 4; i++){
            int idx = tid + i*256;
            int tile = idx >> 9, rem = idx & 511;
            int row = rem >> 3, ch = rem & 7;
            const void* src = tile
                ? (const void*)(g_Vh + ((size_t)bh*Tt + s0n + row)*64 + ch*8)
                : (const void*)(g_kh + ((size_t)bh*Tt + s0n + row)*64 + ch*8);
            cpasync16(base + tile*FTILE + (uint32_t)(row*FLDS + ch*8)*2, src);
        }
        asm volatile("cp.async.commit_group;" ::: "memory");
    };

    {
        #pragma unroll
        for (int i = 0; i < 4; i++){
            int idx = tid + i*256;
            int row = idx >> 3, ch = idx & 7;
            cpasync16(sb + (uint32_t)(row*FLDS + ch*8)*2,
                      g_qh + ((size_t)bh*Tt + t0 + row)*64 + ch*8);
        }
        issueKV(0, 0);
        issueKV(1, 1);
    }

    float o[8][4] = {};
    float l0 = 0.f, l1 = 0.f;
    uint32_t qfh[4][4];

    int st = 0;
    for (int kt = 0; kt < 24; kt++){
        if (kt + 1 < 24) asm volatile("cp.async.wait_group 1;" ::: "memory");
        else             asm volatile("cp.async.wait_group 0;" ::: "memory");
        __syncthreads();
        if (kt + 2 < 24){
            int s2 = st + 2; if (s2 >= 3) s2 -= 3;
            issueKV(kt + 2, s2);
        }

        if (kt == 0){
            #pragma unroll
            for (int ks = 0; ks < 4; ks++){
                uint32_t ad = sb + (uint32_t)((warp*16 + aRow)*FLDS + ks*16 + aCol)*2;
                ldsm4(qfh[ks], ad);
            }
        }

        uint32_t KB = ST0 + st*FSTG;
        float acc[8][4] = {};
        #pragma unroll
        for (int ks = 0; ks < 4; ks++){
            #pragma unroll
            for (int g = 0; g < 2; g++){
                uint32_t bfh[4][2];
                #pragma unroll
                for (int p = 0; p < 2; p++){
                    int ntb = g*4 + p*2;
                    uint32_t bd = KB + (uint32_t)(((ntb + ntOff)*8 + bRowQ)*FLDS + ks*16 + colQ)*2;
                    uint32_t r4[4];
                    ldsm4(r4, bd);
                    bfh[p*2][0]=r4[0]; bfh[p*2][1]=r4[1]; bfh[p*2+1][0]=r4[2]; bfh[p*2+1][1]=r4[3];
                }
                #pragma unroll
                for (int j = 0; j < 4; j++) mma16816h(acc[g*4+j], qfh[ks], bfh[j]);
            }
        }

        float ps0 = 0.f, ps1 = 0.f;
        #pragma unroll
        for (int nt = 0; nt < 8; nt++){
            acc[nt][0] = __expf(acc[nt][0]);
            acc[nt][1] = __expf(acc[nt][1]);
            acc[nt][2] = __expf(acc[nt][2]);
            acc[nt][3] = __expf(acc[nt][3]);
            ps0 += acc[nt][0] + acc[nt][1];
            ps1 += acc[nt][2] + acc[nt][3];
        }
        ps0 += __shfl_xor_sync(~0u, ps0, 1); ps0 += __shfl_xor_sync(~0u, ps0, 2);
        ps1 += __shfl_xor_sync(~0u, ps1, 1); ps1 += __shfl_xor_sync(~0u, ps1, 2);
        l0 += ps0; l1 += ps1;

        uint32_t VB = KB + FTILE;
        #pragma unroll
        for (int kc = 0; kc < 4; kc++){
            uint32_t ap[4];
            ap[0] = packh(acc[2*kc][0],   acc[2*kc][1]);
            ap[1] = packh(acc[2*kc][2],   acc[2*kc][3]);
            ap[2] = packh(acc[2*kc+1][0], acc[2*kc+1][1]);
            ap[3] = packh(acc[2*kc+1][2], acc[2*kc+1][3]);
            #pragma unroll
            for (int g = 0; g < 2; g++){
                uint32_t bfh[4][2];
                #pragma unroll
                for (int p = 0; p < 2; p++){
                    int ntb = g*4 + p*2;
                    uint32_t bd = VB + (uint32_t)((kc*16 + tKey)*FLDS + ntb*8 + tDim)*2;
                    uint32_t r4[4];
                    ldsm4t(r4, bd);
                    bfh[p*2][0]=r4[0]; bfh[p*2][1]=r4[1]; bfh[p*2+1][0]=r4[2]; bfh[p*2+1][1]=r4[3];
                }
                #pragma unroll
                for (int j = 0; j < 4; j++) mma16816h(o[g*4+j], ap, bfh[j]);
            }
        }
        st++; if (st >= 3) st -= 3;
    }

    if (t0 >= TRAIN){
        float ll[2] = {l0, l1};
        #pragma unroll
        for (int r = 0; r < 2; r++){
            int trow = t0 + warp*16 + r0 + 8*r;
            size_t qb = ((size_t)(b*Tt + trow))*1536 + h*64;
            float part = 0.f;
            #pragma unroll
            for (int d = 0; d < 16; d++)
                part += g_qkv[qb + cq*16 + d] * g_qkv[qb + 512 + cq*16 + d];
            part += __shfl_xor_sync(~0u, part, 1);
            part += __shfl_xor_sync(~0u, part, 2);
            float p = __expf(part);
            ll[r] += p;
            const float* vs = g_qkv + qb + 1024;
            #pragma unroll
            for (int nt = 0; nt < 8; nt++){
                o[nt][2*r+0] += p*vs[nt*8 + 2*cq + 0];
                o[nt][2*r+1] += p*vs[nt*8 + 2*cq + 1];
            }
        }
        l0 = ll[0]; l1 = ll[1];
    }

    float inv[2] = {1.f/l0, 1.f/l1};
    #pragma unroll
    for (int r = 0; r < 2; r++){
        int trow = t0 + warp*16 + r0 + 8*r;
        size_t ob = ((size_t)(b*Tt + trow))*Dd + h*64;
        #pragma unroll
        for (int nt = 0; nt < 8; nt++){
            size_t off = ob + nt*8 + 2*cq;
            split_store2h(o[nt][2*r]*inv[r], o[nt][2*r+1]*inv[r], g_ah + off, g_al + off);
        }
    }
}

// ---------------- split-fp16 HMMA GEMM (templated TERMS; Al load skipped at 2) ----------------
// EPI: 0 = fp32 C (+bias,+res), 1 = gelu -> split fp16, 2 = QKV rope scatter
#define BK 32
#define TILE_B (128*64)             // 8192 B
#define STAGE_B (4*TILE_B)          // 32768 B
#define GSM (3*STAGE_B)             // 98304 B

template<int TERMS>
__global__ __launch_bounds__(256, 2) void mma_gemm(
    const hf* __restrict__ Ah, const hf* __restrict__ Al,
    const hf* __restrict__ Bh, const hf* __restrict__ Bl,
    const float* __restrict__ bias, const float* __restrict__ res,
    float* C, hf* Chi, hf* Clo,
    int K, int ldb, int Nreal, int ldC, size_t sA, size_t sB, size_t sC, int EPI)
{
    extern __shared__ __align__(128) char smem[];
    const uint32_t sb = smem_u32(smem);
    const int tid = threadIdx.x, lane = tid & 31, wid = tid >> 5;
    const int m0 = blockIdx.y*128, n0 = blockIdx.x*128;
    const size_t zb = blockIdx.z;
    const hf* pAh = Ah + zb*sA + (size_t)m0*K;
    const hf* pAl = Al + zb*sA + (size_t)m0*K;
    const hf* pBh = Bh + zb*sB + (size_t)n0*ldb;
    const hf* pBl = Bl + zb*sB + (size_t)n0*ldb;

    float acc[4][4][4] = {};
    const int nk = K/BK;

    auto issue = [&](int c, int s){
        uint32_t base = sb + s*STAGE_B;
        #pragma unroll
        for (int i = 0; i < 2; i++){
            int seg = tid + i*256;
            int row = seg >> 2, s4 = seg & 3;
            int phys = s4 ^ ((row >> 1) & 3);
            uint32_t doff = (uint32_t)(row*64 + phys*16);
            const size_t go = (size_t)row*K + c*BK + s4*8;
            const size_t gob = (size_t)row*ldb + c*BK + s4*8;
            cpasync16(base + 0*TILE_B + doff, pAh + go);
            if (TERMS == 3) cpasync16(base + 1*TILE_B + doff, pAl + go);
            cpasync16(base + 2*TILE_B + doff, pBh + gob);
            cpasync16(base + 3*TILE_B + doff, pBl + gob);
        }
        asm volatile("cp.async.commit_group;" ::: "memory");
    };

    issue(0, 0);
    if (nk > 1) issue(1, 1);
    const int wm = (wid>>2)*64, wn = (wid&3)*32;
    const int aRow = lane & 15, aChu = lane >> 4;
    const int bQuad = lane >> 3, bRowQ = lane & 7;
    const int ntOff = bQuad >> 1, bChu = bQuad & 1;

    int st = 0;
    for (int c = 0; c < nk; c++){
        if (c+1 < nk) asm volatile("cp.async.wait_group 1;" ::: "memory");
        else          asm volatile("cp.async.wait_group 0;" ::: "memory");
        __syncthreads();
        if (c+2 < nk){
            int s2 = st + 2; if (s2 >= 3) s2 -= 3;
            issue(c+2, s2);
        }
        uint32_t base = sb + st*STAGE_B;
        #pragma unroll
        for (int ks = 0; ks < 2; ks++){
            uint32_t a_h[4][4], a_l[4][4], b_h[4][2], b_l[4][2];
            #pragma unroll
            for (int mt = 0; mt < 4; mt++){
                int row = wm + mt*16 + aRow;
                int phys = (2*ks + aChu) ^ ((row >> 1) & 3);
                uint32_t ad = base + (uint32_t)(row*64 + phys*16);
                ldsm4(a_h[mt], ad);
                if (TERMS == 3) ldsm4(a_l[mt], ad + TILE_B);
            }
            #pragma unroll
            for (int p = 0; p < 2; p++){
                int row = wn + (p*2 + ntOff)*8 + bRowQ;
                int phys = (2*ks + bChu) ^ ((row >> 1) & 3);
                uint32_t bd = base + 2*TILE_B + (uint32_t)(row*64 + phys*16);
                uint32_t r4[4];
                ldsm4(r4, bd);
                b_h[p*2][0]=r4[0]; b_h[p*2][1]=r4[1]; b_h[p*2+1][0]=r4[2]; b_h[p*2+1][1]=r4[3];
                ldsm4(r4, bd + TILE_B);
                b_l[p*2][0]=r4[0]; b_l[p*2][1]=r4[1]; b_l[p*2+1][0]=r4[2]; b_l[p*2+1][1]=r4[3];
            }
            #pragma unroll
            for (int mt = 0; mt < 4; mt++)
                #pragma unroll
                for (int nt = 0; nt < 4; nt++){
                    mma16816h(acc[mt][nt], a_h[mt], b_h[nt]);
                    mma16816h(acc[mt][nt], a_h[mt], b_l[nt]);
                    if (TERMS == 3) mma16816h(acc[mt][nt], a_l[mt], b_h[nt]);
                }
        }
        st++; if (st >= 3) st -= 3;
    }

    const int r0 = lane >> 2, cW = (lane & 3)*2;
    #pragma unroll
    for (int mt = 0; mt < 4; mt++)
    #pragma unroll
    for (int hh2 = 0; hh2 < 2; hh2++){
        int gm = m0 + wm + mt*16 + r0 + hh2*8;
        #pragma unroll
        for (int nt = 0; nt < 4; nt++){
            float v0 = acc[mt][nt][hh2*2+0], v1 = acc[mt][nt][hh2*2+1];
            int gn = n0 + wn + nt*8 + cW;
            if (bias){ v0 += __ldg(bias+gn); v1 += __ldg(bias+gn+1); }
            if (EPI == 2){
                int b = gm >> 11, t = gm & (Tt-1);
                if (gn < 1024){
                    int hq = (gn & 511) >> 6;
                    int i = (gn & 63) >> 1;
                    float cc = g_cos[t*32+i], ss = g_sin[t*32+i];
                    float r1 = v0*cc - v1*ss, r2 = v0*ss + v1*cc;
                    if (gn < 512){ r1 *= 0.125f; r2 *= 0.125f; }
                    size_t qo = ((size_t)(b*8+hq)*Tt + t)*64 + (gn & 63);
                    if (gn < 512) *(uint32_t*)(g_qh + qo) = packh(r1, r2);
                    else          *(uint32_t*)(g_kh + qo) = packh(r1, r2);
                    if (t >= TRAIN){
                        size_t fo = (size_t)gm*1536 + gn;
                        g_qkv[fo] = r1; g_qkv[fo+1] = r2;
                    }
                } else {
                    int h2 = (gn - 1024) >> 6, dd = (gn - 1024) & 63;
                    size_t vo = ((size_t)(b*8+h2)*Tt + t)*64 + dd;
                    *(uint32_t*)(g_Vh + vo) = packh(v0, v1);
                    if (t >= TRAIN){
                        size_t fo = (size_t)gm*1536 + gn;
                        g_qkv[fo] = v0; g_qkv[fo+1] = v1;
                    }
                }
            } else if (EPI == 1){
                size_t off = zb*sC + (size_t)gm*ldC + gn;
                split_store2h(gelu_f(v0), gelu_f(v1), Chi + off, Clo + off);
            } else {
                size_t off = zb*sC + (size_t)gm*ldC + gn;
                if (res){ v0 += res[off]; v1 += res[off+1]; }
                if (gn+1 < Nreal){
                    *(float2*)(C + off) = make_float2(v0, v1);
                } else {
                    if (gn < Nreal) C[off] = v0;
                }
            }
        }
    }
}

// ---------------- weight transpose + split (fp16) ----------------
__global__ void wsplit_kernel(const float* __restrict__ W, hf* oh, hf* ol,
                              int K, int N, int Npad){
    __shared__ float sm[32][33];
    int n0 = blockIdx.x*32, k0 = blockIdx.y*32, z = blockIdx.z;
    const float* Wb = W + (size_t)z*K*N;
    size_t ob = (size_t)z*Npad*K;
    int tx = threadIdx.x, ty = threadIdx.y;
    #pragma unroll
    for (int j = 0; j < 4; j++){
        int n = n0 + tx;
        sm[ty+8*j][tx] = (n < N) ? Wb[(size_t)(k0+ty+8*j)*N + n] : 0.f;
    }
    __syncthreads();
    #pragma unroll
    for (int j = 0; j < 4; j++){
        size_t o = ob + (size_t)(n0+ty+8*j)*K + k0 + tx;
        split2h(sm[tx][ty+8*j], oh[o], ol[o]);
    }
}

// ---------------- misc kernels ----------------
__global__ void embed_kernel(const float* __restrict__ R, const int* __restrict__ y,
                             const float* __restrict__ emb){
    int row = blockIdx.x, t = row & (Tt-1), b = row >> 11;
    const float4* Rr = (const float4*)(R + (size_t)row*Dd);
    float4* Or = (float4*)(g_rep + (size_t)row*Dd);
    if (t < TRAIN){
        int yv = y[b*TRAIN + t];
        const float4* E = (const float4*)(emb + (size_t)yv*Dd);
        for (int i = threadIdx.x; i < Dd/4; i += blockDim.x){
            float4 a = Rr[i]; float4 e = E[i];
            a.x += e.x; a.y += e.y; a.z += e.z; a.w += e.w;
            Or[i] = a;
        }
    } else {
        for (int i = threadIdx.x; i < Dd/4; i += blockDim.x) Or[i] = Rr[i];
    }
}

__global__ __launch_bounds__(256) void ln_kernel(const float* __restrict__ g,
                                                 const float* __restrict__ be){
    int row = blockIdx.x*8 + (threadIdx.x >> 5);
    int lane = threadIdx.x & 31;
    const float4* xr = (const float4*)(g_rep + (size_t)row*Dd);
    float4 v[4];
    float s = 0.f;
    #pragma unroll
    for (int j = 0; j < 4; j++){
        v[j] = xr[lane + 32*j];
        s += v[j].x + v[j].y + v[j].z + v[j].w;
    }
    #pragma unroll
    for (int o = 16; o; o >>= 1) s += __shfl_xor_sync(~0u, s, o);
    float mu = s * (1.f/Dd);
    float vs = 0.f;
    #pragma unroll
    for (int j = 0; j < 4; j++){
        float a = v[j].x-mu, b2 = v[j].y-mu, c = v[j].z-mu, d = v[j].w-mu;
        vs += a*a + b2*b2 + c*c + d*d;
    }
    #pragma unroll
    for (int o = 16; o; o >>= 1) vs += __shfl_xor_sync(~0u, vs, o);
    float rs = rsqrtf(vs*(1.f/Dd) + 1e-5f);
    #pragma unroll
    for (int j = 0; j < 4; j++){
        int i = lane*4 + 128*j;
        float4 gv = *(const float4*)(g + i);
        float4 bv = *(const float4*)(be + i);
        size_t o = (size_t)row*Dd + i;
        split_store2h((v[j].x-mu)*rs*gv.x + bv.x, (v[j].y-mu)*rs*gv.y + bv.y,
                      g_hh + o, g_hl + o);
        split_store2h((v[j].z-mu)*rs*gv.z + bv.z, (v[j].w-mu)*rs*gv.w + bv.w,
                      g_hh + o + 2, g_hl + o + 2);
    }
}

__global__ void rope_table_kernel(){
    int t = blockIdx.x, i = threadIdx.x;
    float inv = (float)pow(100000.0, -((double)(2*i))/64.0);
    float ang = (float)t * inv;
    g_cos[t*32+i] = cosf(ang);
    g_sin[t*32+i] = sinf(ang);
}

__global__ void extract_kernel(){
    int r = blockIdx.x, b = r >> 9, i = r & 511;
    const float* src = g_rep + (size_t)(b*Tt + TRAIN + i)*Dd;
    for (int j = threadIdx.x*2; j < Dd; j += 256){
        split_store2h(src[j], src[j+1], g_th + (size_t)r*Dd + j, g_tl + (size_t)r*Dd + j);
    }
}

// ---------------- launcher ----------------
#define SYM(p, s) cudaGetSymbolAddress((void**)&p, s)

extern "C" void kernel_launch(void* const* d_in, const int* in_sizes, int n_in,
                              void* d_out, int out_size){
    const float* R    = (const float*)d_in[0];
    const int*   y    = (const int*)  d_in[1];
    const float* emb  = (const float*)d_in[2];
    const float* Wqkv = (const float*)d_in[3];
    const float* bqkv = (const float*)d_in[4];
    const float* Wo   = (const float*)d_in[5];
    const float* bo   = (const float*)d_in[6];
    const float* ln1g = (const float*)d_in[7];
    const float* ln1b = (const float*)d_in[8];
    const float* ln2g = (const float*)d_in[9];
    const float* ln2b = (const float*)d_in[10];
    const float* W1   = (const float*)d_in[11];
    const float* b1   = (const float*)d_in[12];
    const float* W2   = (const float*)d_in[13];
    const float* b2   = (const float*)d_in[14];
    const float* pW1  = (const float*)d_in[15];
    const float* pb1  = (const float*)d_in[16];
    const float* pW2  = (const float*)d_in[17];
    const float* pb2  = (const float*)d_in[18];

    cudaFuncSetAttribute(mma_gemm<2>, cudaFuncAttributeMaxDynamicSharedMemorySize, GSM);
    cudaFuncSetAttribute(mma_gemm<3>, cudaFuncAttributeMaxDynamicSharedMemorySize, GSM);
    cudaFuncSetAttribute(flash_kernel, cudaFuncAttributeMaxDynamicSharedMemorySize, FSM);

    float *qkv, *rep;
    hf *hh,*hl,*ah,*al,*fh,*fl,*th,*tl,*gh,*gl;
    hf *Wqkvh,*Wqkvl,*Woh,*Wol,*W1h,*W1l,*W2h,*W2l,*pW1h,*pW1l,*pW2h,*pW2l;
    SYM(qkv,g_qkv); SYM(rep,g_rep);
    SYM(hh,g_hh); SYM(hl,g_hl); SYM(ah,g_ah); SYM(al,g_al);
    SYM(fh,g_fh); SYM(fl,g_fl);
    SYM(th,g_th); SYM(tl,g_tl);
    SYM(gh,g_gh); SYM(gl,g_gl);
    SYM(Wqkvh,g_Wqkvh); SYM(Wqkvl,g_Wqkvl); SYM(Woh,g_Woh); SYM(Wol,g_Wol);
    SYM(W1h,g_W1h); SYM(W1l,g_W1l); SYM(W2h,g_W2h); SYM(W2l,g_W2l);
    SYM(pW1h,g_pW1h); SYM(pW1l,g_pW1l); SYM(pW2h,g_pW2h); SYM(pW2l,g_pW2l);

    dim3 wb(32, 8);
    wsplit_kernel<<<dim3(48,16,12), wb>>>(Wqkv, Wqkvh, Wqkvl, 512, 1536, 1536);
    rope_table_kernel<<<Tt, 32>>>();
    embed_kernel<<<BT, 128>>>(R, y, emb);
    wsplit_kernel<<<dim3(16,16,12), wb>>>(Wo, Woh, Wol, 512, 512, 512);

    for (int l = 0; l < Ll; l++){
        ln_kernel<<<BT/8, 256>>>(ln1g + l*Dd, ln1b + l*Dd);
        mma_gemm<2><<<dim3(12,64,1),256,GSM>>>(hh, hl, Wqkvh + (size_t)l*1536*512, Wqkvl + (size_t)l*1536*512,
            bqkv + l*1536, nullptr, nullptr, nullptr, nullptr, 512, 512, 1536, 1536, 0,0,0, 2);
        if (l == 0){
            wsplit_kernel<<<dim3(64,16,12), wb>>>(W1, W1h, W1l, 512, 2048, 2048);
            wsplit_kernel<<<dim3(16,64,12), wb>>>(W2, W2h, W2l, 2048, 512, 512);
            wsplit_kernel<<<dim3(32,16,1),  wb>>>(pW1, pW1h, pW1l, 512, 1024, 1024);
            wsplit_kernel<<<dim3(4, 32,1),  wb>>>(pW2, pW2h, pW2l, 1024, 100, 128);
        }
        flash_kernel<<<dim3(16, NBH), 256, FSM>>>();
        mma_gemm<2><<<dim3(4,64,1),256,GSM>>>(ah, al, Woh + (size_t)l*512*512, Wol + (size_t)l*512*512,
            bo + l*512, rep, rep, nullptr, nullptr, 512, 512, 512, 512, 0,0,0, 0);
        ln_kernel<<<BT/8, 256>>>(ln2g + l*Dd, ln2b + l*Dd);
        mma_gemm<2><<<dim3(16,64,1),256,GSM>>>(hh, hl, W1h + (size_t)l*2048*512, W1l + (size_t)l*2048*512,
            b1 + l*2048, nullptr, nullptr, fh, fl, 512, 512, 2048, 2048, 0,0,0, 1);
        mma_gemm<2><<<dim3(4,64,1),256,GSM>>>(fh, fl, W2h + (size_t)l*512*2048, W2l + (size_t)l*512*2048,
            b2 + l*512, rep, rep, nullptr, nullptr, 2048, 2048, 512, 512, 0,0,0, 0);
    }

    extract_kernel<<<MTEST, 128>>>();
    mma_gemm<3><<<dim3(8,16,1),256,GSM>>>(th, tl, pW1h, pW1l, pb1, nullptr,
        nullptr, gh, gl, 512, 512, 1024, 1024, 0,0,0, 1);
    mma_gemm<3><<<dim3(1,16,1),256,GSM>>>(gh, gl, pW2h, pW2l, pb2, nullptr,
        (float*)d_out, nullptr, nullptr, 1024, 1024, 100, 100, 0,0,0, 0);
}